// round 8
// baseline (speedup 1.0000x reference)
#include <cuda_runtime.h>
#include <math.h>

// ---------------- problem constants ----------------
#define BB   64
#define NTT  456
#define TOKK 64
#define DD   256
#define HH   8
#define HDD  32
#define FFF  1024
#define LLN  457            // L = NT + 1
#define MROWS (BB * LLN)    // 29248

// ---------------- device scratch (static, no allocs) ----------------
__device__ float g_X  [MROWS * DD];          // activations (B,L,D)        ~30 MB
__device__ float g_T  [MROWS * DD];          // attn out / ffn2 out temp   ~30 MB
__device__ float g_BIG[MROWS * FFF];         // QKV (22.5M) / FFN hidden (29.9M) ~120 MB
__device__ float g_S  [MROWS];               // head scores

// ---------------- helpers ----------------
__device__ __forceinline__ float warp_sum(float v) {
#pragma unroll
    for (int o = 16; o; o >>= 1) v += __shfl_xor_sync(0xffffffffu, v, o);
    return v;
}
__device__ __forceinline__ float warp_max(float v) {
#pragma unroll
    for (int o = 16; o; o >>= 1) v = fmaxf(v, __shfl_xor_sync(0xffffffffu, v, o));
    return v;
}

// ---------------- tiled SGEMM: C[M,N] = A[M,K] @ W[K,N] + bias (optional relu / row remap) ----
// BM=64, BN=128, BK=16; 256 threads; 4x8 micro-tile per thread.
// grid = (M/64, N/128). All shapes divide exactly (M = 64*457 or 64*456).
template<bool RELU, bool REMAP>
__global__ void __launch_bounds__(256) gemm_kernel(
    const float* __restrict__ A, const float* __restrict__ W,
    const float* __restrict__ bias, float* __restrict__ C,
    int K, int N)
{
    __shared__ __align__(16) float As[16][68];   // [k][m], padded stride
    __shared__ __align__(16) float Bs[16][128];  // [k][n]

    const int tid = threadIdx.x;
    const int tx  = tid & 15;       // n-group: 8 cols
    const int ty  = tid >> 4;       // m-group: 4 rows
    const int bm  = blockIdx.x * 64;
    const int bn  = blockIdx.y * 128;

    const int la_r = tid >> 2;            // 0..63
    const int la_k = (tid & 3) << 2;      // 0,4,8,12
    const int lb_r = tid >> 5;            // 0..7
    const int lb_c = (tid & 31) << 2;     // 0..124

    const float* Aptr  = A + (size_t)(bm + la_r) * K + la_k;
    const float* Wptr0 = W + (size_t)lb_r * N + bn + lb_c;
    const float* Wptr1 = W + (size_t)(lb_r + 8) * N + bn + lb_c;

    float acc[4][8];
#pragma unroll
    for (int i = 0; i < 4; i++)
#pragma unroll
        for (int j = 0; j < 8; j++) acc[i][j] = 0.f;

    for (int k0 = 0; k0 < K; k0 += 16) {
        float4 av  = *(const float4*)(Aptr + k0);
        float4 bw0 = *(const float4*)(Wptr0 + (size_t)k0 * N);
        float4 bw1 = *(const float4*)(Wptr1 + (size_t)k0 * N);
        As[la_k + 0][la_r] = av.x;
        As[la_k + 1][la_r] = av.y;
        As[la_k + 2][la_r] = av.z;
        As[la_k + 3][la_r] = av.w;
        *(float4*)&Bs[lb_r][lb_c]     = bw0;
        *(float4*)&Bs[lb_r + 8][lb_c] = bw1;
        __syncthreads();
#pragma unroll
        for (int kk = 0; kk < 16; kk++) {
            float4 a  = *(const float4*)&As[kk][ty * 4];
            float4 b0 = *(const float4*)&Bs[kk][tx * 8];
            float4 b1 = *(const float4*)&Bs[kk][tx * 8 + 4];
            float ar[4] = {a.x, a.y, a.z, a.w};
            float br[8] = {b0.x, b0.y, b0.z, b0.w, b1.x, b1.y, b1.z, b1.w};
#pragma unroll
            for (int i = 0; i < 4; i++)
#pragma unroll
                for (int j = 0; j < 8; j++)
                    acc[i][j] = fmaf(ar[i], br[j], acc[i][j]);
        }
        __syncthreads();
    }

    float4 bb0 = *(const float4*)(bias + bn + tx * 8);
    float4 bb1 = *(const float4*)(bias + bn + tx * 8 + 4);
    float bx[8] = {bb0.x, bb0.y, bb0.z, bb0.w, bb1.x, bb1.y, bb1.z, bb1.w};

#pragma unroll
    for (int i = 0; i < 4; i++) {
        int r = bm + ty * 4 + i;
        int orow = REMAP ? (r + r / NTT + 1) : r;   // (b*NT+t) -> b*L + 1 + t
        float o[8];
#pragma unroll
        for (int j = 0; j < 8; j++) {
            float v = acc[i][j] + bx[j];
            if (RELU) v = fmaxf(v, 0.f);
            o[j] = v;
        }
        float4* cp = (float4*)(C + (size_t)orow * N + bn + tx * 8);
        cp[0] = make_float4(o[0], o[1], o[2], o[3]);
        cp[1] = make_float4(o[4], o[5], o[6], o[7]);
    }
}

// ---------------- CLS row: X[b,0,:] = coords @ w_cls + b_cls ----------------
__global__ void cls_kernel(const float* __restrict__ coords,
                           const float* __restrict__ w_cls,
                           const float* __restrict__ b_cls,
                           float* __restrict__ X)
{
    int b = blockIdx.x, d = threadIdx.x;
    float c0 = coords[b * 3 + 0], c1 = coords[b * 3 + 1], c2 = coords[b * 3 + 2];
    X[(size_t)b * LLN * DD + d] =
        b_cls[d] + c0 * w_cls[d] + c1 * w_cls[DD + d] + c2 * w_cls[2 * DD + d];
}

// ---------------- fused attention: one CTA per (b,h), K/V/S in smem ----------------
// smem floats: K 457*33, V 457*32, S 16*457 (2 score rows per warp), Q 8*64
#define ATTN_SMEM_FLOATS (457*33 + 457*32 + 16*457 + 8*64)
#define ATTN_SMEM_BYTES  (ATTN_SMEM_FLOATS * 4)

__global__ void __launch_bounds__(256) attn_kernel(const float* __restrict__ QKV,
                                                   float* __restrict__ O)
{
    extern __shared__ float sm[];
    float* Ksm = sm;                      // [457][33]
    float* Vsm = Ksm + 457 * 33;          // [457][32]
    float* Ssm = Vsm + 457 * 32;          // [16][457]
    float* Qsm = Ssm + 16 * 457;          // [8][64]

    const int bh = blockIdx.x;
    const int b = bh >> 3, h = bh & 7;
    const int tid = threadIdx.x, w = tid >> 5, lane = tid & 31;
    const float slope = (h < 4) ? 1.0f : 0.5f;           // alibi slopes [1,1,1,1,.5,.5,.5,.5]
    const float scale = 0.17677669529663687f;            // 1/sqrt(32)

    const float* base = QKV + (size_t)b * (LLN * 3 * DD) + h * HDD;

    // stage K and V
    for (int idx = tid; idx < 457 * 32; idx += 256) {
        int j = idx >> 5, d = idx & 31;
        const float* kv = base + (size_t)j * (3 * DD);
        Ksm[j * 33 + d] = kv[DD + d];        // K at offset 256
        Vsm[idx]        = kv[2 * DD + d];    // V at offset 512
    }
    __syncthreads();

    for (int i0 = 2 * w; i0 < LLN; i0 += 16) {
        const bool two = (i0 + 1 < LLN);
        Qsm[w * 64 + lane] = base[(size_t)i0 * (3 * DD) + lane];
        if (two) Qsm[w * 64 + 32 + lane] = base[(size_t)(i0 + 1) * (3 * DD) + lane];
        __syncwarp();

        // scores: lane owns j = lane + 32*t
        float s0[15], s1[15];
#pragma unroll
        for (int t = 0; t < 15; t++) { s0[t] = 0.f; s1[t] = 0.f; }
        for (int d = 0; d < 32; d++) {
            float q0 = Qsm[w * 64 + d];
            float q1 = Qsm[w * 64 + 32 + d];
#pragma unroll
            for (int t = 0; t < 15; t++) {
                int jj = lane + t * 32;
                if (jj < LLN) {
                    float kv = Ksm[jj * 33 + d];
                    s0[t] += q0 * kv;
                    s1[t] += q1 * kv;
                }
            }
        }
        // scale + alibi bias, row max
        float mx0 = -1e30f, mx1 = -1e30f;
#pragma unroll
        for (int t = 0; t < 15; t++) {
            int jj = lane + t * 32;
            if (jj < LLN) {
                s0[t] = s0[t] * scale - slope * fabsf((float)(i0 - jj));
                s1[t] = s1[t] * scale - slope * fabsf((float)(i0 + 1 - jj));
                mx0 = fmaxf(mx0, s0[t]);
                mx1 = fmaxf(mx1, s1[t]);
            }
        }
        mx0 = warp_max(mx0); mx1 = warp_max(mx1);
        float sum0 = 0.f, sum1 = 0.f;
#pragma unroll
        for (int t = 0; t < 15; t++) {
            int jj = lane + t * 32;
            if (jj < LLN) {
                float e0 = __expf(s0[t] - mx0);
                float e1 = __expf(s1[t] - mx1);
                Ssm[(2 * w) * 457 + jj]     = e0;
                Ssm[(2 * w + 1) * 457 + jj] = e1;
                sum0 += e0; sum1 += e1;
            }
        }
        sum0 = warp_sum(sum0); sum1 = warp_sum(sum1);
        float inv0 = 1.f / sum0, inv1 = 1.f / sum1;
        __syncwarp();

        // out: lane owns dim d = lane
        float acc0 = 0.f, acc1 = 0.f;
        const float* p0 = Ssm + (2 * w) * 457;
        const float* p1 = Ssm + (2 * w + 1) * 457;
#pragma unroll 4
        for (int j = 0; j < LLN; j++) {
            float v = Vsm[j * 32 + lane];
            acc0 += p0[j] * v;
            acc1 += p1[j] * v;
        }
        float* op = O + ((size_t)b * LLN + i0) * DD + h * HDD + lane;
        op[0] = acc0 * inv0;
        if (two) op[DD] = acc1 * inv1;
        __syncwarp();
    }
}

// ---------------- fused residual add + LayerNorm (warp per row), in-place on X ----------------
__global__ void __launch_bounds__(256) add_ln_kernel(float* __restrict__ X,
                                                     const float* __restrict__ T,
                                                     const float* __restrict__ g,
                                                     const float* __restrict__ bta)
{
    const int w = threadIdx.x >> 5, lane = threadIdx.x & 31;
    const size_t row = (size_t)blockIdx.x * 8 + w;
    float* xr = X + row * DD;
    const float* tr = T + row * DD;

    float4 x0 = ((const float4*)xr)[lane];
    float4 x1 = ((const float4*)xr)[lane + 32];
    float4 t0 = ((const float4*)tr)[lane];
    float4 t1 = ((const float4*)tr)[lane + 32];
    float v[8] = {x0.x + t0.x, x0.y + t0.y, x0.z + t0.z, x0.w + t0.w,
                  x1.x + t1.x, x1.y + t1.y, x1.z + t1.z, x1.w + t1.w};
    float s = 0.f;
#pragma unroll
    for (int i = 0; i < 8; i++) s += v[i];
    float m = warp_sum(s) * (1.f / 256.f);
    float vs = 0.f;
#pragma unroll
    for (int i = 0; i < 8; i++) { float d = v[i] - m; vs += d * d; }
    float rstd = rsqrtf(warp_sum(vs) * (1.f / 256.f) + 1e-5f);

    float4 g0 = ((const float4*)g)[lane];
    float4 g1 = ((const float4*)g)[lane + 32];
    float4 b0 = ((const float4*)bta)[lane];
    float4 b1 = ((const float4*)bta)[lane + 32];
    float4 o0 = make_float4((v[0]-m)*rstd*g0.x + b0.x, (v[1]-m)*rstd*g0.y + b0.y,
                            (v[2]-m)*rstd*g0.z + b0.z, (v[3]-m)*rstd*g0.w + b0.w);
    float4 o1 = make_float4((v[4]-m)*rstd*g1.x + b1.x, (v[5]-m)*rstd*g1.y + b1.y,
                            (v[6]-m)*rstd*g1.z + b1.z, (v[7]-m)*rstd*g1.w + b1.w);
    ((float4*)xr)[lane]      = o0;
    ((float4*)xr)[lane + 32] = o1;
}

// ---------------- head: per-row th1 -> BN -> gelu -> th2 scalar score ----------------
__global__ void __launch_bounds__(256) head_kernel(
    const float* __restrict__ X,   const float* __restrict__ th1_w,
    const float* __restrict__ th1_b, const float* __restrict__ bn_g,
    const float* __restrict__ bn_b,  const float* __restrict__ th2_w,
    const float* __restrict__ th2_b, float* __restrict__ S)
{
    __shared__ float wsm[DD * 32];   // 32 KB: th1_w staged
    __shared__ float xs[8][DD];      // 8 KB: 8 rows
    const int tid = threadIdx.x, w = tid >> 5, lane = tid & 31;

    for (int i = tid; i < DD * 32 / 4; i += 256)
        ((float4*)wsm)[i] = ((const float4*)th1_w)[i];

    const size_t row = (size_t)blockIdx.x * 8 + w;
    const float4* xr = (const float4*)(X + row * DD);
    float4* xd = (float4*)xs[w];
    xd[lane]      = xr[lane];
    xd[lane + 32] = xr[lane + 32];
    __syncthreads();

    float acc = th1_b[lane];
#pragma unroll 4
    for (int d = 0; d < DD; d++)
        acc += xs[w][d] * wsm[d * 32 + lane];

    float hv = acc * (bn_g[lane] * rsqrtf(1.f + 1e-5f)) + bn_b[lane];
    const float c = 0.7978845608028654f;   // sqrt(2/pi)
    float gl = 0.5f * hv * (1.f + tanhf(c * (hv + 0.044715f * hv * hv * hv)));
    float p = warp_sum(gl * th2_w[lane]);
    if (lane == 0) S[row] = p + th2_b[0];
}

// ---------------- pool: softmax over L, weighted sum of X -> out[b,d] ----------------
__global__ void __launch_bounds__(256) pool_kernel(const float* __restrict__ X,
                                                   const float* __restrict__ S,
                                                   float* __restrict__ out)
{
    __shared__ float wv[LLN];
    __shared__ float red[256];
    const int b = blockIdx.x, tid = threadIdx.x;
    const float* sp = S + (size_t)b * LLN;

    float mx = -1e30f;
    for (int l = tid; l < LLN; l += 256) mx = fmaxf(mx, sp[l]);
    red[tid] = mx; __syncthreads();
    for (int s = 128; s; s >>= 1) { if (tid < s) red[tid] = fmaxf(red[tid], red[tid + s]); __syncthreads(); }
    mx = red[0]; __syncthreads();

    float sum = 0.f;
    for (int l = tid; l < LLN; l += 256) { float e = __expf(sp[l] - mx); wv[l] = e; sum += e; }
    red[tid] = sum; __syncthreads();
    for (int s = 128; s; s >>= 1) { if (tid < s) red[tid] += red[tid + s]; __syncthreads(); }
    float inv = 1.f / red[0];
    __syncthreads();

    float acc = 0.f;
    const float* xp = X + (size_t)b * LLN * DD + tid;
#pragma unroll 4
    for (int l = 0; l < LLN; l++) acc += wv[l] * xp[(size_t)l * DD];
    out[(size_t)b * DD + tid] = acc * inv;
}

// ---------------- launch ----------------
extern "C" void kernel_launch(void* const* d_in, const int* in_sizes, int n_in,
                              void* d_out, int out_size)
{
    const float* gene_exp = (const float*)d_in[0];
    const float* coords   = (const float*)d_in[1];
    const float* w_in     = (const float*)d_in[2];
    const float* b_in     = (const float*)d_in[3];
    const float* w_cls    = (const float*)d_in[4];
    const float* b_cls    = (const float*)d_in[5];
    const float* qkv_w    = (const float*)d_in[6];
    const float* qkv_b    = (const float*)d_in[7];
    const float* ln1_g    = (const float*)d_in[8];
    const float* ln1_b    = (const float*)d_in[9];
    const float* ffn_w1   = (const float*)d_in[10];
    const float* ffn_b1   = (const float*)d_in[11];
    const float* ffn_w2   = (const float*)d_in[12];
    const float* ffn_b2   = (const float*)d_in[13];
    const float* ln2_g    = (const float*)d_in[14];
    const float* ln2_b    = (const float*)d_in[15];
    const float* th1_w    = (const float*)d_in[16];
    const float* th1_b    = (const float*)d_in[17];
    const float* bn_g     = (const float*)d_in[18];
    const float* bn_b     = (const float*)d_in[19];
    const float* th2_w    = (const float*)d_in[20];
    const float* th2_b    = (const float*)d_in[21];
    float* out = (float*)d_out;

    float *X, *T, *BIG, *S;
    cudaGetSymbolAddress((void**)&X,   g_X);
    cudaGetSymbolAddress((void**)&T,   g_T);
    cudaGetSymbolAddress((void**)&BIG, g_BIG);
    cudaGetSymbolAddress((void**)&S,   g_S);

    cudaFuncSetAttribute(attn_kernel, cudaFuncAttributeMaxDynamicSharedMemorySize,
                         ATTN_SMEM_BYTES);

    // embed: CLS row + token GEMM (remapped rows interleave CLS)
    cls_kernel<<<BB, 256>>>(coords, w_cls, b_cls, X);
    gemm_kernel<false, true><<<dim3(NTT * BB / 64, DD / 128), 256>>>(
        gene_exp, w_in, b_in, X, TOKK, DD);

    for (int l = 0; l < 4; l++) {
        // QKV projection -> BIG
        gemm_kernel<false, false><<<dim3(MROWS / 64, (3 * DD) / 128), 256>>>(
            X, qkv_w + (size_t)l * DD * 3 * DD, qkv_b + (size_t)l * 3 * DD, BIG, DD, 3 * DD);
        // attention -> T
        attn_kernel<<<BB * HH, 256, ATTN_SMEM_BYTES>>>(BIG, T);
        // X = LN(X + T)
        add_ln_kernel<<<MROWS / 8, 256>>>(X, T, ln1_g + l * DD, ln1_b + l * DD);
        // FFN1 (relu) -> BIG
        gemm_kernel<true, false><<<dim3(MROWS / 64, FFF / 128), 256>>>(
            X, ffn_w1 + (size_t)l * DD * FFF, ffn_b1 + (size_t)l * FFF, BIG, DD, FFF);
        // FFN2 -> T
        gemm_kernel<false, false><<<dim3(MROWS / 64, DD / 128), 256>>>(
            BIG, ffn_w2 + (size_t)l * FFF * DD, ffn_b2 + (size_t)l * DD, T, FFF, DD);
        // X = LN(X + T)
        add_ln_kernel<<<MROWS / 8, 256>>>(X, T, ln2_g + l * DD, ln2_b + l * DD);
    }

    head_kernel<<<MROWS / 8, 256>>>(X, th1_w, th1_b, bn_g, bn_b, th2_w, th2_b, S);
    pool_kernel<<<BB, 256>>>(X, S, out);
}

// round 12
// speedup vs baseline: 1.5870x; 1.5870x over previous
#include <cuda_runtime.h>
#include <cuda_bf16.h>
#include <math.h>
#include <stdint.h>

// ---------------- problem constants ----------------
#define BB   64
#define NTT  456
#define TOKK 64
#define DD   256
#define HH   8
#define HDD  32
#define FFF  1024
#define LLN  457            // L = NT + 1
#define MROWS (BB * LLN)    // 29248

// ---------------- device scratch (static, no allocs) ----------------
__device__ float g_X  [MROWS * DD];
__device__ float g_T  [MROWS * DD];
__device__ float g_BIG[MROWS * FFF];
__device__ float g_S  [MROWS];

// ---------------- helpers ----------------
__device__ __forceinline__ float warp_sum(float v) {
#pragma unroll
    for (int o = 16; o; o >>= 1) v += __shfl_xor_sync(0xffffffffu, v, o);
    return v;
}
__device__ __forceinline__ float warp_max(float v) {
#pragma unroll
    for (int o = 16; o; o >>= 1) v = fmaxf(v, __shfl_xor_sync(0xffffffffu, v, o));
    return v;
}
__device__ __forceinline__ uint32_t smem_u32(const void* p) {
    uint32_t a;
    asm("{ .reg .u64 t; cvta.to.shared.u64 t, %1; cvt.u32.u64 %0, t; }"
        : "=r"(a) : "l"(p));
    return a;
}
__device__ __forceinline__ uint32_t pack_bf16(float lo, float hi) {
    uint32_t r;   // lo -> low half, hi -> high half
    asm("cvt.rn.bf16x2.f32 %0, %1, %2;" : "=r"(r) : "f"(hi), "f"(lo));
    return r;
}
__device__ __forceinline__ void split2(float x, float& hi, float& lo) {
    __nv_bfloat16 h = __float2bfloat16_rn(x);
    hi = __bfloat162float(h);
    lo = x - hi;
}
// SW64 swizzle for 64-byte rows (8-row atom, conflict-free ldmatrix/STS)
__device__ __forceinline__ uint32_t swz64(uint32_t x) {
    return x ^ ((x >> 3) & 0x30);
}
__device__ __forceinline__ void ldsm4(uint32_t* r, uint32_t addr) {
    asm volatile("ldmatrix.sync.aligned.m8n8.x4.shared.b16 {%0,%1,%2,%3}, [%4];"
                 : "=r"(r[0]), "=r"(r[1]), "=r"(r[2]), "=r"(r[3]) : "r"(addr));
}
__device__ __forceinline__ void mma_bf16(float* d, const uint32_t* a, const uint32_t* b) {
    asm volatile(
        "mma.sync.aligned.m16n8k16.row.col.f32.bf16.bf16.f32 "
        "{%0,%1,%2,%3}, {%4,%5,%6,%7}, {%8,%9}, {%0,%1,%2,%3};"
        : "+f"(d[0]), "+f"(d[1]), "+f"(d[2]), "+f"(d[3])
        : "r"(a[0]), "r"(a[1]), "r"(a[2]), "r"(a[3]), "r"(b[0]), "r"(b[1]));
}

// =====================================================================
// Tensor-core bf16-split GEMM: C[M,N] = A[M,K] @ W[K,N] + bias (opt relu)
// BM=128, BN=128, BK=32, 256 threads (8 warps, warp tile 32x64).
// 3-term split: Ahi*Whi + Ahi*Wlo + Alo*Whi, fp32 accumulate.
// =====================================================================
#define STG_BYTES 32768   // per stage: AHI 8K, ALO 8K, WHI 8K, WLO 8K
#define GEMM_SMEM (2 * STG_BYTES)

template<bool RELU>
__global__ void __launch_bounds__(256, 1)
gemmM_kernel(const float* __restrict__ A, const float* __restrict__ W,
             const float* __restrict__ bias, float* __restrict__ C,
             int M, int K, int N)
{
    extern __shared__ char smc[];
    const uint32_t sb = smem_u32(smc);

    const int tid  = threadIdx.x;
    const int lane = tid & 31, w = tid >> 5;
    const int wm = w & 3, wn = w >> 2;          // warp position: 4 x 2
    const int bm = blockIdx.x * 128, bn = blockIdx.y * 128;

    // ---- A gmem mapping: warp w loads rows w*16..+15, fully coalesced ----
    const float* Ap[4];
    uint32_t aoff[4];
#pragma unroll
    for (int i = 0; i < 4; i++) {
        int lr = w * 16 + i * 4 + (lane >> 3);       // local row 0..127
        int gr = bm + lr; if (gr >= M) gr = M - 1;   // clamp (store guarded)
        Ap[i]   = A + (size_t)gr * K + (lane & 7) * 4;
        aoff[i] = swz64((uint32_t)(lr * 64 + (lane & 7) * 8));
    }
    // ---- W gmem mapping: thread owns column n, half of k-chunk ----
    const int nidx = tid & 127, kh = tid >> 7;       // kh in {0,1}
    const float* Wp = W + bn + nidx;
    const uint32_t woff0 = swz64((uint32_t)(nidx * 64 + kh * 32));
    const uint32_t woff1 = swz64((uint32_t)(nidx * 64 + kh * 32 + 16));

    // ---- ldmatrix lane geometry ----
    const int g = lane >> 3, rr = lane & 7;
    const int a_row = wm * 32 + rr + (g & 1) * 8;    // + mt*16
    const int b_row = wn * 64 + rr + (g & 1) * 8;    // + np*16
    const int kbyt  = (g >> 1) * 16;                 // + ks*32

    float acc[2][8][4];
#pragma unroll
    for (int mt = 0; mt < 2; mt++)
#pragma unroll
        for (int nt = 0; nt < 8; nt++)
#pragma unroll
            for (int q = 0; q < 4; q++) acc[mt][nt][q] = 0.f;

    const int NC = K >> 5;

    // ---------- stage chunk 0 ----------
    {
        const uint32_t AHI = sb, ALO = sb + 8192, WHI = sb + 16384, WLO = sb + 24576;
#pragma unroll
        for (int i = 0; i < 4; i++) {
            float4 f = *(const float4*)(Ap[i]);
            float h0,h1,h2,h3,l0,l1,l2,l3;
            split2(f.x,h0,l0); split2(f.y,h1,l1); split2(f.z,h2,l2); split2(f.w,h3,l3);
            asm volatile("st.shared.v2.b32 [%0], {%1,%2};"
                         :: "r"(AHI + aoff[i]), "r"(pack_bf16(h0,h1)), "r"(pack_bf16(h2,h3)));
            asm volatile("st.shared.v2.b32 [%0], {%1,%2};"
                         :: "r"(ALO + aoff[i]), "r"(pack_bf16(l0,l1)), "r"(pack_bf16(l2,l3)));
        }
        float pw[16];
        const float* wB = Wp + (size_t)(kh * 16) * N;
#pragma unroll
        for (int j = 0; j < 16; j++) pw[j] = wB[(size_t)j * N];
        uint32_t hw[8], lw[8];
#pragma unroll
        for (int j = 0; j < 8; j++) {
            float h0,h1,l0,l1;
            split2(pw[2*j],h0,l0); split2(pw[2*j+1],h1,l1);
            hw[j] = pack_bf16(h0,h1); lw[j] = pack_bf16(l0,l1);
        }
        asm volatile("st.shared.v4.b32 [%0], {%1,%2,%3,%4};"
                     :: "r"(WHI+woff0), "r"(hw[0]),"r"(hw[1]),"r"(hw[2]),"r"(hw[3]));
        asm volatile("st.shared.v4.b32 [%0], {%1,%2,%3,%4};"
                     :: "r"(WHI+woff1), "r"(hw[4]),"r"(hw[5]),"r"(hw[6]),"r"(hw[7]));
        asm volatile("st.shared.v4.b32 [%0], {%1,%2,%3,%4};"
                     :: "r"(WLO+woff0), "r"(lw[0]),"r"(lw[1]),"r"(lw[2]),"r"(lw[3]));
        asm volatile("st.shared.v4.b32 [%0], {%1,%2,%3,%4};"
                     :: "r"(WLO+woff1), "r"(lw[4]),"r"(lw[5]),"r"(lw[6]),"r"(lw[7]));
    }
    __syncthreads();

    // ---------- main loop ----------
    for (int c = 0; c < NC; c++) {
        const bool pf = (c + 1 < NC);
        // prefetch next chunk into regs (consumed after MMAs)
        float4 pA[4];
        float  pw[16];
        if (pf) {
#pragma unroll
            for (int i = 0; i < 4; i++)
                pA[i] = *(const float4*)(Ap[i] + (c + 1) * 32);
            const float* wB = Wp + (size_t)((c + 1) * 32 + kh * 16) * N;
#pragma unroll
            for (int j = 0; j < 16; j++) pw[j] = wB[(size_t)j * N];
        }

        // ---- MMAs on buffer c&1 ----
        const uint32_t base = sb + (uint32_t)(c & 1) * STG_BYTES;
        const uint32_t AHI = base, ALO = base + 8192, WHI = base + 16384, WLO = base + 24576;
#pragma unroll
        for (int ks = 0; ks < 2; ks++) {
            uint32_t Ah[2][4], Al[2][4];
#pragma unroll
            for (int mt = 0; mt < 2; mt++) {
                uint32_t off = swz64((uint32_t)((a_row + mt * 16) * 64 + kbyt + ks * 32));
                ldsm4(Ah[mt], AHI + off);
                ldsm4(Al[mt], ALO + off);
            }
            uint32_t Bh[8][2], Bl[8][2];
#pragma unroll
            for (int np = 0; np < 4; np++) {
                uint32_t off = swz64((uint32_t)((b_row + np * 16) * 64 + kbyt + ks * 32));
                uint32_t t4[4];
                ldsm4(t4, WHI + off);
                Bh[2*np][0] = t4[0]; Bh[2*np+1][0] = t4[1];
                Bh[2*np][1] = t4[2]; Bh[2*np+1][1] = t4[3];
                ldsm4(t4, WLO + off);
                Bl[2*np][0] = t4[0]; Bl[2*np+1][0] = t4[1];
                Bl[2*np][1] = t4[2]; Bl[2*np+1][1] = t4[3];
            }
#pragma unroll
            for (int mt = 0; mt < 2; mt++)
#pragma unroll
                for (int nt = 0; nt < 8; nt++) {
                    mma_bf16(acc[mt][nt], Ah[mt], Bh[nt]);
                    mma_bf16(acc[mt][nt], Ah[mt], Bl[nt]);
                    mma_bf16(acc[mt][nt], Al[mt], Bh[nt]);
                }
        }

        // ---- split + STS of next chunk into buffer (c+1)&1 ----
        if (pf) {
            const uint32_t nb = sb + (uint32_t)((c + 1) & 1) * STG_BYTES;
            const uint32_t nAHI = nb, nALO = nb + 8192, nWHI = nb + 16384, nWLO = nb + 24576;
#pragma unroll
            for (int i = 0; i < 4; i++) {
                float h0,h1,h2,h3,l0,l1,l2,l3;
                split2(pA[i].x,h0,l0); split2(pA[i].y,h1,l1);
                split2(pA[i].z,h2,l2); split2(pA[i].w,h3,l3);
                asm volatile("st.shared.v2.b32 [%0], {%1,%2};"
                             :: "r"(nAHI + aoff[i]), "r"(pack_bf16(h0,h1)), "r"(pack_bf16(h2,h3)));
                asm volatile("st.shared.v2.b32 [%0], {%1,%2};"
                             :: "r"(nALO + aoff[i]), "r"(pack_bf16(l0,l1)), "r"(pack_bf16(l2,l3)));
            }
            uint32_t hw[8], lw[8];
#pragma unroll
            for (int j = 0; j < 8; j++) {
                float h0,h1,l0,l1;
                split2(pw[2*j],h0,l0); split2(pw[2*j+1],h1,l1);
                hw[j] = pack_bf16(h0,h1); lw[j] = pack_bf16(l0,l1);
            }
            asm volatile("st.shared.v4.b32 [%0], {%1,%2,%3,%4};"
                         :: "r"(nWHI+woff0), "r"(hw[0]),"r"(hw[1]),"r"(hw[2]),"r"(hw[3]));
            asm volatile("st.shared.v4.b32 [%0], {%1,%2,%3,%4};"
                         :: "r"(nWHI+woff1), "r"(hw[4]),"r"(hw[5]),"r"(hw[6]),"r"(hw[7]));
            asm volatile("st.shared.v4.b32 [%0], {%1,%2,%3,%4};"
                         :: "r"(nWLO+woff0), "r"(lw[0]),"r"(lw[1]),"r"(lw[2]),"r"(lw[3]));
            asm volatile("st.shared.v4.b32 [%0], {%1,%2,%3,%4};"
                         :: "r"(nWLO+woff1), "r"(lw[4]),"r"(lw[5]),"r"(lw[6]),"r"(lw[7]));
        }
        __syncthreads();
    }

    // ---------- epilogue: regs -> gmem ----------
#pragma unroll
    for (int mt = 0; mt < 2; mt++) {
        const int gr0 = bm + wm * 32 + mt * 16 + (lane >> 2);
        const int gr1 = gr0 + 8;
#pragma unroll
        for (int nt = 0; nt < 8; nt++) {
            const int gc = bn + wn * 64 + nt * 8 + (lane & 3) * 2;
            float2 bz = *(const float2*)(bias + gc);
            float v0 = acc[mt][nt][0] + bz.x, v1 = acc[mt][nt][1] + bz.y;
            float v2 = acc[mt][nt][2] + bz.x, v3 = acc[mt][nt][3] + bz.y;
            if (RELU) {
                v0 = fmaxf(v0, 0.f); v1 = fmaxf(v1, 0.f);
                v2 = fmaxf(v2, 0.f); v3 = fmaxf(v3, 0.f);
            }
            if (gr0 < M) *(float2*)(C + (size_t)gr0 * N + gc) = make_float2(v0, v1);
            if (gr1 < M) *(float2*)(C + (size_t)gr1 * N + gc) = make_float2(v2, v3);
        }
    }
}

// ---------------- SIMT SGEMM for embed (tiny, needs row remap) ----------------
template<bool RELU, bool REMAP>
__global__ void __launch_bounds__(256) gemm_kernel(
    const float* __restrict__ A, const float* __restrict__ W,
    const float* __restrict__ bias, float* __restrict__ C,
    int K, int N)
{
    __shared__ __align__(16) float As[16][68];
    __shared__ __align__(16) float Bs[16][128];

    const int tid = threadIdx.x;
    const int tx  = tid & 15;
    const int ty  = tid >> 4;
    const int bm  = blockIdx.x * 64;
    const int bn  = blockIdx.y * 128;

    const int la_r = tid >> 2;
    const int la_k = (tid & 3) << 2;
    const int lb_r = tid >> 5;
    const int lb_c = (tid & 31) << 2;

    const float* Aptr  = A + (size_t)(bm + la_r) * K + la_k;
    const float* Wptr0 = W + (size_t)lb_r * N + bn + lb_c;
    const float* Wptr1 = W + (size_t)(lb_r + 8) * N + bn + lb_c;

    float acc[4][8];
#pragma unroll
    for (int i = 0; i < 4; i++)
#pragma unroll
        for (int j = 0; j < 8; j++) acc[i][j] = 0.f;

    for (int k0 = 0; k0 < K; k0 += 16) {
        float4 av  = *(const float4*)(Aptr + k0);
        float4 bw0 = *(const float4*)(Wptr0 + (size_t)k0 * N);
        float4 bw1 = *(const float4*)(Wptr1 + (size_t)k0 * N);
        As[la_k + 0][la_r] = av.x;
        As[la_k + 1][la_r] = av.y;
        As[la_k + 2][la_r] = av.z;
        As[la_k + 3][la_r] = av.w;
        *(float4*)&Bs[lb_r][lb_c]     = bw0;
        *(float4*)&Bs[lb_r + 8][lb_c] = bw1;
        __syncthreads();
#pragma unroll
        for (int kk = 0; kk < 16; kk++) {
            float4 a  = *(const float4*)&As[kk][ty * 4];
            float4 b0 = *(const float4*)&Bs[kk][tx * 8];
            float4 b1 = *(const float4*)&Bs[kk][tx * 8 + 4];
            float ar[4] = {a.x, a.y, a.z, a.w};
            float br[8] = {b0.x, b0.y, b0.z, b0.w, b1.x, b1.y, b1.z, b1.w};
#pragma unroll
            for (int i = 0; i < 4; i++)
#pragma unroll
                for (int j = 0; j < 8; j++)
                    acc[i][j] = fmaf(ar[i], br[j], acc[i][j]);
        }
        __syncthreads();
    }

    float4 bb0 = *(const float4*)(bias + bn + tx * 8);
    float4 bb1 = *(const float4*)(bias + bn + tx * 8 + 4);
    float bx[8] = {bb0.x, bb0.y, bb0.z, bb0.w, bb1.x, bb1.y, bb1.z, bb1.w};

#pragma unroll
    for (int i = 0; i < 4; i++) {
        int r = bm + ty * 4 + i;
        int orow = REMAP ? (r + r / NTT + 1) : r;
        float o[8];
#pragma unroll
        for (int j = 0; j < 8; j++) {
            float v = acc[i][j] + bx[j];
            if (RELU) v = fmaxf(v, 0.f);
            o[j] = v;
        }
        float4* cp = (float4*)(C + (size_t)orow * N + bn + tx * 8);
        cp[0] = make_float4(o[0], o[1], o[2], o[3]);
        cp[1] = make_float4(o[4], o[5], o[6], o[7]);
    }
}

// ---------------- CLS row ----------------
__global__ void cls_kernel(const float* __restrict__ coords,
                           const float* __restrict__ w_cls,
                           const float* __restrict__ b_cls,
                           float* __restrict__ X)
{
    int b = blockIdx.x, d = threadIdx.x;
    float c0 = coords[b * 3 + 0], c1 = coords[b * 3 + 1], c2 = coords[b * 3 + 2];
    X[(size_t)b * LLN * DD + d] =
        b_cls[d] + c0 * w_cls[d] + c1 * w_cls[DD + d] + c2 * w_cls[2 * DD + d];
}

// ---------------- fused attention ----------------
#define ATTN_SMEM_FLOATS (457*33 + 457*32 + 16*457 + 8*64)
#define ATTN_SMEM_BYTES  (ATTN_SMEM_FLOATS * 4)

__global__ void __launch_bounds__(256) attn_kernel(const float* __restrict__ QKV,
                                                   float* __restrict__ O)
{
    extern __shared__ float sm[];
    float* Ksm = sm;
    float* Vsm = Ksm + 457 * 33;
    float* Ssm = Vsm + 457 * 32;
    float* Qsm = Ssm + 16 * 457;

    const int bh = blockIdx.x;
    const int b = bh >> 3, h = bh & 7;
    const int tid = threadIdx.x, w = tid >> 5, lane = tid & 31;
    const float slope = (h < 4) ? 1.0f : 0.5f;
    const float scale = 0.17677669529663687f;

    const float* base = QKV + (size_t)b * (LLN * 3 * DD) + h * HDD;

    for (int idx = tid; idx < 457 * 32; idx += 256) {
        int j = idx >> 5, d = idx & 31;
        const float* kv = base + (size_t)j * (3 * DD);
        Ksm[j * 33 + d] = kv[DD + d];
        Vsm[idx]        = kv[2 * DD + d];
    }
    __syncthreads();

    for (int i0 = 2 * w; i0 < LLN; i0 += 16) {
        const bool two = (i0 + 1 < LLN);
        Qsm[w * 64 + lane] = base[(size_t)i0 * (3 * DD) + lane];
        if (two) Qsm[w * 64 + 32 + lane] = base[(size_t)(i0 + 1) * (3 * DD) + lane];
        __syncwarp();

        float s0[15], s1[15];
#pragma unroll
        for (int t = 0; t < 15; t++) { s0[t] = 0.f; s1[t] = 0.f; }
        for (int d = 0; d < 32; d++) {
            float q0 = Qsm[w * 64 + d];
            float q1 = Qsm[w * 64 + 32 + d];
#pragma unroll
            for (int t = 0; t < 15; t++) {
                int jj = lane + t * 32;
                if (jj < LLN) {
                    float kv = Ksm[jj * 33 + d];
                    s0[t] += q0 * kv;
                    s1[t] += q1 * kv;
                }
            }
        }
        float mx0 = -1e30f, mx1 = -1e30f;
#pragma unroll
        for (int t = 0; t < 15; t++) {
            int jj = lane + t * 32;
            if (jj < LLN) {
                s0[t] = s0[t] * scale - slope * fabsf((float)(i0 - jj));
                s1[t] = s1[t] * scale - slope * fabsf((float)(i0 + 1 - jj));
                mx0 = fmaxf(mx0, s0[t]);
                mx1 = fmaxf(mx1, s1[t]);
            }
        }
        mx0 = warp_max(mx0); mx1 = warp_max(mx1);
        float sum0 = 0.f, sum1 = 0.f;
#pragma unroll
        for (int t = 0; t < 15; t++) {
            int jj = lane + t * 32;
            if (jj < LLN) {
                float e0 = __expf(s0[t] - mx0);
                float e1 = __expf(s1[t] - mx1);
                Ssm[(2 * w) * 457 + jj]     = e0;
                Ssm[(2 * w + 1) * 457 + jj] = e1;
                sum0 += e0; sum1 += e1;
            }
        }
        sum0 = warp_sum(sum0); sum1 = warp_sum(sum1);
        float inv0 = 1.f / sum0, inv1 = 1.f / sum1;
        __syncwarp();

        float acc0 = 0.f, acc1 = 0.f;
        const float* p0 = Ssm + (2 * w) * 457;
        const float* p1 = Ssm + (2 * w + 1) * 457;
#pragma unroll 4
        for (int j = 0; j < LLN; j++) {
            float v = Vsm[j * 32 + lane];
            acc0 += p0[j] * v;
            acc1 += p1[j] * v;
        }
        float* op = O + ((size_t)b * LLN + i0) * DD + h * HDD + lane;
        op[0] = acc0 * inv0;
        if (two) op[DD] = acc1 * inv1;
        __syncwarp();
    }
}

// ---------------- fused residual add + LayerNorm ----------------
__global__ void __launch_bounds__(256) add_ln_kernel(float* __restrict__ X,
                                                     const float* __restrict__ T,
                                                     const float* __restrict__ g,
                                                     const float* __restrict__ bta)
{
    const int w = threadIdx.x >> 5, lane = threadIdx.x & 31;
    const size_t row = (size_t)blockIdx.x * 8 + w;
    float* xr = X + row * DD;
    const float* tr = T + row * DD;

    float4 x0 = ((const float4*)xr)[lane];
    float4 x1 = ((const float4*)xr)[lane + 32];
    float4 t0 = ((const float4*)tr)[lane];
    float4 t1 = ((const float4*)tr)[lane + 32];
    float v[8] = {x0.x + t0.x, x0.y + t0.y, x0.z + t0.z, x0.w + t0.w,
                  x1.x + t1.x, x1.y + t1.y, x1.z + t1.z, x1.w + t1.w};
    float s = 0.f;
#pragma unroll
    for (int i = 0; i < 8; i++) s += v[i];
    float m = warp_sum(s) * (1.f / 256.f);
    float vs = 0.f;
#pragma unroll
    for (int i = 0; i < 8; i++) { float d = v[i] - m; vs += d * d; }
    float rstd = rsqrtf(warp_sum(vs) * (1.f / 256.f) + 1e-5f);

    float4 g0 = ((const float4*)g)[lane];
    float4 g1 = ((const float4*)g)[lane + 32];
    float4 b0 = ((const float4*)bta)[lane];
    float4 b1 = ((const float4*)bta)[lane + 32];
    float4 o0 = make_float4((v[0]-m)*rstd*g0.x + b0.x, (v[1]-m)*rstd*g0.y + b0.y,
                            (v[2]-m)*rstd*g0.z + b0.z, (v[3]-m)*rstd*g0.w + b0.w);
    float4 o1 = make_float4((v[4]-m)*rstd*g1.x + b1.x, (v[5]-m)*rstd*g1.y + b1.y,
                            (v[6]-m)*rstd*g1.z + b1.z, (v[7]-m)*rstd*g1.w + b1.w);
    ((float4*)xr)[lane]      = o0;
    ((float4*)xr)[lane + 32] = o1;
}

// ---------------- head ----------------
__global__ void __launch_bounds__(256) head_kernel(
    const float* __restrict__ X,   const float* __restrict__ th1_w,
    const float* __restrict__ th1_b, const float* __restrict__ bn_g,
    const float* __restrict__ bn_b,  const float* __restrict__ th2_w,
    const float* __restrict__ th2_b, float* __restrict__ S)
{
    __shared__ float wsm[DD * 32];
    __shared__ float xs[8][DD];
    const int tid = threadIdx.x, w = tid >> 5, lane = tid & 31;

    for (int i = tid; i < DD * 32 / 4; i += 256)
        ((float4*)wsm)[i] = ((const float4*)th1_w)[i];

    const size_t row = (size_t)blockIdx.x * 8 + w;
    const float4* xr = (const float4*)(X + row * DD);
    float4* xd = (float4*)xs[w];
    xd[lane]      = xr[lane];
    xd[lane + 32] = xr[lane + 32];
    __syncthreads();

    float acc = th1_b[lane];
#pragma unroll 4
    for (int d = 0; d < DD; d++)
        acc += xs[w][d] * wsm[d * 32 + lane];

    float hv = acc * (bn_g[lane] * rsqrtf(1.f + 1e-5f)) + bn_b[lane];
    const float c = 0.7978845608028654f;
    float gl = 0.5f * hv * (1.f + tanhf(c * (hv + 0.044715f * hv * hv * hv)));
    float p = warp_sum(gl * th2_w[lane]);
    if (lane == 0) S[row] = p + th2_b[0];
}

// ---------------- pool ----------------
__global__ void __launch_bounds__(256) pool_kernel(const float* __restrict__ X,
                                                   const float* __restrict__ S,
                                                   float* __restrict__ out)
{
    __shared__ float wv[LLN];
    __shared__ float red[256];
    const int b = blockIdx.x, tid = threadIdx.x;
    const float* sp = S + (size_t)b * LLN;

    float mx = -1e30f;
    for (int l = tid; l < LLN; l += 256) mx = fmaxf(mx, sp[l]);
    red[tid] = mx; __syncthreads();
    for (int s = 128; s; s >>= 1) { if (tid < s) red[tid] = fmaxf(red[tid], red[tid + s]); __syncthreads(); }
    mx = red[0]; __syncthreads();

    float sum = 0.f;
    for (int l = tid; l < LLN; l += 256) { float e = __expf(sp[l] - mx); wv[l] = e; sum += e; }
    red[tid] = sum; __syncthreads();
    for (int s = 128; s; s >>= 1) { if (tid < s) red[tid] += red[tid + s]; __syncthreads(); }
    float inv = 1.f / red[0];
    __syncthreads();

    float acc = 0.f;
    const float* xp = X + (size_t)b * LLN * DD + tid;
#pragma unroll 4
    for (int l = 0; l < LLN; l++) acc += wv[l] * xp[(size_t)l * DD];
    out[(size_t)b * DD + tid] = acc * inv;
}

// ---------------- launch ----------------
extern "C" void kernel_launch(void* const* d_in, const int* in_sizes, int n_in,
                              void* d_out, int out_size)
{
    const float* gene_exp = (const float*)d_in[0];
    const float* coords   = (const float*)d_in[1];
    const float* w_in     = (const float*)d_in[2];
    const float* b_in     = (const float*)d_in[3];
    const float* w_cls    = (const float*)d_in[4];
    const float* b_cls    = (const float*)d_in[5];
    const float* qkv_w    = (const float*)d_in[6];
    const float* qkv_b    = (const float*)d_in[7];
    const float* ln1_g    = (const float*)d_in[8];
    const float* ln1_b    = (const float*)d_in[9];
    const float* ffn_w1   = (const float*)d_in[10];
    const float* ffn_b1   = (const float*)d_in[11];
    const float* ffn_w2   = (const float*)d_in[12];
    const float* ffn_b2   = (const float*)d_in[13];
    const float* ln2_g    = (const float*)d_in[14];
    const float* ln2_b    = (const float*)d_in[15];
    const float* th1_w    = (const float*)d_in[16];
    const float* th1_b    = (const float*)d_in[17];
    const float* bn_g     = (const float*)d_in[18];
    const float* bn_b     = (const float*)d_in[19];
    const float* th2_w    = (const float*)d_in[20];
    const float* th2_b    = (const float*)d_in[21];
    float* out = (float*)d_out;

    float *X, *T, *BIG, *S;
    cudaGetSymbolAddress((void**)&X,   g_X);
    cudaGetSymbolAddress((void**)&T,   g_T);
    cudaGetSymbolAddress((void**)&BIG, g_BIG);
    cudaGetSymbolAddress((void**)&S,   g_S);

    cudaFuncSetAttribute(attn_kernel, cudaFuncAttributeMaxDynamicSharedMemorySize,
                         ATTN_SMEM_BYTES);
    cudaFuncSetAttribute(gemmM_kernel<false>, cudaFuncAttributeMaxDynamicSharedMemorySize,
                         GEMM_SMEM);
    cudaFuncSetAttribute(gemmM_kernel<true>, cudaFuncAttributeMaxDynamicSharedMemorySize,
                         GEMM_SMEM);

    const int GM = (MROWS + 127) / 128;   // 229

    // embed: CLS row + token GEMM (SIMT, remapped rows)
    cls_kernel<<<BB, 256>>>(coords, w_cls, b_cls, X);
    gemm_kernel<false, true><<<dim3(NTT * BB / 64, DD / 128), 256>>>(
        gene_exp, w_in, b_in, X, TOKK, DD);

    for (int l = 0; l < 4; l++) {
        gemmM_kernel<false><<<dim3(GM, (3 * DD) / 128), 256, GEMM_SMEM>>>(
            X, qkv_w + (size_t)l * DD * 3 * DD, qkv_b + (size_t)l * 3 * DD, BIG,
            MROWS, DD, 3 * DD);
        attn_kernel<<<BB * HH, 256, ATTN_SMEM_BYTES>>>(BIG, T);
        add_ln_kernel<<<MROWS / 8, 256>>>(X, T, ln1_g + l * DD, ln1_b + l * DD);
        gemmM_kernel<true><<<dim3(GM, FFF / 128), 256, GEMM_SMEM>>>(
            X, ffn_w1 + (size_t)l * DD * FFF, ffn_b1 + (size_t)l * FFF, BIG,
            MROWS, DD, FFF);
        gemmM_kernel<false><<<dim3(GM, DD / 128), 256, GEMM_SMEM>>>(
            BIG, ffn_w2 + (size_t)l * FFF * DD, ffn_b2 + (size_t)l * DD, T,
            MROWS, FFF, DD);
        add_ln_kernel<<<MROWS / 8, 256>>>(X, T, ln2_g + l * DD, ln2_b + l * DD);
    }

    head_kernel<<<MROWS / 8, 256>>>(X, th1_w, th1_b, bn_g, bn_b, th2_w, th2_b, S);
    pool_kernel<<<BB, 256>>>(X, S, out);
}

// round 13
// speedup vs baseline: 1.5895x; 1.0016x over previous
#include <cuda_runtime.h>
#include <cuda_bf16.h>
#include <math.h>
#include <stdint.h>

// ---------------- problem constants ----------------
#define BB   64
#define NTT  456
#define TOKK 64
#define DD   256
#define HH   8
#define HDD  32
#define FFF  1024
#define LLN  457            // L = NT + 1
#define MROWS (BB * LLN)    // 29248

// ---------------- device scratch (static, no allocs) ----------------
__device__ float g_X  [MROWS * DD];
__device__ float g_T  [MROWS * DD];
__device__ float g_BIG[MROWS * FFF];
__device__ float g_S  [MROWS];

// ---------------- helpers ----------------
__device__ __forceinline__ float warp_sum(float v) {
#pragma unroll
    for (int o = 16; o; o >>= 1) v += __shfl_xor_sync(0xffffffffu, v, o);
    return v;
}
__device__ __forceinline__ float warp_max(float v) {
#pragma unroll
    for (int o = 16; o; o >>= 1) v = fmaxf(v, __shfl_xor_sync(0xffffffffu, v, o));
    return v;
}
__device__ __forceinline__ uint32_t smem_u32(const void* p) {
    uint32_t a;
    asm("{ .reg .u64 t; cvta.to.shared.u64 t, %1; cvt.u32.u64 %0, t; }"
        : "=r"(a) : "l"(p));
    return a;
}
__device__ __forceinline__ uint32_t pack_bf16(float lo, float hi) {
    uint32_t r;   // lo -> low half, hi -> high half
    asm("cvt.rn.bf16x2.f32 %0, %1, %2;" : "=r"(r) : "f"(hi), "f"(lo));
    return r;
}
__device__ __forceinline__ void split2(float x, float& hi, float& lo) {
    __nv_bfloat16 h = __float2bfloat16_rn(x);
    hi = __bfloat162float(h);
    lo = x - hi;
}
// SW64 swizzle for 64-byte rows (8-row atom, conflict-free ldmatrix/STS)
__device__ __forceinline__ uint32_t swz64(uint32_t x) {
    return x ^ ((x >> 3) & 0x30);
}
__device__ __forceinline__ void ldsm4(uint32_t* r, uint32_t addr) {
    asm volatile("ldmatrix.sync.aligned.m8n8.x4.shared.b16 {%0,%1,%2,%3}, [%4];"
                 : "=r"(r[0]), "=r"(r[1]), "=r"(r[2]), "=r"(r[3]) : "r"(addr));
}
__device__ __forceinline__ void mma_bf16(float* d, const uint32_t* a, const uint32_t* b) {
    asm volatile(
        "mma.sync.aligned.m16n8k16.row.col.f32.bf16.bf16.f32 "
        "{%0,%1,%2,%3}, {%4,%5,%6,%7}, {%8,%9}, {%0,%1,%2,%3};"
        : "+f"(d[0]), "+f"(d[1]), "+f"(d[2]), "+f"(d[3])
        : "r"(a[0]), "r"(a[1]), "r"(a[2]), "r"(a[3]), "r"(b[0]), "r"(b[1]));
}

// =====================================================================
// Tensor-core bf16-split GEMM: C[M,N] = A[M,K] @ W[K,N] + bias (opt relu)
// BM=128, BN=128, BK=32, 256 threads (8 warps, warp tile 32x64).
// 3-term split: Ahi*Whi + Ahi*Wlo + Alo*Whi, fp32 accumulate.
// =====================================================================
#define STG_BYTES 32768   // per stage: AHI 8K, ALO 8K, WHI 8K, WLO 8K
#define GEMM_SMEM (2 * STG_BYTES)

template<bool RELU>
__global__ void __launch_bounds__(256, 1)
gemmM_kernel(const float* __restrict__ A, const float* __restrict__ W,
             const float* __restrict__ bias, float* __restrict__ C,
             int M, int K, int N)
{
    extern __shared__ char smc[];
    const uint32_t sb = smem_u32(smc);

    const int tid  = threadIdx.x;
    const int lane = tid & 31, w = tid >> 5;
    const int wm = w & 3, wn = w >> 2;          // warp position: 4 x 2
    const int bm = blockIdx.x * 128, bn = blockIdx.y * 128;

    // ---- A gmem mapping: warp w loads rows w*16..+15, fully coalesced ----
    const float* Ap[4];
    uint32_t aoff[4];
#pragma unroll
    for (int i = 0; i < 4; i++) {
        int lr = w * 16 + i * 4 + (lane >> 3);       // local row 0..127
        int gr = bm + lr; if (gr >= M) gr = M - 1;   // clamp (store guarded)
        Ap[i]   = A + (size_t)gr * K + (lane & 7) * 4;
        aoff[i] = swz64((uint32_t)(lr * 64 + (lane & 7) * 8));
    }
    // ---- W gmem mapping: thread owns column n, half of k-chunk ----
    const int nidx = tid & 127, kh = tid >> 7;       // kh in {0,1}
    const float* Wp = W + bn + nidx;
    const uint32_t woff0 = swz64((uint32_t)(nidx * 64 + kh * 32));
    const uint32_t woff1 = swz64((uint32_t)(nidx * 64 + kh * 32 + 16));

    // ---- ldmatrix lane geometry ----
    const int g = lane >> 3, rr = lane & 7;
    const int a_row = wm * 32 + rr + (g & 1) * 8;    // + mt*16
    const int b_row = wn * 64 + rr + (g & 1) * 8;    // + np*16
    const int kbyt  = (g >> 1) * 16;                 // + ks*32

    float acc[2][8][4];
#pragma unroll
    for (int mt = 0; mt < 2; mt++)
#pragma unroll
        for (int nt = 0; nt < 8; nt++)
#pragma unroll
            for (int q = 0; q < 4; q++) acc[mt][nt][q] = 0.f;

    const int NC = K >> 5;

    // ---------- stage chunk 0 ----------
    {
        const uint32_t AHI = sb, ALO = sb + 8192, WHI = sb + 16384, WLO = sb + 24576;
#pragma unroll
        for (int i = 0; i < 4; i++) {
            float4 f = *(const float4*)(Ap[i]);
            float h0,h1,h2,h3,l0,l1,l2,l3;
            split2(f.x,h0,l0); split2(f.y,h1,l1); split2(f.z,h2,l2); split2(f.w,h3,l3);
            asm volatile("st.shared.v2.b32 [%0], {%1,%2};"
                         :: "r"(AHI + aoff[i]), "r"(pack_bf16(h0,h1)), "r"(pack_bf16(h2,h3)));
            asm volatile("st.shared.v2.b32 [%0], {%1,%2};"
                         :: "r"(ALO + aoff[i]), "r"(pack_bf16(l0,l1)), "r"(pack_bf16(l2,l3)));
        }
        float pw[16];
        const float* wB = Wp + (size_t)(kh * 16) * N;
#pragma unroll
        for (int j = 0; j < 16; j++) pw[j] = wB[(size_t)j * N];
        uint32_t hw[8], lw[8];
#pragma unroll
        for (int j = 0; j < 8; j++) {
            float h0,h1,l0,l1;
            split2(pw[2*j],h0,l0); split2(pw[2*j+1],h1,l1);
            hw[j] = pack_bf16(h0,h1); lw[j] = pack_bf16(l0,l1);
        }
        asm volatile("st.shared.v4.b32 [%0], {%1,%2,%3,%4};"
                     :: "r"(WHI+woff0), "r"(hw[0]),"r"(hw[1]),"r"(hw[2]),"r"(hw[3]));
        asm volatile("st.shared.v4.b32 [%0], {%1,%2,%3,%4};"
                     :: "r"(WHI+woff1), "r"(hw[4]),"r"(hw[5]),"r"(hw[6]),"r"(hw[7]));
        asm volatile("st.shared.v4.b32 [%0], {%1,%2,%3,%4};"
                     :: "r"(WLO+woff0), "r"(lw[0]),"r"(lw[1]),"r"(lw[2]),"r"(lw[3]));
        asm volatile("st.shared.v4.b32 [%0], {%1,%2,%3,%4};"
                     :: "r"(WLO+woff1), "r"(lw[4]),"r"(lw[5]),"r"(lw[6]),"r"(lw[7]));
    }
    __syncthreads();

    // ---------- main loop ----------
    for (int c = 0; c < NC; c++) {
        const bool pf = (c + 1 < NC);
        // prefetch next chunk into regs (consumed after MMAs)
        float4 pA[4];
        float  pw[16];
        if (pf) {
#pragma unroll
            for (int i = 0; i < 4; i++)
                pA[i] = *(const float4*)(Ap[i] + (c + 1) * 32);
            const float* wB = Wp + (size_t)((c + 1) * 32 + kh * 16) * N;
#pragma unroll
            for (int j = 0; j < 16; j++) pw[j] = wB[(size_t)j * N];
        }

        // ---- MMAs on buffer c&1 ----
        const uint32_t base = sb + (uint32_t)(c & 1) * STG_BYTES;
        const uint32_t AHI = base, ALO = base + 8192, WHI = base + 16384, WLO = base + 24576;
#pragma unroll
        for (int ks = 0; ks < 2; ks++) {
            uint32_t Ah[2][4], Al[2][4];
#pragma unroll
            for (int mt = 0; mt < 2; mt++) {
                uint32_t off = swz64((uint32_t)((a_row + mt * 16) * 64 + kbyt + ks * 32));
                ldsm4(Ah[mt], AHI + off);
                ldsm4(Al[mt], ALO + off);
            }
            uint32_t Bh[8][2], Bl[8][2];
#pragma unroll
            for (int np = 0; np < 4; np++) {
                uint32_t off = swz64((uint32_t)((b_row + np * 16) * 64 + kbyt + ks * 32));
                uint32_t t4[4];
                ldsm4(t4, WHI + off);
                Bh[2*np][0] = t4[0]; Bh[2*np+1][0] = t4[1];
                Bh[2*np][1] = t4[2]; Bh[2*np+1][1] = t4[3];
                ldsm4(t4, WLO + off);
                Bl[2*np][0] = t4[0]; Bl[2*np+1][0] = t4[1];
                Bl[2*np][1] = t4[2]; Bl[2*np+1][1] = t4[3];
            }
#pragma unroll
            for (int mt = 0; mt < 2; mt++)
#pragma unroll
                for (int nt = 0; nt < 8; nt++) {
                    mma_bf16(acc[mt][nt], Ah[mt], Bh[nt]);
                    mma_bf16(acc[mt][nt], Ah[mt], Bl[nt]);
                    mma_bf16(acc[mt][nt], Al[mt], Bh[nt]);
                }
        }

        // ---- split + STS of next chunk into buffer (c+1)&1 ----
        if (pf) {
            const uint32_t nb = sb + (uint32_t)((c + 1) & 1) * STG_BYTES;
            const uint32_t nAHI = nb, nALO = nb + 8192, nWHI = nb + 16384, nWLO = nb + 24576;
#pragma unroll
            for (int i = 0; i < 4; i++) {
                float h0,h1,h2,h3,l0,l1,l2,l3;
                split2(pA[i].x,h0,l0); split2(pA[i].y,h1,l1);
                split2(pA[i].z,h2,l2); split2(pA[i].w,h3,l3);
                asm volatile("st.shared.v2.b32 [%0], {%1,%2};"
                             :: "r"(nAHI + aoff[i]), "r"(pack_bf16(h0,h1)), "r"(pack_bf16(h2,h3)));
                asm volatile("st.shared.v2.b32 [%0], {%1,%2};"
                             :: "r"(nALO + aoff[i]), "r"(pack_bf16(l0,l1)), "r"(pack_bf16(l2,l3)));
            }
            uint32_t hw[8], lw[8];
#pragma unroll
            for (int j = 0; j < 8; j++) {
                float h0,h1,l0,l1;
                split2(pw[2*j],h0,l0); split2(pw[2*j+1],h1,l1);
                hw[j] = pack_bf16(h0,h1); lw[j] = pack_bf16(l0,l1);
            }
            asm volatile("st.shared.v4.b32 [%0], {%1,%2,%3,%4};"
                         :: "r"(nWHI+woff0), "r"(hw[0]),"r"(hw[1]),"r"(hw[2]),"r"(hw[3]));
            asm volatile("st.shared.v4.b32 [%0], {%1,%2,%3,%4};"
                         :: "r"(nWHI+woff1), "r"(hw[4]),"r"(hw[5]),"r"(hw[6]),"r"(hw[7]));
            asm volatile("st.shared.v4.b32 [%0], {%1,%2,%3,%4};"
                         :: "r"(nWLO+woff0), "r"(lw[0]),"r"(lw[1]),"r"(lw[2]),"r"(lw[3]));
            asm volatile("st.shared.v4.b32 [%0], {%1,%2,%3,%4};"
                         :: "r"(nWLO+woff1), "r"(lw[4]),"r"(lw[5]),"r"(lw[6]),"r"(lw[7]));
        }
        __syncthreads();
    }

    // ---------- epilogue: regs -> gmem ----------
#pragma unroll
    for (int mt = 0; mt < 2; mt++) {
        const int gr0 = bm + wm * 32 + mt * 16 + (lane >> 2);
        const int gr1 = gr0 + 8;
#pragma unroll
        for (int nt = 0; nt < 8; nt++) {
            const int gc = bn + wn * 64 + nt * 8 + (lane & 3) * 2;
            float2 bz = *(const float2*)(bias + gc);
            float v0 = acc[mt][nt][0] + bz.x, v1 = acc[mt][nt][1] + bz.y;
            float v2 = acc[mt][nt][2] + bz.x, v3 = acc[mt][nt][3] + bz.y;
            if (RELU) {
                v0 = fmaxf(v0, 0.f); v1 = fmaxf(v1, 0.f);
                v2 = fmaxf(v2, 0.f); v3 = fmaxf(v3, 0.f);
            }
            if (gr0 < M) *(float2*)(C + (size_t)gr0 * N + gc) = make_float2(v0, v1);
            if (gr1 < M) *(float2*)(C + (size_t)gr1 * N + gc) = make_float2(v2, v3);
        }
    }
}

// ---------------- SIMT SGEMM for embed (tiny, needs row remap) ----------------
template<bool RELU, bool REMAP>
__global__ void __launch_bounds__(256) gemm_kernel(
    const float* __restrict__ A, const float* __restrict__ W,
    const float* __restrict__ bias, float* __restrict__ C,
    int K, int N)
{
    __shared__ __align__(16) float As[16][68];
    __shared__ __align__(16) float Bs[16][128];

    const int tid = threadIdx.x;
    const int tx  = tid & 15;
    const int ty  = tid >> 4;
    const int bm  = blockIdx.x * 64;
    const int bn  = blockIdx.y * 128;

    const int la_r = tid >> 2;
    const int la_k = (tid & 3) << 2;
    const int lb_r = tid >> 5;
    const int lb_c = (tid & 31) << 2;

    const float* Aptr  = A + (size_t)(bm + la_r) * K + la_k;
    const float* Wptr0 = W + (size_t)lb_r * N + bn + lb_c;
    const float* Wptr1 = W + (size_t)(lb_r + 8) * N + bn + lb_c;

    float acc[4][8];
#pragma unroll
    for (int i = 0; i < 4; i++)
#pragma unroll
        for (int j = 0; j < 8; j++) acc[i][j] = 0.f;

    for (int k0 = 0; k0 < K; k0 += 16) {
        float4 av  = *(const float4*)(Aptr + k0);
        float4 bw0 = *(const float4*)(Wptr0 + (size_t)k0 * N);
        float4 bw1 = *(const float4*)(Wptr1 + (size_t)k0 * N);
        As[la_k + 0][la_r] = av.x;
        As[la_k + 1][la_r] = av.y;
        As[la_k + 2][la_r] = av.z;
        As[la_k + 3][la_r] = av.w;
        *(float4*)&Bs[lb_r][lb_c]     = bw0;
        *(float4*)&Bs[lb_r + 8][lb_c] = bw1;
        __syncthreads();
#pragma unroll
        for (int kk = 0; kk < 16; kk++) {
            float4 a  = *(const float4*)&As[kk][ty * 4];
            float4 b0 = *(const float4*)&Bs[kk][tx * 8];
            float4 b1 = *(const float4*)&Bs[kk][tx * 8 + 4];
            float ar[4] = {a.x, a.y, a.z, a.w};
            float br[8] = {b0.x, b0.y, b0.z, b0.w, b1.x, b1.y, b1.z, b1.w};
#pragma unroll
            for (int i = 0; i < 4; i++)
#pragma unroll
                for (int j = 0; j < 8; j++)
                    acc[i][j] = fmaf(ar[i], br[j], acc[i][j]);
        }
        __syncthreads();
    }

    float4 bb0 = *(const float4*)(bias + bn + tx * 8);
    float4 bb1 = *(const float4*)(bias + bn + tx * 8 + 4);
    float bx[8] = {bb0.x, bb0.y, bb0.z, bb0.w, bb1.x, bb1.y, bb1.z, bb1.w};

#pragma unroll
    for (int i = 0; i < 4; i++) {
        int r = bm + ty * 4 + i;
        int orow = REMAP ? (r + r / NTT + 1) : r;
        float o[8];
#pragma unroll
        for (int j = 0; j < 8; j++) {
            float v = acc[i][j] + bx[j];
            if (RELU) v = fmaxf(v, 0.f);
            o[j] = v;
        }
        float4* cp = (float4*)(C + (size_t)orow * N + bn + tx * 8);
        cp[0] = make_float4(o[0], o[1], o[2], o[3]);
        cp[1] = make_float4(o[4], o[5], o[6], o[7]);
    }
}

// ---------------- CLS row ----------------
__global__ void cls_kernel(const float* __restrict__ coords,
                           const float* __restrict__ w_cls,
                           const float* __restrict__ b_cls,
                           float* __restrict__ X)
{
    int b = blockIdx.x, d = threadIdx.x;
    float c0 = coords[b * 3 + 0], c1 = coords[b * 3 + 1], c2 = coords[b * 3 + 2];
    X[(size_t)b * LLN * DD + d] =
        b_cls[d] + c0 * w_cls[d] + c1 * w_cls[DD + d] + c2 * w_cls[2 * DD + d];
}

// ---------------- fused attention ----------------
#define ATTN_SMEM_FLOATS (457*33 + 457*32 + 16*457 + 8*64)
#define ATTN_SMEM_BYTES  (ATTN_SMEM_FLOATS * 4)

__global__ void __launch_bounds__(256) attn_kernel(const float* __restrict__ QKV,
                                                   float* __restrict__ O)
{
    extern __shared__ float sm[];
    float* Ksm = sm;
    float* Vsm = Ksm + 457 * 33;
    float* Ssm = Vsm + 457 * 32;
    float* Qsm = Ssm + 16 * 457;

    const int bh = blockIdx.x;
    const int b = bh >> 3, h = bh & 7;
    const int tid = threadIdx.x, w = tid >> 5, lane = tid & 31;
    const float slope = (h < 4) ? 1.0f : 0.5f;
    const float scale = 0.17677669529663687f;

    const float* base = QKV + (size_t)b * (LLN * 3 * DD) + h * HDD;

    for (int idx = tid; idx < 457 * 32; idx += 256) {
        int j = idx >> 5, d = idx & 31;
        const float* kv = base + (size_t)j * (3 * DD);
        Ksm[j * 33 + d] = kv[DD + d];
        Vsm[idx]        = kv[2 * DD + d];
    }
    __syncthreads();

    for (int i0 = 2 * w; i0 < LLN; i0 += 16) {
        const bool two = (i0 + 1 < LLN);
        Qsm[w * 64 + lane] = base[(size_t)i0 * (3 * DD) + lane];
        if (two) Qsm[w * 64 + 32 + lane] = base[(size_t)(i0 + 1) * (3 * DD) + lane];
        __syncwarp();

        float s0[15], s1[15];
#pragma unroll
        for (int t = 0; t < 15; t++) { s0[t] = 0.f; s1[t] = 0.f; }
        for (int d = 0; d < 32; d++) {
            float q0 = Qsm[w * 64 + d];
            float q1 = Qsm[w * 64 + 32 + d];
#pragma unroll
            for (int t = 0; t < 15; t++) {
                int jj = lane + t * 32;
                if (jj < LLN) {
                    float kv = Ksm[jj * 33 + d];
                    s0[t] += q0 * kv;
                    s1[t] += q1 * kv;
                }
            }
        }
        float mx0 = -1e30f, mx1 = -1e30f;
#pragma unroll
        for (int t = 0; t < 15; t++) {
            int jj = lane + t * 32;
            if (jj < LLN) {
                s0[t] = s0[t] * scale - slope * fabsf((float)(i0 - jj));
                s1[t] = s1[t] * scale - slope * fabsf((float)(i0 + 1 - jj));
                mx0 = fmaxf(mx0, s0[t]);
                mx1 = fmaxf(mx1, s1[t]);
            }
        }
        mx0 = warp_max(mx0); mx1 = warp_max(mx1);
        float sum0 = 0.f, sum1 = 0.f;
#pragma unroll
        for (int t = 0; t < 15; t++) {
            int jj = lane + t * 32;
            if (jj < LLN) {
                float e0 = __expf(s0[t] - mx0);
                float e1 = __expf(s1[t] - mx1);
                Ssm[(2 * w) * 457 + jj]     = e0;
                Ssm[(2 * w + 1) * 457 + jj] = e1;
                sum0 += e0; sum1 += e1;
            }
        }
        sum0 = warp_sum(sum0); sum1 = warp_sum(sum1);
        float inv0 = 1.f / sum0, inv1 = 1.f / sum1;
        __syncwarp();

        float acc0 = 0.f, acc1 = 0.f;
        const float* p0 = Ssm + (2 * w) * 457;
        const float* p1 = Ssm + (2 * w + 1) * 457;
#pragma unroll 4
        for (int j = 0; j < LLN; j++) {
            float v = Vsm[j * 32 + lane];
            acc0 += p0[j] * v;
            acc1 += p1[j] * v;
        }
        float* op = O + ((size_t)b * LLN + i0) * DD + h * HDD + lane;
        op[0] = acc0 * inv0;
        if (two) op[DD] = acc1 * inv1;
        __syncwarp();
    }
}

// ---------------- fused residual add + LayerNorm ----------------
__global__ void __launch_bounds__(256) add_ln_kernel(float* __restrict__ X,
                                                     const float* __restrict__ T,
                                                     const float* __restrict__ g,
                                                     const float* __restrict__ bta)
{
    const int w = threadIdx.x >> 5, lane = threadIdx.x & 31;
    const size_t row = (size_t)blockIdx.x * 8 + w;
    float* xr = X + row * DD;
    const float* tr = T + row * DD;

    float4 x0 = ((const float4*)xr)[lane];
    float4 x1 = ((const float4*)xr)[lane + 32];
    float4 t0 = ((const float4*)tr)[lane];
    float4 t1 = ((const float4*)tr)[lane + 32];
    float v[8] = {x0.x + t0.x, x0.y + t0.y, x0.z + t0.z, x0.w + t0.w,
                  x1.x + t1.x, x1.y + t1.y, x1.z + t1.z, x1.w + t1.w};
    float s = 0.f;
#pragma unroll
    for (int i = 0; i < 8; i++) s += v[i];
    float m = warp_sum(s) * (1.f / 256.f);
    float vs = 0.f;
#pragma unroll
    for (int i = 0; i < 8; i++) { float d = v[i] - m; vs += d * d; }
    float rstd = rsqrtf(warp_sum(vs) * (1.f / 256.f) + 1e-5f);

    float4 g0 = ((const float4*)g)[lane];
    float4 g1 = ((const float4*)g)[lane + 32];
    float4 b0 = ((const float4*)bta)[lane];
    float4 b1 = ((const float4*)bta)[lane + 32];
    float4 o0 = make_float4((v[0]-m)*rstd*g0.x + b0.x, (v[1]-m)*rstd*g0.y + b0.y,
                            (v[2]-m)*rstd*g0.z + b0.z, (v[3]-m)*rstd*g0.w + b0.w);
    float4 o1 = make_float4((v[4]-m)*rstd*g1.x + b1.x, (v[5]-m)*rstd*g1.y + b1.y,
                            (v[6]-m)*rstd*g1.z + b1.z, (v[7]-m)*rstd*g1.w + b1.w);
    ((float4*)xr)[lane]      = o0;
    ((float4*)xr)[lane + 32] = o1;
}

// ---------------- head ----------------
__global__ void __launch_bounds__(256) head_kernel(
    const float* __restrict__ X,   const float* __restrict__ th1_w,
    const float* __restrict__ th1_b, const float* __restrict__ bn_g,
    const float* __restrict__ bn_b,  const float* __restrict__ th2_w,
    const float* __restrict__ th2_b, float* __restrict__ S)
{
    __shared__ float wsm[DD * 32];
    __shared__ float xs[8][DD];
    const int tid = threadIdx.x, w = tid >> 5, lane = tid & 31;

    for (int i = tid; i < DD * 32 / 4; i += 256)
        ((float4*)wsm)[i] = ((const float4*)th1_w)[i];

    const size_t row = (size_t)blockIdx.x * 8 + w;
    const float4* xr = (const float4*)(X + row * DD);
    float4* xd = (float4*)xs[w];
    xd[lane]      = xr[lane];
    xd[lane + 32] = xr[lane + 32];
    __syncthreads();

    float acc = th1_b[lane];
#pragma unroll 4
    for (int d = 0; d < DD; d++)
        acc += xs[w][d] * wsm[d * 32 + lane];

    float hv = acc * (bn_g[lane] * rsqrtf(1.f + 1e-5f)) + bn_b[lane];
    const float c = 0.7978845608028654f;
    float gl = 0.5f * hv * (1.f + tanhf(c * (hv + 0.044715f * hv * hv * hv)));
    float p = warp_sum(gl * th2_w[lane]);
    if (lane == 0) S[row] = p + th2_b[0];
}

// ---------------- pool ----------------
__global__ void __launch_bounds__(256) pool_kernel(const float* __restrict__ X,
                                                   const float* __restrict__ S,
                                                   float* __restrict__ out)
{
    __shared__ float wv[LLN];
    __shared__ float red[256];
    const int b = blockIdx.x, tid = threadIdx.x;
    const float* sp = S + (size_t)b * LLN;

    float mx = -1e30f;
    for (int l = tid; l < LLN; l += 256) mx = fmaxf(mx, sp[l]);
    red[tid] = mx; __syncthreads();
    for (int s = 128; s; s >>= 1) { if (tid < s) red[tid] = fmaxf(red[tid], red[tid + s]); __syncthreads(); }
    mx = red[0]; __syncthreads();

    float sum = 0.f;
    for (int l = tid; l < LLN; l += 256) { float e = __expf(sp[l] - mx); wv[l] = e; sum += e; }
    red[tid] = sum; __syncthreads();
    for (int s = 128; s; s >>= 1) { if (tid < s) red[tid] += red[tid + s]; __syncthreads(); }
    float inv = 1.f / red[0];
    __syncthreads();

    float acc = 0.f;
    const float* xp = X + (size_t)b * LLN * DD + tid;
#pragma unroll 4
    for (int l = 0; l < LLN; l++) acc += wv[l] * xp[(size_t)l * DD];
    out[(size_t)b * DD + tid] = acc * inv;
}

// ---------------- launch ----------------
extern "C" void kernel_launch(void* const* d_in, const int* in_sizes, int n_in,
                              void* d_out, int out_size)
{
    const float* gene_exp = (const float*)d_in[0];
    const float* coords   = (const float*)d_in[1];
    const float* w_in     = (const float*)d_in[2];
    const float* b_in     = (const float*)d_in[3];
    const float* w_cls    = (const float*)d_in[4];
    const float* b_cls    = (const float*)d_in[5];
    const float* qkv_w    = (const float*)d_in[6];
    const float* qkv_b    = (const float*)d_in[7];
    const float* ln1_g    = (const float*)d_in[8];
    const float* ln1_b    = (const float*)d_in[9];
    const float* ffn_w1   = (const float*)d_in[10];
    const float* ffn_b1   = (const float*)d_in[11];
    const float* ffn_w2   = (const float*)d_in[12];
    const float* ffn_b2   = (const float*)d_in[13];
    const float* ln2_g    = (const float*)d_in[14];
    const float* ln2_b    = (const float*)d_in[15];
    const float* th1_w    = (const float*)d_in[16];
    const float* th1_b    = (const float*)d_in[17];
    const float* bn_g     = (const float*)d_in[18];
    const float* bn_b     = (const float*)d_in[19];
    const float* th2_w    = (const float*)d_in[20];
    const float* th2_b    = (const float*)d_in[21];
    float* out = (float*)d_out;

    float *X, *T, *BIG, *S;
    cudaGetSymbolAddress((void**)&X,   g_X);
    cudaGetSymbolAddress((void**)&T,   g_T);
    cudaGetSymbolAddress((void**)&BIG, g_BIG);
    cudaGetSymbolAddress((void**)&S,   g_S);

    cudaFuncSetAttribute(attn_kernel, cudaFuncAttributeMaxDynamicSharedMemorySize,
                         ATTN_SMEM_BYTES);
    cudaFuncSetAttribute(gemmM_kernel<false>, cudaFuncAttributeMaxDynamicSharedMemorySize,
                         GEMM_SMEM);
    cudaFuncSetAttribute(gemmM_kernel<true>, cudaFuncAttributeMaxDynamicSharedMemorySize,
                         GEMM_SMEM);

    const int GM = (MROWS + 127) / 128;   // 229

    // embed: CLS row + token GEMM (SIMT, remapped rows)
    cls_kernel<<<BB, 256>>>(coords, w_cls, b_cls, X);
    gemm_kernel<false, true><<<dim3(NTT * BB / 64, DD / 128), 256>>>(
        gene_exp, w_in, b_in, X, TOKK, DD);

    for (int l = 0; l < 4; l++) {
        gemmM_kernel<false><<<dim3(GM, (3 * DD) / 128), 256, GEMM_SMEM>>>(
            X, qkv_w + (size_t)l * DD * 3 * DD, qkv_b + (size_t)l * 3 * DD, BIG,
            MROWS, DD, 3 * DD);
        attn_kernel<<<BB * HH, 256, ATTN_SMEM_BYTES>>>(BIG, T);
        add_ln_kernel<<<MROWS / 8, 256>>>(X, T, ln1_g + l * DD, ln1_b + l * DD);
        gemmM_kernel<true><<<dim3(GM, FFF / 128), 256, GEMM_SMEM>>>(
            X, ffn_w1 + (size_t)l * DD * FFF, ffn_b1 + (size_t)l * FFF, BIG,
            MROWS, DD, FFF);
        gemmM_kernel<false><<<dim3(GM, DD / 128), 256, GEMM_SMEM>>>(
            BIG, ffn_w2 + (size_t)l * FFF * DD, ffn_b2 + (size_t)l * DD, T,
            MROWS, FFF, DD);
        add_ln_kernel<<<MROWS / 8, 256>>>(X, T, ln2_g + l * DD, ln2_b + l * DD);
    }

    head_kernel<<<MROWS / 8, 256>>>(X, th1_w, th1_b, bn_g, bn_b, th2_w, th2_b, S);
    pool_kernel<<<BB, 256>>>(X, S, out);
}

// round 14
// speedup vs baseline: 1.6616x; 1.0454x over previous
#include <cuda_runtime.h>
#include <cuda_bf16.h>
#include <math.h>
#include <stdint.h>

// ---------------- problem constants ----------------
#define BB   64
#define NTT  456
#define TOKK 64
#define DD   256
#define HH   8
#define HDD  32
#define FFF  1024
#define LLN  457            // L = NT + 1
#define MROWS (BB * LLN)    // 29248
#define WPL  720896         // weight elems per layer: 256*768 + 256*1024 + 1024*256

// ---------------- device scratch (static, no allocs) ----------------
__device__ float g_X  [MROWS * DD];
__device__ float g_T  [MROWS * DD];
__device__ float g_QKV[MROWS * 3 * DD];
__device__ __nv_bfloat16 g_Xh[MROWS * DD],  g_Xl[MROWS * DD];
__device__ __nv_bfloat16 g_Hh[MROWS * FFF], g_Hl[MROWS * FFF];
__device__ __nv_bfloat16 g_Wh[4 * WPL],     g_Wl[4 * WPL];
__device__ float g_S  [MROWS];

// ---------------- helpers ----------------
__device__ __forceinline__ float warp_sum(float v) {
#pragma unroll
    for (int o = 16; o; o >>= 1) v += __shfl_xor_sync(0xffffffffu, v, o);
    return v;
}
__device__ __forceinline__ float warp_max(float v) {
#pragma unroll
    for (int o = 16; o; o >>= 1) v = fmaxf(v, __shfl_xor_sync(0xffffffffu, v, o));
    return v;
}
__device__ __forceinline__ uint32_t smem_u32(const void* p) {
    uint32_t a;
    asm("{ .reg .u64 t; cvta.to.shared.u64 t, %1; cvt.u32.u64 %0, t; }"
        : "=r"(a) : "l"(p));
    return a;
}
__device__ __forceinline__ uint32_t pack_bf16(float lo, float hi) {
    uint32_t r;   // lo -> low half, hi -> high half
    asm("cvt.rn.bf16x2.f32 %0, %1, %2;" : "=r"(r) : "f"(hi), "f"(lo));
    return r;
}
__device__ __forceinline__ void split2(float x, float& hi, float& lo) {
    __nv_bfloat16 h = __float2bfloat16_rn(x);
    hi = __bfloat162float(h);
    lo = x - hi;
}
// SW64 swizzle for 64-byte rows (involution; conflict-free ldmatrix/STS)
__device__ __forceinline__ uint32_t swz64(uint32_t x) {
    return x ^ ((x >> 3) & 0x30);
}
__device__ __forceinline__ void ldsm4(uint32_t* r, uint32_t addr) {
    asm volatile("ldmatrix.sync.aligned.m8n8.x4.shared.b16 {%0,%1,%2,%3}, [%4];"
                 : "=r"(r[0]), "=r"(r[1]), "=r"(r[2]), "=r"(r[3]) : "r"(addr));
}
__device__ __forceinline__ void mma_bf16(float* d, const uint32_t* a, const uint32_t* b) {
    asm volatile(
        "mma.sync.aligned.m16n8k16.row.col.f32.bf16.bf16.f32 "
        "{%0,%1,%2,%3}, {%4,%5,%6,%7}, {%8,%9}, {%0,%1,%2,%3};"
        : "+f"(d[0]), "+f"(d[1]), "+f"(d[2]), "+f"(d[3])
        : "r"(a[0]), "r"(a[1]), "r"(a[2]), "r"(a[3]), "r"(b[0]), "r"(b[1]));
}
__device__ __forceinline__ void cp16(uint32_t dst, const void* src) {
    asm volatile("cp.async.cg.shared.global [%0], [%1], 16;" :: "r"(dst), "l"(src));
}
#define CP_COMMIT() asm volatile("cp.async.commit_group;" ::: "memory")
#define CP_WAIT2()  asm volatile("cp.async.wait_group 2;" ::: "memory")

// =====================================================================
// weight pre-split: W[K][N] fp32 -> tiled/swizzled bf16 hi/lo
// tile = 128 n x 32 k, elem offset within tile = swz64(n_local*64+k_local*2)/2
// tile index = n_blk*(K/32) + c  (matches GEMM blockIdx.x = n_blk)
// =====================================================================
__global__ void split_w_kernel(const float* __restrict__ W,
                               __nv_bfloat16* __restrict__ Wh,
                               __nv_bfloat16* __restrict__ Wl,
                               int K, int N)
{
    int idx = blockIdx.x * 256 + threadIdx.x;
    if (idx >= K * N) return;
    int tile = idx >> 12, w2 = idx & 4095;
    int kc = K >> 5;
    int n_blk = tile / kc, c = tile % kc;
    uint32_t orig = swz64((uint32_t)w2 * 2);
    int n_local = orig >> 6, k_local = (orig & 63) >> 1;
    int k = c * 32 + k_local, n = n_blk * 128 + n_local;
    float v = W[(size_t)k * N + n];
    float hi, lo; split2(v, hi, lo);
    Wh[idx] = __float2bfloat16_rn(hi);
    Wl[idx] = __float2bfloat16_rn(lo);
}

// =====================================================================
// Pure-bf16 tensor-core split GEMM: C = A @ W + bias
// A pre-split bf16 hi/lo [M][K]; W pre-split+tiled bf16 hi/lo.
// BM=128, BN=128, BK=32, 256 threads, 4-stage cp.async pipeline.
// 3-term: Ahi*Whi + Ahi*Wlo + Alo*Whi, fp32 accum.
// grid = (N/128, ceil(M/128))  -> n fastest for A reuse in L2.
// =====================================================================
#define GM_STAGES 4
#define STG 32768
#define GEMM_SMEM (GM_STAGES * STG)   // 131072

template<bool RELU, bool SPLIT_OUT>
__global__ void __launch_bounds__(256, 1)
gemmA_kernel(const __nv_bfloat16* __restrict__ Ah, const __nv_bfloat16* __restrict__ Al,
             const __nv_bfloat16* __restrict__ Wh, const __nv_bfloat16* __restrict__ Wl,
             const float* __restrict__ bias,
             float* __restrict__ Cf,
             __nv_bfloat16* __restrict__ Ch, __nv_bfloat16* __restrict__ Cl,
             int M, int K, int N)
{
    extern __shared__ char smc[];
    const uint32_t sb = smem_u32(smc);
    const int tid = threadIdx.x, lane = tid & 31, w = tid >> 5;
    const int wm = w & 3, wn = w >> 2;
    const int bn = blockIdx.x * 128, bm = blockIdx.y * 128;
    const int NC = K >> 5;

    // per-thread cp.async geometry (2 quads each for A-hi/lo, W-hi/lo)
    int arow[2]; uint32_t adst[2]; const __nv_bfloat16 *pah[2], *pal[2];
#pragma unroll
    for (int i = 0; i < 2; i++) {
        int q = tid + i * 256;
        int row = q >> 2, seg = q & 3;
        int gr = bm + row; if (gr >= M) gr = M - 1;
        arow[i] = row;
        pah[i] = Ah + (size_t)gr * K + seg * 8;
        pal[i] = Al + (size_t)gr * K + seg * 8;
        adst[i] = swz64((uint32_t)(row * 64 + seg * 16));
    }
    const size_t wtb = (size_t)blockIdx.x * NC * 4096;   // tile base (elements)

    auto load_stage = [&](int c, int s) {
        const uint32_t base = sb + (uint32_t)s * STG;
#pragma unroll
        for (int i = 0; i < 2; i++) {
            int q = tid + i * 256;
            cp16(base +         adst[i], pah[i] + c * 32);
            cp16(base +  8192 + adst[i], pal[i] + c * 32);
            size_t wo = wtb + (size_t)c * 4096 + q * 8;
            cp16(base + 16384 + q * 16, Wh + wo);
            cp16(base + 24576 + q * 16, Wl + wo);
        }
    };

    // prologue: stages 0..2
#pragma unroll
    for (int s = 0; s < GM_STAGES - 1; s++) { load_stage(s, s); CP_COMMIT(); }

    // ldmatrix lane geometry
    const int g = lane >> 3, rr = lane & 7;
    const int a_row = wm * 32 + rr + (g & 1) * 8;
    const int b_row = wn * 64 + rr + (g & 1) * 8;
    const int kbyt  = (g >> 1) * 16;

    float acc[2][8][4];
#pragma unroll
    for (int mt = 0; mt < 2; mt++)
#pragma unroll
        for (int nt = 0; nt < 8; nt++)
#pragma unroll
            for (int q = 0; q < 4; q++) acc[mt][nt][q] = 0.f;

    for (int c = 0; c < NC; c++) {
        CP_WAIT2();
        __syncthreads();
        const uint32_t base = sb + (uint32_t)(c & (GM_STAGES - 1)) * STG;
        const uint32_t AHI = base, ALO = base + 8192, WHI = base + 16384, WLO = base + 24576;
#pragma unroll
        for (int ks = 0; ks < 2; ks++) {
            uint32_t Ahf[2][4], Alf[2][4];
#pragma unroll
            for (int mt = 0; mt < 2; mt++) {
                uint32_t off = swz64((uint32_t)((a_row + mt * 16) * 64 + kbyt + ks * 32));
                ldsm4(Ahf[mt], AHI + off);
                ldsm4(Alf[mt], ALO + off);
            }
            uint32_t Bh[8][2], Bl[8][2];
#pragma unroll
            for (int np = 0; np < 4; np++) {
                uint32_t off = swz64((uint32_t)((b_row + np * 16) * 64 + kbyt + ks * 32));
                uint32_t t4[4];
                ldsm4(t4, WHI + off);
                Bh[2*np][0] = t4[0]; Bh[2*np+1][0] = t4[1];
                Bh[2*np][1] = t4[2]; Bh[2*np+1][1] = t4[3];
                ldsm4(t4, WLO + off);
                Bl[2*np][0] = t4[0]; Bl[2*np+1][0] = t4[1];
                Bl[2*np][1] = t4[2]; Bl[2*np+1][1] = t4[3];
            }
#pragma unroll
            for (int mt = 0; mt < 2; mt++)
#pragma unroll
                for (int nt = 0; nt < 8; nt++) {
                    mma_bf16(acc[mt][nt], Ahf[mt], Bh[nt]);
                    mma_bf16(acc[mt][nt], Ahf[mt], Bl[nt]);
                    mma_bf16(acc[mt][nt], Alf[mt], Bh[nt]);
                }
        }
        if (c + GM_STAGES - 1 < NC)
            load_stage(c + GM_STAGES - 1, (c + GM_STAGES - 1) & (GM_STAGES - 1));
        CP_COMMIT();   // exactly one group per iter (may be empty) keeps wait_group math exact
    }

    // ---------- epilogue ----------
#pragma unroll
    for (int mt = 0; mt < 2; mt++) {
        const int gr0 = bm + wm * 32 + mt * 16 + (lane >> 2);
        const int gr1 = gr0 + 8;
#pragma unroll
        for (int nt = 0; nt < 8; nt++) {
            const int gc = bn + wn * 64 + nt * 8 + (lane & 3) * 2;
            float2 bz = *(const float2*)(bias + gc);
            float v0 = acc[mt][nt][0] + bz.x, v1 = acc[mt][nt][1] + bz.y;
            float v2 = acc[mt][nt][2] + bz.x, v3 = acc[mt][nt][3] + bz.y;
            if (RELU) {
                v0 = fmaxf(v0, 0.f); v1 = fmaxf(v1, 0.f);
                v2 = fmaxf(v2, 0.f); v3 = fmaxf(v3, 0.f);
            }
            if (SPLIT_OUT) {
                float h0,h1,l0,l1;
                if (gr0 < M) {
                    split2(v0,h0,l0); split2(v1,h1,l1);
                    *(uint32_t*)(Ch + (size_t)gr0 * N + gc) = pack_bf16(h0, h1);
                    *(uint32_t*)(Cl + (size_t)gr0 * N + gc) = pack_bf16(l0, l1);
                }
                if (gr1 < M) {
                    split2(v2,h0,l0); split2(v3,h1,l1);
                    *(uint32_t*)(Ch + (size_t)gr1 * N + gc) = pack_bf16(h0, h1);
                    *(uint32_t*)(Cl + (size_t)gr1 * N + gc) = pack_bf16(l0, l1);
                }
            } else {
                if (gr0 < M) *(float2*)(Cf + (size_t)gr0 * N + gc) = make_float2(v0, v1);
                if (gr1 < M) *(float2*)(Cf + (size_t)gr1 * N + gc) = make_float2(v2, v3);
            }
        }
    }
}

// ---------------- SIMT SGEMM for embed (K=64, row remap, emits X + hi/lo) ----------------
__global__ void __launch_bounds__(256) gemm_embed_kernel(
    const float* __restrict__ A, const float* __restrict__ W,
    const float* __restrict__ bias, float* __restrict__ C,
    __nv_bfloat16* __restrict__ Xh, __nv_bfloat16* __restrict__ Xl,
    int K, int N)
{
    __shared__ __align__(16) float As[16][68];
    __shared__ __align__(16) float Bs[16][128];

    const int tid = threadIdx.x;
    const int tx  = tid & 15;
    const int ty  = tid >> 4;
    const int bm  = blockIdx.x * 64;
    const int bn  = blockIdx.y * 128;

    const int la_r = tid >> 2;
    const int la_k = (tid & 3) << 2;
    const int lb_r = tid >> 5;
    const int lb_c = (tid & 31) << 2;

    const float* Aptr  = A + (size_t)(bm + la_r) * K + la_k;
    const float* Wptr0 = W + (size_t)lb_r * N + bn + lb_c;
    const float* Wptr1 = W + (size_t)(lb_r + 8) * N + bn + lb_c;

    float acc[4][8];
#pragma unroll
    for (int i = 0; i < 4; i++)
#pragma unroll
        for (int j = 0; j < 8; j++) acc[i][j] = 0.f;

    for (int k0 = 0; k0 < K; k0 += 16) {
        float4 av  = *(const float4*)(Aptr + k0);
        float4 bw0 = *(const float4*)(Wptr0 + (size_t)k0 * N);
        float4 bw1 = *(const float4*)(Wptr1 + (size_t)k0 * N);
        As[la_k + 0][la_r] = av.x;
        As[la_k + 1][la_r] = av.y;
        As[la_k + 2][la_r] = av.z;
        As[la_k + 3][la_r] = av.w;
        *(float4*)&Bs[lb_r][lb_c]     = bw0;
        *(float4*)&Bs[lb_r + 8][lb_c] = bw1;
        __syncthreads();
#pragma unroll
        for (int kk = 0; kk < 16; kk++) {
            float4 a  = *(const float4*)&As[kk][ty * 4];
            float4 b0 = *(const float4*)&Bs[kk][tx * 8];
            float4 b1 = *(const float4*)&Bs[kk][tx * 8 + 4];
            float ar[4] = {a.x, a.y, a.z, a.w};
            float br[8] = {b0.x, b0.y, b0.z, b0.w, b1.x, b1.y, b1.z, b1.w};
#pragma unroll
            for (int i = 0; i < 4; i++)
#pragma unroll
                for (int j = 0; j < 8; j++)
                    acc[i][j] = fmaf(ar[i], br[j], acc[i][j]);
        }
        __syncthreads();
    }

    float4 bb0 = *(const float4*)(bias + bn + tx * 8);
    float4 bb1 = *(const float4*)(bias + bn + tx * 8 + 4);
    float bx[8] = {bb0.x, bb0.y, bb0.z, bb0.w, bb1.x, bb1.y, bb1.z, bb1.w};

#pragma unroll
    for (int i = 0; i < 4; i++) {
        int r = bm + ty * 4 + i;
        int orow = r + r / NTT + 1;   // (b*NT+t) -> b*L + 1 + t
        float o[8], h[8], lo[8];
#pragma unroll
        for (int j = 0; j < 8; j++) {
            o[j] = acc[i][j] + bx[j];
            split2(o[j], h[j], lo[j]);
        }
        size_t off = (size_t)orow * N + bn + tx * 8;
        float4* cp = (float4*)(C + off);
        cp[0] = make_float4(o[0], o[1], o[2], o[3]);
        cp[1] = make_float4(o[4], o[5], o[6], o[7]);
        uint32_t* ph = (uint32_t*)(Xh + off);
        uint32_t* pl = (uint32_t*)(Xl + off);
        ph[0] = pack_bf16(h[0],h[1]);  ph[1] = pack_bf16(h[2],h[3]);
        ph[2] = pack_bf16(h[4],h[5]);  ph[3] = pack_bf16(h[6],h[7]);
        pl[0] = pack_bf16(lo[0],lo[1]); pl[1] = pack_bf16(lo[2],lo[3]);
        pl[2] = pack_bf16(lo[4],lo[5]); pl[3] = pack_bf16(lo[6],lo[7]);
    }
}

// ---------------- CLS row ----------------
__global__ void cls_kernel(const float* __restrict__ coords,
                           const float* __restrict__ w_cls,
                           const float* __restrict__ b_cls,
                           float* __restrict__ X,
                           __nv_bfloat16* __restrict__ Xh,
                           __nv_bfloat16* __restrict__ Xl)
{
    int b = blockIdx.x, d = threadIdx.x;
    float c0 = coords[b * 3 + 0], c1 = coords[b * 3 + 1], c2 = coords[b * 3 + 2];
    float v = b_cls[d] + c0 * w_cls[d] + c1 * w_cls[DD + d] + c2 * w_cls[2 * DD + d];
    size_t off = (size_t)b * LLN * DD + d;
    X[off] = v;
    float hi, lo; split2(v, hi, lo);
    Xh[off] = __float2bfloat16_rn(hi);
    Xl[off] = __float2bfloat16_rn(lo);
}

// ---------------- fused attention ----------------
#define ATTN_SMEM_FLOATS (457*33 + 457*32 + 16*457 + 8*64)
#define ATTN_SMEM_BYTES  (ATTN_SMEM_FLOATS * 4)

__global__ void __launch_bounds__(256) attn_kernel(const float* __restrict__ QKV,
                                                   float* __restrict__ O)
{
    extern __shared__ float sm[];
    float* Ksm = sm;
    float* Vsm = Ksm + 457 * 33;
    float* Ssm = Vsm + 457 * 32;
    float* Qsm = Ssm + 16 * 457;

    const int bh = blockIdx.x;
    const int b = bh >> 3, h = bh & 7;
    const int tid = threadIdx.x, w = tid >> 5, lane = tid & 31;
    const float slope = (h < 4) ? 1.0f : 0.5f;
    const float scale = 0.17677669529663687f;

    const float* base = QKV + (size_t)b * (LLN * 3 * DD) + h * HDD;

    for (int idx = tid; idx < 457 * 32; idx += 256) {
        int j = idx >> 5, d = idx & 31;
        const float* kv = base + (size_t)j * (3 * DD);
        Ksm[j * 33 + d] = kv[DD + d];
        Vsm[idx]        = kv[2 * DD + d];
    }
    __syncthreads();

    for (int i0 = 2 * w; i0 < LLN; i0 += 16) {
        const bool two = (i0 + 1 < LLN);
        Qsm[w * 64 + lane] = base[(size_t)i0 * (3 * DD) + lane];
        if (two) Qsm[w * 64 + 32 + lane] = base[(size_t)(i0 + 1) * (3 * DD) + lane];
        __syncwarp();

        float s0[15], s1[15];
#pragma unroll
        for (int t = 0; t < 15; t++) { s0[t] = 0.f; s1[t] = 0.f; }
        for (int d = 0; d < 32; d++) {
            float q0 = Qsm[w * 64 + d];
            float q1 = Qsm[w * 64 + 32 + d];
#pragma unroll
            for (int t = 0; t < 15; t++) {
                int jj = lane + t * 32;
                if (jj < LLN) {
                    float kv = Ksm[jj * 33 + d];
                    s0[t] += q0 * kv;
                    s1[t] += q1 * kv;
                }
            }
        }
        float mx0 = -1e30f, mx1 = -1e30f;
#pragma unroll
        for (int t = 0; t < 15; t++) {
            int jj = lane + t * 32;
            if (jj < LLN) {
                s0[t] = s0[t] * scale - slope * fabsf((float)(i0 - jj));
                s1[t] = s1[t] * scale - slope * fabsf((float)(i0 + 1 - jj));
                mx0 = fmaxf(mx0, s0[t]);
                mx1 = fmaxf(mx1, s1[t]);
            }
        }
        mx0 = warp_max(mx0); mx1 = warp_max(mx1);
        float sum0 = 0.f, sum1 = 0.f;
#pragma unroll
        for (int t = 0; t < 15; t++) {
            int jj = lane + t * 32;
            if (jj < LLN) {
                float e0 = __expf(s0[t] - mx0);
                float e1 = __expf(s1[t] - mx1);
                Ssm[(2 * w) * 457 + jj]     = e0;
                Ssm[(2 * w + 1) * 457 + jj] = e1;
                sum0 += e0; sum1 += e1;
            }
        }
        sum0 = warp_sum(sum0); sum1 = warp_sum(sum1);
        float inv0 = 1.f / sum0, inv1 = 1.f / sum1;
        __syncwarp();

        float acc0 = 0.f, acc1 = 0.f;
        const float* p0 = Ssm + (2 * w) * 457;
        const float* p1 = Ssm + (2 * w + 1) * 457;
#pragma unroll 4
        for (int j = 0; j < LLN; j++) {
            float v = Vsm[j * 32 + lane];
            acc0 += p0[j] * v;
            acc1 += p1[j] * v;
        }
        float* op = O + ((size_t)b * LLN + i0) * DD + h * HDD + lane;
        op[0] = acc0 * inv0;
        if (two) op[DD] = acc1 * inv1;
        __syncwarp();
    }
}

// ---------------- fused residual add + LayerNorm (emits fp32 X + bf16 hi/lo) ----------------
__global__ void __launch_bounds__(256) add_ln_kernel(float* __restrict__ X,
                                                     const float* __restrict__ T,
                                                     const float* __restrict__ g,
                                                     const float* __restrict__ bta,
                                                     __nv_bfloat16* __restrict__ Xh,
                                                     __nv_bfloat16* __restrict__ Xl)
{
    const int w = threadIdx.x >> 5, lane = threadIdx.x & 31;
    const size_t row = (size_t)blockIdx.x * 8 + w;
    float* xr = X + row * DD;
    const float* tr = T + row * DD;

    float4 x0 = ((const float4*)xr)[lane];
    float4 x1 = ((const float4*)xr)[lane + 32];
    float4 t0 = ((const float4*)tr)[lane];
    float4 t1 = ((const float4*)tr)[lane + 32];
    float v[8] = {x0.x + t0.x, x0.y + t0.y, x0.z + t0.z, x0.w + t0.w,
                  x1.x + t1.x, x1.y + t1.y, x1.z + t1.z, x1.w + t1.w};
    float s = 0.f;
#pragma unroll
    for (int i = 0; i < 8; i++) s += v[i];
    float m = warp_sum(s) * (1.f / 256.f);
    float vs = 0.f;
#pragma unroll
    for (int i = 0; i < 8; i++) { float d = v[i] - m; vs += d * d; }
    float rstd = rsqrtf(warp_sum(vs) * (1.f / 256.f) + 1e-5f);

    float4 g0 = ((const float4*)g)[lane];
    float4 g1 = ((const float4*)g)[lane + 32];
    float4 b0 = ((const float4*)bta)[lane];
    float4 b1 = ((const float4*)bta)[lane + 32];
    float o[8];
    o[0]=(v[0]-m)*rstd*g0.x + b0.x; o[1]=(v[1]-m)*rstd*g0.y + b0.y;
    o[2]=(v[2]-m)*rstd*g0.z + b0.z; o[3]=(v[3]-m)*rstd*g0.w + b0.w;
    o[4]=(v[4]-m)*rstd*g1.x + b1.x; o[5]=(v[5]-m)*rstd*g1.y + b1.y;
    o[6]=(v[6]-m)*rstd*g1.z + b1.z; o[7]=(v[7]-m)*rstd*g1.w + b1.w;
    ((float4*)xr)[lane]      = make_float4(o[0],o[1],o[2],o[3]);
    ((float4*)xr)[lane + 32] = make_float4(o[4],o[5],o[6],o[7]);

    float h[8], lo[8];
#pragma unroll
    for (int i = 0; i < 8; i++) split2(o[i], h[i], lo[i]);
    uint32_t* ph = (uint32_t*)(Xh + row * DD);
    uint32_t* pl = (uint32_t*)(Xl + row * DD);
    ph[lane*2]      = pack_bf16(h[0],h[1]);  ph[lane*2+1]      = pack_bf16(h[2],h[3]);
    ph[64+lane*2]   = pack_bf16(h[4],h[5]);  ph[64+lane*2+1]   = pack_bf16(h[6],h[7]);
    pl[lane*2]      = pack_bf16(lo[0],lo[1]); pl[lane*2+1]     = pack_bf16(lo[2],lo[3]);
    pl[64+lane*2]   = pack_bf16(lo[4],lo[5]); pl[64+lane*2+1]  = pack_bf16(lo[6],lo[7]);
}

// ---------------- head ----------------
__global__ void __launch_bounds__(256) head_kernel(
    const float* __restrict__ X,   const float* __restrict__ th1_w,
    const float* __restrict__ th1_b, const float* __restrict__ bn_g,
    const float* __restrict__ bn_b,  const float* __restrict__ th2_w,
    const float* __restrict__ th2_b, float* __restrict__ S)
{
    __shared__ float wsm[DD * 32];
    __shared__ float xs[8][DD];
    const int tid = threadIdx.x, w = tid >> 5, lane = tid & 31;

    for (int i = tid; i < DD * 32 / 4; i += 256)
        ((float4*)wsm)[i] = ((const float4*)th1_w)[i];

    const size_t row = (size_t)blockIdx.x * 8 + w;
    const float4* xr = (const float4*)(X + row * DD);
    float4* xd = (float4*)xs[w];
    xd[lane]      = xr[lane];
    xd[lane + 32] = xr[lane + 32];
    __syncthreads();

    float acc = th1_b[lane];
#pragma unroll 4
    for (int d = 0; d < DD; d++)
        acc += xs[w][d] * wsm[d * 32 + lane];

    float hv = acc * (bn_g[lane] * rsqrtf(1.f + 1e-5f)) + bn_b[lane];
    const float c = 0.7978845608028654f;
    float gl = 0.5f * hv * (1.f + tanhf(c * (hv + 0.044715f * hv * hv * hv)));
    float p = warp_sum(gl * th2_w[lane]);
    if (lane == 0) S[row] = p + th2_b[0];
}

// ---------------- pool ----------------
__global__ void __launch_bounds__(256) pool_kernel(const float* __restrict__ X,
                                                   const float* __restrict__ S,
                                                   float* __restrict__ out)
{
    __shared__ float wv[LLN];
    __shared__ float red[256];
    const int b = blockIdx.x, tid = threadIdx.x;
    const float* sp = S + (size_t)b * LLN;

    float mx = -1e30f;
    for (int l = tid; l < LLN; l += 256) mx = fmaxf(mx, sp[l]);
    red[tid] = mx; __syncthreads();
    for (int s = 128; s; s >>= 1) { if (tid < s) red[tid] = fmaxf(red[tid], red[tid + s]); __syncthreads(); }
    mx = red[0]; __syncthreads();

    float sum = 0.f;
    for (int l = tid; l < LLN; l += 256) { float e = __expf(sp[l] - mx); wv[l] = e; sum += e; }
    red[tid] = sum; __syncthreads();
    for (int s = 128; s; s >>= 1) { if (tid < s) red[tid] += red[tid + s]; __syncthreads(); }
    float inv = 1.f / red[0];
    __syncthreads();

    float acc = 0.f;
    const float* xp = X + (size_t)b * LLN * DD + tid;
#pragma unroll 4
    for (int l = 0; l < LLN; l++) acc += wv[l] * xp[(size_t)l * DD];
    out[(size_t)b * DD + tid] = acc * inv;
}

// ---------------- launch ----------------
extern "C" void kernel_launch(void* const* d_in, const int* in_sizes, int n_in,
                              void* d_out, int out_size)
{
    const float* gene_exp = (const float*)d_in[0];
    const float* coords   = (const float*)d_in[1];
    const float* w_in     = (const float*)d_in[2];
    const float* b_in     = (const float*)d_in[3];
    const float* w_cls    = (const float*)d_in[4];
    const float* b_cls    = (const float*)d_in[5];
    const float* qkv_w    = (const float*)d_in[6];
    const float* qkv_b    = (const float*)d_in[7];
    const float* ln1_g    = (const float*)d_in[8];
    const float* ln1_b    = (const float*)d_in[9];
    const float* ffn_w1   = (const float*)d_in[10];
    const float* ffn_b1   = (const float*)d_in[11];
    const float* ffn_w2   = (const float*)d_in[12];
    const float* ffn_b2   = (const float*)d_in[13];
    const float* ln2_g    = (const float*)d_in[14];
    const float* ln2_b    = (const float*)d_in[15];
    const float* th1_w    = (const float*)d_in[16];
    const float* th1_b    = (const float*)d_in[17];
    const float* bn_g     = (const float*)d_in[18];
    const float* bn_b     = (const float*)d_in[19];
    const float* th2_w    = (const float*)d_in[20];
    const float* th2_b    = (const float*)d_in[21];
    float* out = (float*)d_out;

    float *X, *T, *QKV, *S;
    __nv_bfloat16 *Xh, *Xl, *Hh, *Hl, *Wh, *Wl;
    cudaGetSymbolAddress((void**)&X,   g_X);
    cudaGetSymbolAddress((void**)&T,   g_T);
    cudaGetSymbolAddress((void**)&QKV, g_QKV);
    cudaGetSymbolAddress((void**)&S,   g_S);
    cudaGetSymbolAddress((void**)&Xh,  g_Xh);
    cudaGetSymbolAddress((void**)&Xl,  g_Xl);
    cudaGetSymbolAddress((void**)&Hh,  g_Hh);
    cudaGetSymbolAddress((void**)&Hl,  g_Hl);
    cudaGetSymbolAddress((void**)&Wh,  g_Wh);
    cudaGetSymbolAddress((void**)&Wl,  g_Wl);

    cudaFuncSetAttribute(attn_kernel, cudaFuncAttributeMaxDynamicSharedMemorySize,
                         ATTN_SMEM_BYTES);
    cudaFuncSetAttribute(gemmA_kernel<false,false>,
                         cudaFuncAttributeMaxDynamicSharedMemorySize, GEMM_SMEM);
    cudaFuncSetAttribute(gemmA_kernel<true,true>,
                         cudaFuncAttributeMaxDynamicSharedMemorySize, GEMM_SMEM);

    const int GM = (MROWS + 127) / 128;   // 229

    // ---- weight pre-split (pre-tiled, pre-swizzled) ----
    for (int l = 0; l < 4; l++) {
        split_w_kernel<<<(256*768 + 255)/256, 256>>>(
            qkv_w + (size_t)l * 196608, Wh + (size_t)l * WPL, Wl + (size_t)l * WPL, 256, 768);
        split_w_kernel<<<(256*1024 + 255)/256, 256>>>(
            ffn_w1 + (size_t)l * 262144, Wh + (size_t)l * WPL + 196608,
            Wl + (size_t)l * WPL + 196608, 256, 1024);
        split_w_kernel<<<(1024*256 + 255)/256, 256>>>(
            ffn_w2 + (size_t)l * 262144, Wh + (size_t)l * WPL + 458752,
            Wl + (size_t)l * WPL + 458752, 1024, 256);
    }

    // ---- embed: CLS row + token GEMM (emits X fp32 + bf16 hi/lo) ----
    cls_kernel<<<BB, 256>>>(coords, w_cls, b_cls, X, Xh, Xl);
    gemm_embed_kernel<<<dim3(NTT * BB / 64, DD / 128), 256>>>(
        gene_exp, w_in, b_in, X, Xh, Xl, TOKK, DD);

    for (int l = 0; l < 4; l++) {
        const __nv_bfloat16* Wq  = Wh + (size_t)l * WPL;
        const __nv_bfloat16* Wql = Wl + (size_t)l * WPL;
        gemmA_kernel<false,false><<<dim3(6, GM), 256, GEMM_SMEM>>>(
            Xh, Xl, Wq, Wql, qkv_b + (size_t)l * 768,
            QKV, nullptr, nullptr, MROWS, 256, 768);
        attn_kernel<<<BB * HH, 256, ATTN_SMEM_BYTES>>>(QKV, T);
        add_ln_kernel<<<MROWS / 8, 256>>>(X, T, ln1_g + l * DD, ln1_b + l * DD, Xh, Xl);
        gemmA_kernel<true,true><<<dim3(8, GM), 256, GEMM_SMEM>>>(
            Xh, Xl, Wq + 196608, Wql + 196608, ffn_b1 + (size_t)l * FFF,
            nullptr, Hh, Hl, MROWS, 256, 1024);
        gemmA_kernel<false,false><<<dim3(2, GM), 256, GEMM_SMEM>>>(
            Hh, Hl, Wq + 458752, Wql + 458752, ffn_b2 + (size_t)l * DD,
            T, nullptr, nullptr, MROWS, 1024, 256);
        add_ln_kernel<<<MROWS / 8, 256>>>(X, T, ln2_g + l * DD, ln2_b + l * DD, Xh, Xl);
    }

    head_kernel<<<MROWS / 8, 256>>>(X, th1_w, th1_b, bn_g, bn_b, th2_w, th2_b, S);
    pool_kernel<<<BB, 256>>>(X, S, out);
}

// round 15
// speedup vs baseline: 1.9848x; 1.1945x over previous
#include <cuda_runtime.h>
#include <cuda_bf16.h>
#include <math.h>
#include <stdint.h>

// ---------------- problem constants ----------------
#define BB   64
#define NTT  456
#define TOKK 64
#define DD   256
#define HH   8
#define HDD  32
#define FFF  1024
#define LLN  457            // L = NT + 1
#define MROWS (BB * LLN)    // 29248
#define WPL  720896         // weight elems per layer: 256*768 + 256*1024 + 1024*256

// ---------------- device scratch (static, no allocs) ----------------
__device__ float g_X  [MROWS * DD];
__device__ float g_T  [MROWS * DD];
__device__ float g_QKV[MROWS * 3 * DD];
__device__ __nv_bfloat16 g_Xh[MROWS * DD],  g_Xl[MROWS * DD];
__device__ __nv_bfloat16 g_Hh[MROWS * FFF], g_Hl[MROWS * FFF];
__device__ __nv_bfloat16 g_Wh[4 * WPL],     g_Wl[4 * WPL];
__device__ float g_S  [MROWS];

// ---------------- helpers ----------------
__device__ __forceinline__ float warp_sum(float v) {
#pragma unroll
    for (int o = 16; o; o >>= 1) v += __shfl_xor_sync(0xffffffffu, v, o);
    return v;
}
__device__ __forceinline__ float warp_max(float v) {
#pragma unroll
    for (int o = 16; o; o >>= 1) v = fmaxf(v, __shfl_xor_sync(0xffffffffu, v, o));
    return v;
}
__device__ __forceinline__ uint32_t smem_u32(const void* p) {
    uint32_t a;
    asm("{ .reg .u64 t; cvta.to.shared.u64 t, %1; cvt.u32.u64 %0, t; }"
        : "=r"(a) : "l"(p));
    return a;
}
__device__ __forceinline__ uint32_t pack_bf16(float lo, float hi) {
    uint32_t r;   // lo -> low half, hi -> high half
    asm("cvt.rn.bf16x2.f32 %0, %1, %2;" : "=r"(r) : "f"(hi), "f"(lo));
    return r;
}
__device__ __forceinline__ void split2(float x, float& hi, float& lo) {
    __nv_bfloat16 h = __float2bfloat16_rn(x);
    hi = __bfloat162float(h);
    lo = x - hi;
}
// SW64 swizzle for 64-byte rows (involution; conflict-free ldmatrix/STS)
__device__ __forceinline__ uint32_t swz64(uint32_t x) {
    return x ^ ((x >> 3) & 0x30);
}
__device__ __forceinline__ void ldsm4(uint32_t* r, uint32_t addr) {
    asm volatile("ldmatrix.sync.aligned.m8n8.x4.shared.b16 {%0,%1,%2,%3}, [%4];"
                 : "=r"(r[0]), "=r"(r[1]), "=r"(r[2]), "=r"(r[3]) : "r"(addr));
}
__device__ __forceinline__ void mma_bf16(float* d, const uint32_t* a, const uint32_t* b) {
    asm volatile(
        "mma.sync.aligned.m16n8k16.row.col.f32.bf16.bf16.f32 "
        "{%0,%1,%2,%3}, {%4,%5,%6,%7}, {%8,%9}, {%0,%1,%2,%3};"
        : "+f"(d[0]), "+f"(d[1]), "+f"(d[2]), "+f"(d[3])
        : "r"(a[0]), "r"(a[1]), "r"(a[2]), "r"(a[3]), "r"(b[0]), "r"(b[1]));
}
__device__ __forceinline__ void cp16(uint32_t dst, const void* src) {
    asm volatile("cp.async.cg.shared.global [%0], [%1], 16;" :: "r"(dst), "l"(src));
}
#define CP_COMMIT() asm volatile("cp.async.commit_group;" ::: "memory")
#define CP_WAIT1()  asm volatile("cp.async.wait_group 1;" ::: "memory")

// =====================================================================
// weight pre-split: W[K][N] fp32 -> tiled/swizzled bf16 hi/lo
// blockIdx.y = layer; one launch per weight type.
// =====================================================================
__global__ void split_w_kernel(const float* __restrict__ W,
                               __nv_bfloat16* __restrict__ Wh,
                               __nv_bfloat16* __restrict__ Wl,
                               int K, int N)
{
    int idx = blockIdx.x * 256 + threadIdx.x;
    if (idx >= K * N) return;
    const size_t lw = (size_t)blockIdx.y * K * N;
    const size_t lo_ = (size_t)blockIdx.y * WPL;
    int tile = idx >> 12, w2 = idx & 4095;
    int kc = K >> 5;
    int n_blk = tile / kc, c = tile % kc;
    uint32_t orig = swz64((uint32_t)w2 * 2);
    int n_local = orig >> 6, k_local = (orig & 63) >> 1;
    int k = c * 32 + k_local, n = n_blk * 128 + n_local;
    float v = W[lw + (size_t)k * N + n];
    float hi, lo; split2(v, hi, lo);
    Wh[lo_ + idx] = __float2bfloat16_rn(hi);
    Wl[lo_ + idx] = __float2bfloat16_rn(lo);
}

// =====================================================================
// Pure-bf16 tensor-core split GEMM: C = A @ W + bias
// BM=128, BN=128, BK=32, 256 threads, 3-stage cp.async, 2 CTAs/SM.
// 3-term: Ahi*Whi + Ahi*Wlo + Alo*Whi, fp32 accum.
// grid = (N/128, ceil(M/128))
// =====================================================================
#define GM_STAGES 3
#define STG 32768
#define GEMM_SMEM (GM_STAGES * STG)   // 98304 -> 2 CTAs/SM

template<bool RELU, bool SPLIT_OUT>
__global__ void __launch_bounds__(256, 2)
gemmA_kernel(const __nv_bfloat16* __restrict__ Ah, const __nv_bfloat16* __restrict__ Al,
             const __nv_bfloat16* __restrict__ Wh, const __nv_bfloat16* __restrict__ Wl,
             const float* __restrict__ bias,
             float* __restrict__ Cf,
             __nv_bfloat16* __restrict__ Ch, __nv_bfloat16* __restrict__ Cl,
             int M, int K, int N)
{
    extern __shared__ char smc[];
    const uint32_t sb = smem_u32(smc);
    const int tid = threadIdx.x, lane = tid & 31, w = tid >> 5;
    const int wm = w & 3, wn = w >> 2;
    const int bn = blockIdx.x * 128, bm = blockIdx.y * 128;
    const int NC = K >> 5;

    // per-thread cp.async geometry (2 quads each for A-hi/lo, W-hi/lo)
    uint32_t adst[2]; const __nv_bfloat16 *pah[2], *pal[2];
#pragma unroll
    for (int i = 0; i < 2; i++) {
        int q = tid + i * 256;
        int row = q >> 2, seg = q & 3;
        int gr = bm + row; if (gr >= M) gr = M - 1;
        pah[i] = Ah + (size_t)gr * K + seg * 8;
        pal[i] = Al + (size_t)gr * K + seg * 8;
        adst[i] = swz64((uint32_t)(row * 64 + seg * 16));
    }
    const size_t wtb = (size_t)blockIdx.x * NC * 4096;   // tile base (elements)

    auto load_stage = [&](int c, int s) {
        const uint32_t base = sb + (uint32_t)s * STG;
#pragma unroll
        for (int i = 0; i < 2; i++) {
            int q = tid + i * 256;
            cp16(base +         adst[i], pah[i] + c * 32);
            cp16(base +  8192 + adst[i], pal[i] + c * 32);
            size_t wo = wtb + (size_t)c * 4096 + q * 8;
            cp16(base + 16384 + q * 16, Wh + wo);
            cp16(base + 24576 + q * 16, Wl + wo);
        }
    };

    // prologue: stages 0,1
#pragma unroll
    for (int s = 0; s < GM_STAGES - 1; s++) { load_stage(s, s); CP_COMMIT(); }

    // ldmatrix lane geometry
    const int g = lane >> 3, rr = lane & 7;
    const int a_row = wm * 32 + rr + (g & 1) * 8;
    const int b_row = wn * 64 + rr + (g & 1) * 8;
    const int kbyt  = (g >> 1) * 16;

    float acc[2][8][4];
#pragma unroll
    for (int mt = 0; mt < 2; mt++)
#pragma unroll
        for (int nt = 0; nt < 8; nt++)
#pragma unroll
            for (int q = 0; q < 4; q++) acc[mt][nt][q] = 0.f;

    int sc = 0;   // stage index of chunk c (mod 3)
    for (int c = 0; c < NC; c++) {
        CP_WAIT1();
        __syncthreads();
        const uint32_t base = sb + (uint32_t)sc * STG;
        const uint32_t AHI = base, ALO = base + 8192, WHI = base + 16384, WLO = base + 24576;
#pragma unroll
        for (int ks = 0; ks < 2; ks++) {
            uint32_t Ahf[2][4], Alf[2][4];
#pragma unroll
            for (int mt = 0; mt < 2; mt++) {
                uint32_t off = swz64((uint32_t)((a_row + mt * 16) * 64 + kbyt + ks * 32));
                ldsm4(Ahf[mt], AHI + off);
                ldsm4(Alf[mt], ALO + off);
            }
            uint32_t Bh[8][2], Bl[8][2];
#pragma unroll
            for (int np = 0; np < 4; np++) {
                uint32_t off = swz64((uint32_t)((b_row + np * 16) * 64 + kbyt + ks * 32));
                uint32_t t4[4];
                ldsm4(t4, WHI + off);
                Bh[2*np][0] = t4[0]; Bh[2*np+1][0] = t4[1];
                Bh[2*np][1] = t4[2]; Bh[2*np+1][1] = t4[3];
                ldsm4(t4, WLO + off);
                Bl[2*np][0] = t4[0]; Bl[2*np+1][0] = t4[1];
                Bl[2*np][1] = t4[2]; Bl[2*np+1][1] = t4[3];
            }
#pragma unroll
            for (int mt = 0; mt < 2; mt++)
#pragma unroll
                for (int nt = 0; nt < 8; nt++) {
                    mma_bf16(acc[mt][nt], Ahf[mt], Bh[nt]);
                    mma_bf16(acc[mt][nt], Ahf[mt], Bl[nt]);
                    mma_bf16(acc[mt][nt], Alf[mt], Bh[nt]);
                }
        }
        if (c + GM_STAGES - 1 < NC) {
            int ns = sc;   // (c+2) mod 3 == stage being freed next? no: reuse slot of c after +? compute below
            ns = sc;       // placeholder; real: stage for chunk c+2 is (sc+2)%3
            ns = sc + 2; if (ns >= GM_STAGES) ns -= GM_STAGES;
            load_stage(c + GM_STAGES - 1, ns);
        }
        CP_COMMIT();   // exactly one group per iter keeps wait_group accounting exact
        if (++sc == GM_STAGES) sc = 0;
    }

    // ---------- epilogue ----------
#pragma unroll
    for (int mt = 0; mt < 2; mt++) {
        const int gr0 = bm + wm * 32 + mt * 16 + (lane >> 2);
        const int gr1 = gr0 + 8;
#pragma unroll
        for (int nt = 0; nt < 8; nt++) {
            const int gc = bn + wn * 64 + nt * 8 + (lane & 3) * 2;
            float2 bz = *(const float2*)(bias + gc);
            float v0 = acc[mt][nt][0] + bz.x, v1 = acc[mt][nt][1] + bz.y;
            float v2 = acc[mt][nt][2] + bz.x, v3 = acc[mt][nt][3] + bz.y;
            if (RELU) {
                v0 = fmaxf(v0, 0.f); v1 = fmaxf(v1, 0.f);
                v2 = fmaxf(v2, 0.f); v3 = fmaxf(v3, 0.f);
            }
            if (SPLIT_OUT) {
                float h0,h1,l0,l1;
                if (gr0 < M) {
                    split2(v0,h0,l0); split2(v1,h1,l1);
                    *(uint32_t*)(Ch + (size_t)gr0 * N + gc) = pack_bf16(h0, h1);
                    *(uint32_t*)(Cl + (size_t)gr0 * N + gc) = pack_bf16(l0, l1);
                }
                if (gr1 < M) {
                    split2(v2,h0,l0); split2(v3,h1,l1);
                    *(uint32_t*)(Ch + (size_t)gr1 * N + gc) = pack_bf16(h0, h1);
                    *(uint32_t*)(Cl + (size_t)gr1 * N + gc) = pack_bf16(l0, l1);
                }
            } else {
                if (gr0 < M) *(float2*)(Cf + (size_t)gr0 * N + gc) = make_float2(v0, v1);
                if (gr1 < M) *(float2*)(Cf + (size_t)gr1 * N + gc) = make_float2(v2, v3);
            }
        }
    }
}

// ---------------- SIMT SGEMM for embed (K=64, row remap, emits X + hi/lo) ----------------
__global__ void __launch_bounds__(256) gemm_embed_kernel(
    const float* __restrict__ A, const float* __restrict__ W,
    const float* __restrict__ bias, float* __restrict__ C,
    __nv_bfloat16* __restrict__ Xh, __nv_bfloat16* __restrict__ Xl,
    int K, int N)
{
    __shared__ __align__(16) float As[16][68];
    __shared__ __align__(16) float Bs[16][128];

    const int tid = threadIdx.x;
    const int tx  = tid & 15;
    const int ty  = tid >> 4;
    const int bm  = blockIdx.x * 64;
    const int bn  = blockIdx.y * 128;

    const int la_r = tid >> 2;
    const int la_k = (tid & 3) << 2;
    const int lb_r = tid >> 5;
    const int lb_c = (tid & 31) << 2;

    const float* Aptr  = A + (size_t)(bm + la_r) * K + la_k;
    const float* Wptr0 = W + (size_t)lb_r * N + bn + lb_c;
    const float* Wptr1 = W + (size_t)(lb_r + 8) * N + bn + lb_c;

    float acc[4][8];
#pragma unroll
    for (int i = 0; i < 4; i++)
#pragma unroll
        for (int j = 0; j < 8; j++) acc[i][j] = 0.f;

    for (int k0 = 0; k0 < K; k0 += 16) {
        float4 av  = *(const float4*)(Aptr + k0);
        float4 bw0 = *(const float4*)(Wptr0 + (size_t)k0 * N);
        float4 bw1 = *(const float4*)(Wptr1 + (size_t)k0 * N);
        As[la_k + 0][la_r] = av.x;
        As[la_k + 1][la_r] = av.y;
        As[la_k + 2][la_r] = av.z;
        As[la_k + 3][la_r] = av.w;
        *(float4*)&Bs[lb_r][lb_c]     = bw0;
        *(float4*)&Bs[lb_r + 8][lb_c] = bw1;
        __syncthreads();
#pragma unroll
        for (int kk = 0; kk < 16; kk++) {
            float4 a  = *(const float4*)&As[kk][ty * 4];
            float4 b0 = *(const float4*)&Bs[kk][tx * 8];
            float4 b1 = *(const float4*)&Bs[kk][tx * 8 + 4];
            float ar[4] = {a.x, a.y, a.z, a.w};
            float br[8] = {b0.x, b0.y, b0.z, b0.w, b1.x, b1.y, b1.z, b1.w};
#pragma unroll
            for (int i = 0; i < 4; i++)
#pragma unroll
                for (int j = 0; j < 8; j++)
                    acc[i][j] = fmaf(ar[i], br[j], acc[i][j]);
        }
        __syncthreads();
    }

    float4 bb0 = *(const float4*)(bias + bn + tx * 8);
    float4 bb1 = *(const float4*)(bias + bn + tx * 8 + 4);
    float bx[8] = {bb0.x, bb0.y, bb0.z, bb0.w, bb1.x, bb1.y, bb1.z, bb1.w};

#pragma unroll
    for (int i = 0; i < 4; i++) {
        int r = bm + ty * 4 + i;
        int orow = r + r / NTT + 1;   // (b*NT+t) -> b*L + 1 + t
        float o[8], h[8], lo[8];
#pragma unroll
        for (int j = 0; j < 8; j++) {
            o[j] = acc[i][j] + bx[j];
            split2(o[j], h[j], lo[j]);
        }
        size_t off = (size_t)orow * N + bn + tx * 8;
        float4* cp = (float4*)(C + off);
        cp[0] = make_float4(o[0], o[1], o[2], o[3]);
        cp[1] = make_float4(o[4], o[5], o[6], o[7]);
        uint32_t* ph = (uint32_t*)(Xh + off);
        uint32_t* pl = (uint32_t*)(Xl + off);
        ph[0] = pack_bf16(h[0],h[1]);  ph[1] = pack_bf16(h[2],h[3]);
        ph[2] = pack_bf16(h[4],h[5]);  ph[3] = pack_bf16(h[6],h[7]);
        pl[0] = pack_bf16(lo[0],lo[1]); pl[1] = pack_bf16(lo[2],lo[3]);
        pl[2] = pack_bf16(lo[4],lo[5]); pl[3] = pack_bf16(lo[6],lo[7]);
    }
}

// ---------------- CLS row ----------------
__global__ void cls_kernel(const float* __restrict__ coords,
                           const float* __restrict__ w_cls,
                           const float* __restrict__ b_cls,
                           float* __restrict__ X,
                           __nv_bfloat16* __restrict__ Xh,
                           __nv_bfloat16* __restrict__ Xl)
{
    int b = blockIdx.x, d = threadIdx.x;
    float c0 = coords[b * 3 + 0], c1 = coords[b * 3 + 1], c2 = coords[b * 3 + 2];
    float v = b_cls[d] + c0 * w_cls[d] + c1 * w_cls[DD + d] + c2 * w_cls[2 * DD + d];
    size_t off = (size_t)b * LLN * DD + d;
    X[off] = v;
    float hi, lo; split2(v, hi, lo);
    Xh[off] = __float2bfloat16_rn(hi);
    Xl[off] = __float2bfloat16_rn(lo);
}

// ---------------- fused attention: 512 threads, 16 warps ----------------
#define ATTN_SMEM_FLOATS (457*33 + 457*32 + 32*457 + 16*64)
#define ATTN_SMEM_BYTES  (ATTN_SMEM_FLOATS * 4)

__global__ void __launch_bounds__(512) attn_kernel(const float* __restrict__ QKV,
                                                   float* __restrict__ O)
{
    extern __shared__ float sm[];
    float* Ksm = sm;                      // [457][33]
    float* Vsm = Ksm + 457 * 33;          // [457][32]
    float* Ssm = Vsm + 457 * 32;          // [32][457]
    float* Qsm = Ssm + 32 * 457;          // [16][64]

    const int bh = blockIdx.x;
    const int b = bh >> 3, h = bh & 7;
    const int tid = threadIdx.x, w = tid >> 5, lane = tid & 31;
    const float slope = (h < 4) ? 1.0f : 0.5f;
    const float scale = 0.17677669529663687f;

    const float* base = QKV + (size_t)b * (LLN * 3 * DD) + h * HDD;

    for (int idx = tid; idx < 457 * 32; idx += 512) {
        int j = idx >> 5, d = idx & 31;
        const float* kv = base + (size_t)j * (3 * DD);
        Ksm[j * 33 + d] = kv[DD + d];
        Vsm[idx]        = kv[2 * DD + d];
    }
    __syncthreads();

    for (int i0 = 2 * w; i0 < LLN; i0 += 32) {
        const bool two = (i0 + 1 < LLN);
        Qsm[w * 64 + lane] = base[(size_t)i0 * (3 * DD) + lane];
        if (two) Qsm[w * 64 + 32 + lane] = base[(size_t)(i0 + 1) * (3 * DD) + lane];
        __syncwarp();

        float s0[15], s1[15];
#pragma unroll
        for (int t = 0; t < 15; t++) { s0[t] = 0.f; s1[t] = 0.f; }
        for (int d = 0; d < 32; d++) {
            float q0 = Qsm[w * 64 + d];
            float q1 = Qsm[w * 64 + 32 + d];
#pragma unroll
            for (int t = 0; t < 15; t++) {
                int jj = lane + t * 32;
                if (jj < LLN) {
                    float kv = Ksm[jj * 33 + d];
                    s0[t] += q0 * kv;
                    s1[t] += q1 * kv;
                }
            }
        }
        float mx0 = -1e30f, mx1 = -1e30f;
#pragma unroll
        for (int t = 0; t < 15; t++) {
            int jj = lane + t * 32;
            if (jj < LLN) {
                s0[t] = s0[t] * scale - slope * fabsf((float)(i0 - jj));
                s1[t] = s1[t] * scale - slope * fabsf((float)(i0 + 1 - jj));
                mx0 = fmaxf(mx0, s0[t]);
                mx1 = fmaxf(mx1, s1[t]);
            }
        }
        mx0 = warp_max(mx0); mx1 = warp_max(mx1);
        float sum0 = 0.f, sum1 = 0.f;
#pragma unroll
        for (int t = 0; t < 15; t++) {
            int jj = lane + t * 32;
            if (jj < LLN) {
                float e0 = __expf(s0[t] - mx0);
                float e1 = __expf(s1[t] - mx1);
                Ssm[(2 * w) * 457 + jj]     = e0;
                Ssm[(2 * w + 1) * 457 + jj] = e1;
                sum0 += e0; sum1 += e1;
            }
        }
        sum0 = warp_sum(sum0); sum1 = warp_sum(sum1);
        float inv0 = 1.f / sum0, inv1 = 1.f / sum1;
        __syncwarp();

        float acc0 = 0.f, acc1 = 0.f;
        const float* p0 = Ssm + (2 * w) * 457;
        const float* p1 = Ssm + (2 * w + 1) * 457;
#pragma unroll 4
        for (int j = 0; j < LLN; j++) {
            float v = Vsm[j * 32 + lane];
            acc0 += p0[j] * v;
            acc1 += p1[j] * v;
        }
        float* op = O + ((size_t)b * LLN + i0) * DD + h * HDD + lane;
        op[0] = acc0 * inv0;
        if (two) op[DD] = acc1 * inv1;
        __syncwarp();
    }
}

// ---------------- fused residual add + LayerNorm (emits fp32 X + bf16 hi/lo) ----------------
__global__ void __launch_bounds__(256) add_ln_kernel(float* __restrict__ X,
                                                     const float* __restrict__ T,
                                                     const float* __restrict__ g,
                                                     const float* __restrict__ bta,
                                                     __nv_bfloat16* __restrict__ Xh,
                                                     __nv_bfloat16* __restrict__ Xl)
{
    const int w = threadIdx.x >> 5, lane = threadIdx.x & 31;
    const size_t row = (size_t)blockIdx.x * 8 + w;
    float* xr = X + row * DD;
    const float* tr = T + row * DD;

    float4 x0 = ((const float4*)xr)[lane];
    float4 x1 = ((const float4*)xr)[lane + 32];
    float4 t0 = ((const float4*)tr)[lane];
    float4 t1 = ((const float4*)tr)[lane + 32];
    float v[8] = {x0.x + t0.x, x0.y + t0.y, x0.z + t0.z, x0.w + t0.w,
                  x1.x + t1.x, x1.y + t1.y, x1.z + t1.z, x1.w + t1.w};
    float s = 0.f;
#pragma unroll
    for (int i = 0; i < 8; i++) s += v[i];
    float m = warp_sum(s) * (1.f / 256.f);
    float vs = 0.f;
#pragma unroll
    for (int i = 0; i < 8; i++) { float d = v[i] - m; vs += d * d; }
    float rstd = rsqrtf(warp_sum(vs) * (1.f / 256.f) + 1e-5f);

    float4 g0 = ((const float4*)g)[lane];
    float4 g1 = ((const float4*)g)[lane + 32];
    float4 b0 = ((const float4*)bta)[lane];
    float4 b1 = ((const float4*)bta)[lane + 32];
    float o[8];
    o[0]=(v[0]-m)*rstd*g0.x + b0.x; o[1]=(v[1]-m)*rstd*g0.y + b0.y;
    o[2]=(v[2]-m)*rstd*g0.z + b0.z; o[3]=(v[3]-m)*rstd*g0.w + b0.w;
    o[4]=(v[4]-m)*rstd*g1.x + b1.x; o[5]=(v[5]-m)*rstd*g1.y + b1.y;
    o[6]=(v[6]-m)*rstd*g1.z + b1.z; o[7]=(v[7]-m)*rstd*g1.w + b1.w;
    ((float4*)xr)[lane]      = make_float4(o[0],o[1],o[2],o[3]);
    ((float4*)xr)[lane + 32] = make_float4(o[4],o[5],o[6],o[7]);

    float h[8], lo[8];
#pragma unroll
    for (int i = 0; i < 8; i++) split2(o[i], h[i], lo[i]);
    uint32_t* ph = (uint32_t*)(Xh + row * DD);
    uint32_t* pl = (uint32_t*)(Xl + row * DD);
    ph[lane*2]      = pack_bf16(h[0],h[1]);  ph[lane*2+1]      = pack_bf16(h[2],h[3]);
    ph[64+lane*2]   = pack_bf16(h[4],h[5]);  ph[64+lane*2+1]   = pack_bf16(h[6],h[7]);
    pl[lane*2]      = pack_bf16(lo[0],lo[1]); pl[lane*2+1]     = pack_bf16(lo[2],lo[3]);
    pl[64+lane*2]   = pack_bf16(lo[4],lo[5]); pl[64+lane*2+1]  = pack_bf16(lo[6],lo[7]);
}

// ---------------- head ----------------
__global__ void __launch_bounds__(256) head_kernel(
    const float* __restrict__ X,   const float* __restrict__ th1_w,
    const float* __restrict__ th1_b, const float* __restrict__ bn_g,
    const float* __restrict__ bn_b,  const float* __restrict__ th2_w,
    const float* __restrict__ th2_b, float* __restrict__ S)
{
    __shared__ float wsm[DD * 32];
    __shared__ float xs[8][DD];
    const int tid = threadIdx.x, w = tid >> 5, lane = tid & 31;

    for (int i = tid; i < DD * 32 / 4; i += 256)
        ((float4*)wsm)[i] = ((const float4*)th1_w)[i];

    const size_t row = (size_t)blockIdx.x * 8 + w;
    const float4* xr = (const float4*)(X + row * DD);
    float4* xd = (float4*)xs[w];
    xd[lane]      = xr[lane];
    xd[lane + 32] = xr[lane + 32];
    __syncthreads();

    float acc = th1_b[lane];
#pragma unroll 4
    for (int d = 0; d < DD; d++)
        acc += xs[w][d] * wsm[d * 32 + lane];

    float hv = acc * (bn_g[lane] * rsqrtf(1.f + 1e-5f)) + bn_b[lane];
    const float c = 0.7978845608028654f;
    float gl = 0.5f * hv * (1.f + tanhf(c * (hv + 0.044715f * hv * hv * hv)));
    float p = warp_sum(gl * th2_w[lane]);
    if (lane == 0) S[row] = p + th2_b[0];
}

// ---------------- pool ----------------
__global__ void __launch_bounds__(256) pool_kernel(const float* __restrict__ X,
                                                   const float* __restrict__ S,
                                                   float* __restrict__ out)
{
    __shared__ float wv[LLN];
    __shared__ float red[256];
    const int b = blockIdx.x, tid = threadIdx.x;
    const float* sp = S + (size_t)b * LLN;

    float mx = -1e30f;
    for (int l = tid; l < LLN; l += 256) mx = fmaxf(mx, sp[l]);
    red[tid] = mx; __syncthreads();
    for (int s = 128; s; s >>= 1) { if (tid < s) red[tid] = fmaxf(red[tid], red[tid + s]); __syncthreads(); }
    mx = red[0]; __syncthreads();

    float sum = 0.f;
    for (int l = tid; l < LLN; l += 256) { float e = __expf(sp[l] - mx); wv[l] = e; sum += e; }
    red[tid] = sum; __syncthreads();
    for (int s = 128; s; s >>= 1) { if (tid < s) red[tid] += red[tid + s]; __syncthreads(); }
    float inv = 1.f / red[0];
    __syncthreads();

    float acc = 0.f;
    const float* xp = X + (size_t)b * LLN * DD + tid;
#pragma unroll 4
    for (int l = 0; l < LLN; l++) acc += wv[l] * xp[(size_t)l * DD];
    out[(size_t)b * DD + tid] = acc * inv;
}

// ---------------- launch ----------------
extern "C" void kernel_launch(void* const* d_in, const int* in_sizes, int n_in,
                              void* d_out, int out_size)
{
    const float* gene_exp = (const float*)d_in[0];
    const float* coords   = (const float*)d_in[1];
    const float* w_in     = (const float*)d_in[2];
    const float* b_in     = (const float*)d_in[3];
    const float* w_cls    = (const float*)d_in[4];
    const float* b_cls    = (const float*)d_in[5];
    const float* qkv_w    = (const float*)d_in[6];
    const float* qkv_b    = (const float*)d_in[7];
    const float* ln1_g    = (const float*)d_in[8];
    const float* ln1_b    = (const float*)d_in[9];
    const float* ffn_w1   = (const float*)d_in[10];
    const float* ffn_b1   = (const float*)d_in[11];
    const float* ffn_w2   = (const float*)d_in[12];
    const float* ffn_b2   = (const float*)d_in[13];
    const float* ln2_g    = (const float*)d_in[14];
    const float* ln2_b    = (const float*)d_in[15];
    const float* th1_w    = (const float*)d_in[16];
    const float* th1_b    = (const float*)d_in[17];
    const float* bn_g     = (const float*)d_in[18];
    const float* bn_b     = (const float*)d_in[19];
    const float* th2_w    = (const float*)d_in[20];
    const float* th2_b    = (const float*)d_in[21];
    float* out = (float*)d_out;

    float *X, *T, *QKV, *S;
    __nv_bfloat16 *Xh, *Xl, *Hh, *Hl, *Wh, *Wl;
    cudaGetSymbolAddress((void**)&X,   g_X);
    cudaGetSymbolAddress((void**)&T,   g_T);
    cudaGetSymbolAddress((void**)&QKV, g_QKV);
    cudaGetSymbolAddress((void**)&S,   g_S);
    cudaGetSymbolAddress((void**)&Xh,  g_Xh);
    cudaGetSymbolAddress((void**)&Xl,  g_Xl);
    cudaGetSymbolAddress((void**)&Hh,  g_Hh);
    cudaGetSymbolAddress((void**)&Hl,  g_Hl);
    cudaGetSymbolAddress((void**)&Wh,  g_Wh);
    cudaGetSymbolAddress((void**)&Wl,  g_Wl);

    cudaFuncSetAttribute(attn_kernel, cudaFuncAttributeMaxDynamicSharedMemorySize,
                         ATTN_SMEM_BYTES);
    cudaFuncSetAttribute(gemmA_kernel<false,false>,
                         cudaFuncAttributeMaxDynamicSharedMemorySize, GEMM_SMEM);
    cudaFuncSetAttribute(gemmA_kernel<true,true>,
                         cudaFuncAttributeMaxDynamicSharedMemorySize, GEMM_SMEM);

    const int GM = (MROWS + 127) / 128;   // 229

    // ---- weight pre-split (pre-tiled, pre-swizzled); blockIdx.y = layer ----
    split_w_kernel<<<dim3((256*768 + 255)/256, 4), 256>>>(qkv_w,  Wh,          Wl,          256, 768);
    split_w_kernel<<<dim3((256*1024 + 255)/256, 4), 256>>>(ffn_w1, Wh + 196608, Wl + 196608, 256, 1024);
    split_w_kernel<<<dim3((1024*256 + 255)/256, 4), 256>>>(ffn_w2, Wh + 458752, Wl + 458752, 1024, 256);

    // ---- embed: CLS row + token GEMM (emits X fp32 + bf16 hi/lo) ----
    cls_kernel<<<BB, 256>>>(coords, w_cls, b_cls, X, Xh, Xl);
    gemm_embed_kernel<<<dim3(NTT * BB / 64, DD / 128), 256>>>(
        gene_exp, w_in, b_in, X, Xh, Xl, TOKK, DD);

    for (int l = 0; l < 4; l++) {
        const __nv_bfloat16* Wq  = Wh + (size_t)l * WPL;
        const __nv_bfloat16* Wql = Wl + (size_t)l * WPL;
        gemmA_kernel<false,false><<<dim3(6, GM), 256, GEMM_SMEM>>>(
            Xh, Xl, Wq, Wql, qkv_b + (size_t)l * 768,
            QKV, nullptr, nullptr, MROWS, 256, 768);
        attn_kernel<<<BB * HH, 512, ATTN_SMEM_BYTES>>>(QKV, T);
        add_ln_kernel<<<MROWS / 8, 256>>>(X, T, ln1_g + l * DD, ln1_b + l * DD, Xh, Xl);
        gemmA_kernel<true,true><<<dim3(8, GM), 256, GEMM_SMEM>>>(
            Xh, Xl, Wq + 196608, Wql + 196608, ffn_b1 + (size_t)l * FFF,
            nullptr, Hh, Hl, MROWS, 256, 1024);
        gemmA_kernel<false,false><<<dim3(2, GM), 256, GEMM_SMEM>>>(
            Hh, Hl, Wq + 458752, Wql + 458752, ffn_b2 + (size_t)l * DD,
            T, nullptr, nullptr, MROWS, 1024, 256);
        add_ln_kernel<<<MROWS / 8, 256>>>(X, T, ln2_g + l * DD, ln2_b + l * DD, Xh, Xl);
    }

    head_kernel<<<MROWS / 8, 256>>>(X, th1_w, th1_b, bn_g, bn_b, th2_w, th2_b, S);
    pool_kernel<<<BB, 256>>>(X, S, out);
}

// round 16
// speedup vs baseline: 2.1968x; 1.1068x over previous
#include <cuda_runtime.h>
#include <cuda_fp16.h>
#include <math.h>
#include <stdint.h>

// ---------------- problem constants ----------------
#define BB   64
#define NTT  456
#define TOKK 64
#define DD   256
#define HH   8
#define HDD  32
#define FFF  1024
#define LLN  457            // L = NT + 1
#define MROWS (BB * LLN)    // 29248
#define WPL  720896         // weight elems per layer: 256*768 + 256*1024 + 1024*256

// ---------------- device scratch (static, no allocs) ----------------
__device__ float g_X  [MROWS * DD];
__device__ float g_T  [MROWS * DD];
__device__ float g_QKV[MROWS * 3 * DD];
__device__ __half g_Xh[MROWS * DD],  g_Xl[MROWS * DD];
__device__ __half g_Hh[MROWS * FFF], g_Hl[MROWS * FFF];
__device__ __half g_Wh[4 * WPL];
__device__ float g_S  [MROWS];

// ---------------- helpers ----------------
__device__ __forceinline__ float warp_sum(float v) {
#pragma unroll
    for (int o = 16; o; o >>= 1) v += __shfl_xor_sync(0xffffffffu, v, o);
    return v;
}
__device__ __forceinline__ float warp_max(float v) {
#pragma unroll
    for (int o = 16; o; o >>= 1) v = fmaxf(v, __shfl_xor_sync(0xffffffffu, v, o));
    return v;
}
__device__ __forceinline__ uint32_t smem_u32(const void* p) {
    uint32_t a;
    asm("{ .reg .u64 t; cvta.to.shared.u64 t, %1; cvt.u32.u64 %0, t; }"
        : "=r"(a) : "l"(p));
    return a;
}
__device__ __forceinline__ uint32_t pack_f16(float lo, float hi) {
    uint32_t r;   // lo -> low half, hi -> high half
    asm("cvt.rn.f16x2.f32 %0, %1, %2;" : "=r"(r) : "f"(hi), "f"(lo));
    return r;
}
__device__ __forceinline__ void split2h(float x, float& hi, float& lo) {
    __half h = __float2half_rn(x);
    hi = __half2float(h);
    lo = x - hi;
}
// SW64 swizzle for 64-byte rows (involution; conflict-free ldmatrix/STS)
__device__ __forceinline__ uint32_t swz64(uint32_t x) {
    return x ^ ((x >> 3) & 0x30);
}
__device__ __forceinline__ void ldsm4(uint32_t* r, uint32_t addr) {
    asm volatile("ldmatrix.sync.aligned.m8n8.x4.shared.b16 {%0,%1,%2,%3}, [%4];"
                 : "=r"(r[0]), "=r"(r[1]), "=r"(r[2]), "=r"(r[3]) : "r"(addr));
}
__device__ __forceinline__ void mma_f16(float* d, const uint32_t* a, const uint32_t* b) {
    asm volatile(
        "mma.sync.aligned.m16n8k16.row.col.f32.f16.f16.f32 "
        "{%0,%1,%2,%3}, {%4,%5,%6,%7}, {%8,%9}, {%0,%1,%2,%3};"
        : "+f"(d[0]), "+f"(d[1]), "+f"(d[2]), "+f"(d[3])
        : "r"(a[0]), "r"(a[1]), "r"(a[2]), "r"(a[3]), "r"(b[0]), "r"(b[1]));
}
__device__ __forceinline__ void cp16(uint32_t dst, const void* src) {
    asm volatile("cp.async.cg.shared.global [%0], [%1], 16;" :: "r"(dst), "l"(src));
}
#define CP_COMMIT() asm volatile("cp.async.commit_group;" ::: "memory")
#define CP_WAIT2()  asm volatile("cp.async.wait_group 2;" ::: "memory")

// =====================================================================
// weight pre-split: W[K][N] fp32 -> tiled/swizzled single fp16
// tile = 128 n x 32 k; blockIdx.y = layer.
// =====================================================================
__global__ void split_w_kernel(const float* __restrict__ W,
                               __half* __restrict__ Wh,
                               int K, int N)
{
    int idx = blockIdx.x * 256 + threadIdx.x;
    if (idx >= K * N) return;
    const size_t lw = (size_t)blockIdx.y * K * N;
    const size_t lo_ = (size_t)blockIdx.y * WPL;
    int tile = idx >> 12, w2 = idx & 4095;
    int kc = K >> 5;
    int n_blk = tile / kc, c = tile % kc;
    uint32_t orig = swz64((uint32_t)w2 * 2);
    int n_local = orig >> 6, k_local = (orig & 63) >> 1;
    int k = c * 32 + k_local, n = n_blk * 128 + n_local;
    Wh[lo_ + idx] = __float2half_rn(W[lw + (size_t)k * N + n]);
}

// =====================================================================
// fp16 2-term tensor-core GEMM: C = A @ W + bias
// A pre-split fp16 hi/lo; W single fp16 pre-tiled.
// BM=128, BN=128, BK=32, 256 threads, 4-stage cp.async, 2 CTAs/SM.
// C = Ahi*W + Alo*W, fp32 accum.  grid = (N/128, ceil(M/128))
// =====================================================================
#define GM_STAGES 4
#define STG 24576            // AHI 8K + ALO 8K + WH 8K
#define GEMM_SMEM (GM_STAGES * STG)   // 98304 -> 2 CTAs/SM

template<bool RELU, bool SPLIT_OUT>
__global__ void __launch_bounds__(256, 2)
gemmA_kernel(const __half* __restrict__ Ah, const __half* __restrict__ Al,
             const __half* __restrict__ Wh,
             const float* __restrict__ bias,
             float* __restrict__ Cf,
             __half* __restrict__ Ch, __half* __restrict__ Cl,
             int M, int K, int N)
{
    extern __shared__ char smc[];
    const uint32_t sb = smem_u32(smc);
    const int tid = threadIdx.x, lane = tid & 31, w = tid >> 5;
    const int wm = w & 3, wn = w >> 2;
    const int bn = blockIdx.x * 128, bm = blockIdx.y * 128;
    const int NC = K >> 5;

    // per-thread cp.async geometry
    uint32_t adst[2]; const __half *pah[2], *pal[2];
#pragma unroll
    for (int i = 0; i < 2; i++) {
        int q = tid + i * 256;
        int row = q >> 2, seg = q & 3;
        int gr = bm + row; if (gr >= M) gr = M - 1;
        pah[i] = Ah + (size_t)gr * K + seg * 8;
        pal[i] = Al + (size_t)gr * K + seg * 8;
        adst[i] = swz64((uint32_t)(row * 64 + seg * 16));
    }
    const size_t wtb = (size_t)blockIdx.x * NC * 4096;   // W tile base (elements)

    auto load_stage = [&](int c, int s) {
        const uint32_t base = sb + (uint32_t)s * STG;
#pragma unroll
        for (int i = 0; i < 2; i++) {
            int q = tid + i * 256;
            cp16(base +         adst[i], pah[i] + c * 32);
            cp16(base +  8192 + adst[i], pal[i] + c * 32);
            cp16(base + 16384 + q * 16, Wh + wtb + (size_t)c * 4096 + q * 8);
        }
    };

    // prologue: stages 0..2
#pragma unroll
    for (int s = 0; s < GM_STAGES - 1; s++) { load_stage(s, s); CP_COMMIT(); }

    // ldmatrix lane geometry
    const int g = lane >> 3, rr = lane & 7;
    const int a_row = wm * 32 + rr + (g & 1) * 8;
    const int b_row = wn * 64 + rr + (g & 1) * 8;
    const int kbyt  = (g >> 1) * 16;

    float acc[2][8][4];
#pragma unroll
    for (int mt = 0; mt < 2; mt++)
#pragma unroll
        for (int nt = 0; nt < 8; nt++)
#pragma unroll
            for (int q = 0; q < 4; q++) acc[mt][nt][q] = 0.f;

    for (int c = 0; c < NC; c++) {
        CP_WAIT2();
        __syncthreads();
        const uint32_t base = sb + (uint32_t)(c & 3) * STG;
        const uint32_t AHI = base, ALO = base + 8192, WH = base + 16384;
#pragma unroll
        for (int ks = 0; ks < 2; ks++) {
            uint32_t Ahf[2][4], Alf[2][4];
#pragma unroll
            for (int mt = 0; mt < 2; mt++) {
                uint32_t off = swz64((uint32_t)((a_row + mt * 16) * 64 + kbyt + ks * 32));
                ldsm4(Ahf[mt], AHI + off);
                ldsm4(Alf[mt], ALO + off);
            }
            uint32_t B[8][2];
#pragma unroll
            for (int np = 0; np < 4; np++) {
                uint32_t off = swz64((uint32_t)((b_row + np * 16) * 64 + kbyt + ks * 32));
                uint32_t t4[4];
                ldsm4(t4, WH + off);
                B[2*np][0] = t4[0]; B[2*np+1][0] = t4[1];
                B[2*np][1] = t4[2]; B[2*np+1][1] = t4[3];
            }
#pragma unroll
            for (int mt = 0; mt < 2; mt++)
#pragma unroll
                for (int nt = 0; nt < 8; nt++) {
                    mma_f16(acc[mt][nt], Ahf[mt], B[nt]);
                    mma_f16(acc[mt][nt], Alf[mt], B[nt]);
                }
        }
        if (c + GM_STAGES - 1 < NC)
            load_stage(c + GM_STAGES - 1, (c + GM_STAGES - 1) & 3);
        CP_COMMIT();   // one group per iter keeps wait_group accounting exact
    }

    // ---------- epilogue ----------
#pragma unroll
    for (int mt = 0; mt < 2; mt++) {
        const int gr0 = bm + wm * 32 + mt * 16 + (lane >> 2);
        const int gr1 = gr0 + 8;
#pragma unroll
        for (int nt = 0; nt < 8; nt++) {
            const int gc = bn + wn * 64 + nt * 8 + (lane & 3) * 2;
            float2 bz = *(const float2*)(bias + gc);
            float v0 = acc[mt][nt][0] + bz.x, v1 = acc[mt][nt][1] + bz.y;
            float v2 = acc[mt][nt][2] + bz.x, v3 = acc[mt][nt][3] + bz.y;
            if (RELU) {
                v0 = fmaxf(v0, 0.f); v1 = fmaxf(v1, 0.f);
                v2 = fmaxf(v2, 0.f); v3 = fmaxf(v3, 0.f);
            }
            if (SPLIT_OUT) {
                float h0,h1,l0,l1;
                if (gr0 < M) {
                    split2h(v0,h0,l0); split2h(v1,h1,l1);
                    *(uint32_t*)(Ch + (size_t)gr0 * N + gc) = pack_f16(h0, h1);
                    *(uint32_t*)(Cl + (size_t)gr0 * N + gc) = pack_f16(l0, l1);
                }
                if (gr1 < M) {
                    split2h(v2,h0,l0); split2h(v3,h1,l1);
                    *(uint32_t*)(Ch + (size_t)gr1 * N + gc) = pack_f16(h0, h1);
                    *(uint32_t*)(Cl + (size_t)gr1 * N + gc) = pack_f16(l0, l1);
                }
            } else {
                if (gr0 < M) *(float2*)(Cf + (size_t)gr0 * N + gc) = make_float2(v0, v1);
                if (gr1 < M) *(float2*)(Cf + (size_t)gr1 * N + gc) = make_float2(v2, v3);
            }
        }
    }
}

// ---------------- SIMT SGEMM for embed (K=64, row remap, emits X + hi/lo) ----------------
__global__ void __launch_bounds__(256) gemm_embed_kernel(
    const float* __restrict__ A, const float* __restrict__ W,
    const float* __restrict__ bias, float* __restrict__ C,
    __half* __restrict__ Xh, __half* __restrict__ Xl,
    int K, int N)
{
    __shared__ __align__(16) float As[16][68];
    __shared__ __align__(16) float Bs[16][128];

    const int tid = threadIdx.x;
    const int tx  = tid & 15;
    const int ty  = tid >> 4;
    const int bm  = blockIdx.x * 64;
    const int bn  = blockIdx.y * 128;

    const int la_r = tid >> 2;
    const int la_k = (tid & 3) << 2;
    const int lb_r = tid >> 5;
    const int lb_c = (tid & 31) << 2;

    const float* Aptr  = A + (size_t)(bm + la_r) * K + la_k;
    const float* Wptr0 = W + (size_t)lb_r * N + bn + lb_c;
    const float* Wptr1 = W + (size_t)(lb_r + 8) * N + bn + lb_c;

    float acc[4][8];
#pragma unroll
    for (int i = 0; i < 4; i++)
#pragma unroll
        for (int j = 0; j < 8; j++) acc[i][j] = 0.f;

    for (int k0 = 0; k0 < K; k0 += 16) {
        float4 av  = *(const float4*)(Aptr + k0);
        float4 bw0 = *(const float4*)(Wptr0 + (size_t)k0 * N);
        float4 bw1 = *(const float4*)(Wptr1 + (size_t)k0 * N);
        As[la_k + 0][la_r] = av.x;
        As[la_k + 1][la_r] = av.y;
        As[la_k + 2][la_r] = av.z;
        As[la_k + 3][la_r] = av.w;
        *(float4*)&Bs[lb_r][lb_c]     = bw0;
        *(float4*)&Bs[lb_r + 8][lb_c] = bw1;
        __syncthreads();
#pragma unroll
        for (int kk = 0; kk < 16; kk++) {
            float4 a  = *(const float4*)&As[kk][ty * 4];
            float4 b0 = *(const float4*)&Bs[kk][tx * 8];
            float4 b1 = *(const float4*)&Bs[kk][tx * 8 + 4];
            float ar[4] = {a.x, a.y, a.z, a.w};
            float br[8] = {b0.x, b0.y, b0.z, b0.w, b1.x, b1.y, b1.z, b1.w};
#pragma unroll
            for (int i = 0; i < 4; i++)
#pragma unroll
                for (int j = 0; j < 8; j++)
                    acc[i][j] = fmaf(ar[i], br[j], acc[i][j]);
        }
        __syncthreads();
    }

    float4 bb0 = *(const float4*)(bias + bn + tx * 8);
    float4 bb1 = *(const float4*)(bias + bn + tx * 8 + 4);
    float bx[8] = {bb0.x, bb0.y, bb0.z, bb0.w, bb1.x, bb1.y, bb1.z, bb1.w};

#pragma unroll
    for (int i = 0; i < 4; i++) {
        int r = bm + ty * 4 + i;
        int orow = r + r / NTT + 1;   // (b*NT+t) -> b*L + 1 + t
        float o[8], h[8], lo[8];
#pragma unroll
        for (int j = 0; j < 8; j++) {
            o[j] = acc[i][j] + bx[j];
            split2h(o[j], h[j], lo[j]);
        }
        size_t off = (size_t)orow * N + bn + tx * 8;
        float4* cp = (float4*)(C + off);
        cp[0] = make_float4(o[0], o[1], o[2], o[3]);
        cp[1] = make_float4(o[4], o[5], o[6], o[7]);
        uint32_t* ph = (uint32_t*)(Xh + off);
        uint32_t* pl = (uint32_t*)(Xl + off);
        ph[0] = pack_f16(h[0],h[1]);  ph[1] = pack_f16(h[2],h[3]);
        ph[2] = pack_f16(h[4],h[5]);  ph[3] = pack_f16(h[6],h[7]);
        pl[0] = pack_f16(lo[0],lo[1]); pl[1] = pack_f16(lo[2],lo[3]);
        pl[2] = pack_f16(lo[4],lo[5]); pl[3] = pack_f16(lo[6],lo[7]);
    }
}

// ---------------- CLS row ----------------
__global__ void cls_kernel(const float* __restrict__ coords,
                           const float* __restrict__ w_cls,
                           const float* __restrict__ b_cls,
                           float* __restrict__ X,
                           __half* __restrict__ Xh,
                           __half* __restrict__ Xl)
{
    int b = blockIdx.x, d = threadIdx.x;
    float c0 = coords[b * 3 + 0], c1 = coords[b * 3 + 1], c2 = coords[b * 3 + 2];
    float v = b_cls[d] + c0 * w_cls[d] + c1 * w_cls[DD + d] + c2 * w_cls[2 * DD + d];
    size_t off = (size_t)b * LLN * DD + d;
    X[off] = v;
    float hi, lo; split2h(v, hi, lo);
    Xh[off] = __float2half_rn(hi);
    Xl[off] = __float2half_rn(lo);
}

// ---------------- fused attention: 512 threads, 16 warps ----------------
#define ATTN_SMEM_FLOATS (457*33 + 457*32 + 32*457 + 16*64)
#define ATTN_SMEM_BYTES  (ATTN_SMEM_FLOATS * 4)

__global__ void __launch_bounds__(512) attn_kernel(const float* __restrict__ QKV,
                                                   float* __restrict__ O)
{
    extern __shared__ float sm[];
    float* Ksm = sm;                      // [457][33]
    float* Vsm = Ksm + 457 * 33;          // [457][32]
    float* Ssm = Vsm + 457 * 32;          // [32][457]
    float* Qsm = Ssm + 32 * 457;          // [16][64]

    const int bh = blockIdx.x;
    const int b = bh >> 3, h = bh & 7;
    const int tid = threadIdx.x, w = tid >> 5, lane = tid & 31;
    const float slope = (h < 4) ? 1.0f : 0.5f;
    const float scale = 0.17677669529663687f;

    const float* base = QKV + (size_t)b * (LLN * 3 * DD) + h * HDD;

    for (int idx = tid; idx < 457 * 32; idx += 512) {
        int j = idx >> 5, d = idx & 31;
        const float* kv = base + (size_t)j * (3 * DD);
        Ksm[j * 33 + d] = kv[DD + d];
        Vsm[idx]        = kv[2 * DD + d];
    }
    __syncthreads();

    for (int i0 = 2 * w; i0 < LLN; i0 += 32) {
        const bool two = (i0 + 1 < LLN);
        Qsm[w * 64 + lane] = base[(size_t)i0 * (3 * DD) + lane];
        if (two) Qsm[w * 64 + 32 + lane] = base[(size_t)(i0 + 1) * (3 * DD) + lane];
        __syncwarp();

        float s0[15], s1[15];
#pragma unroll
        for (int t = 0; t < 15; t++) { s0[t] = 0.f; s1[t] = 0.f; }
        for (int d = 0; d < 32; d++) {
            float q0 = Qsm[w * 64 + d];
            float q1 = Qsm[w * 64 + 32 + d];
#pragma unroll
            for (int t = 0; t < 15; t++) {
                int jj = lane + t * 32;
                if (jj < LLN) {
                    float kv = Ksm[jj * 33 + d];
                    s0[t] += q0 * kv;
                    s1[t] += q1 * kv;
                }
            }
        }
        float mx0 = -1e30f, mx1 = -1e30f;
#pragma unroll
        for (int t = 0; t < 15; t++) {
            int jj = lane + t * 32;
            if (jj < LLN) {
                s0[t] = s0[t] * scale - slope * fabsf((float)(i0 - jj));
                s1[t] = s1[t] * scale - slope * fabsf((float)(i0 + 1 - jj));
                mx0 = fmaxf(mx0, s0[t]);
                mx1 = fmaxf(mx1, s1[t]);
            }
        }
        mx0 = warp_max(mx0); mx1 = warp_max(mx1);
        float sum0 = 0.f, sum1 = 0.f;
#pragma unroll
        for (int t = 0; t < 15; t++) {
            int jj = lane + t * 32;
            if (jj < LLN) {
                float e0 = __expf(s0[t] - mx0);
                float e1 = __expf(s1[t] - mx1);
                Ssm[(2 * w) * 457 + jj]     = e0;
                Ssm[(2 * w + 1) * 457 + jj] = e1;
                sum0 += e0; sum1 += e1;
            }
        }
        sum0 = warp_sum(sum0); sum1 = warp_sum(sum1);
        float inv0 = 1.f / sum0, inv1 = 1.f / sum1;
        __syncwarp();

        float acc0 = 0.f, acc1 = 0.f;
        const float* p0 = Ssm + (2 * w) * 457;
        const float* p1 = Ssm + (2 * w + 1) * 457;
#pragma unroll 4
        for (int j = 0; j < LLN; j++) {
            float v = Vsm[j * 32 + lane];
            acc0 += p0[j] * v;
            acc1 += p1[j] * v;
        }
        float* op = O + ((size_t)b * LLN + i0) * DD + h * HDD + lane;
        op[0] = acc0 * inv0;
        if (two) op[DD] = acc1 * inv1;
        __syncwarp();
    }
}

// ---------------- fused residual add + LayerNorm (emits fp32 X + fp16 hi/lo) ----------------
__global__ void __launch_bounds__(256) add_ln_kernel(float* __restrict__ X,
                                                     const float* __restrict__ T,
                                                     const float* __restrict__ g,
                                                     const float* __restrict__ bta,
                                                     __half* __restrict__ Xh,
                                                     __half* __restrict__ Xl)
{
    const int w = threadIdx.x >> 5, lane = threadIdx.x & 31;
    const size_t row = (size_t)blockIdx.x * 8 + w;
    float* xr = X + row * DD;
    const float* tr = T + row * DD;

    float4 x0 = ((const float4*)xr)[lane];
    float4 x1 = ((const float4*)xr)[lane + 32];
    float4 t0 = ((const float4*)tr)[lane];
    float4 t1 = ((const float4*)tr)[lane + 32];
    float v[8] = {x0.x + t0.x, x0.y + t0.y, x0.z + t0.z, x0.w + t0.w,
                  x1.x + t1.x, x1.y + t1.y, x1.z + t1.z, x1.w + t1.w};
    float s = 0.f;
#pragma unroll
    for (int i = 0; i < 8; i++) s += v[i];
    float m = warp_sum(s) * (1.f / 256.f);
    float vs = 0.f;
#pragma unroll
    for (int i = 0; i < 8; i++) { float d = v[i] - m; vs += d * d; }
    float rstd = rsqrtf(warp_sum(vs) * (1.f / 256.f) + 1e-5f);

    float4 g0 = ((const float4*)g)[lane];
    float4 g1 = ((const float4*)g)[lane + 32];
    float4 b0 = ((const float4*)bta)[lane];
    float4 b1 = ((const float4*)bta)[lane + 32];
    float o[8];
    o[0]=(v[0]-m)*rstd*g0.x + b0.x; o[1]=(v[1]-m)*rstd*g0.y + b0.y;
    o[2]=(v[2]-m)*rstd*g0.z + b0.z; o[3]=(v[3]-m)*rstd*g0.w + b0.w;
    o[4]=(v[4]-m)*rstd*g1.x + b1.x; o[5]=(v[5]-m)*rstd*g1.y + b1.y;
    o[6]=(v[6]-m)*rstd*g1.z + b1.z; o[7]=(v[7]-m)*rstd*g1.w + b1.w;
    ((float4*)xr)[lane]      = make_float4(o[0],o[1],o[2],o[3]);
    ((float4*)xr)[lane + 32] = make_float4(o[4],o[5],o[6],o[7]);

    float h[8], lo[8];
#pragma unroll
    for (int i = 0; i < 8; i++) split2h(o[i], h[i], lo[i]);
    uint32_t* ph = (uint32_t*)(Xh + row * DD);
    uint32_t* pl = (uint32_t*)(Xl + row * DD);
    ph[lane*2]      = pack_f16(h[0],h[1]);  ph[lane*2+1]      = pack_f16(h[2],h[3]);
    ph[64+lane*2]   = pack_f16(h[4],h[5]);  ph[64+lane*2+1]   = pack_f16(h[6],h[7]);
    pl[lane*2]      = pack_f16(lo[0],lo[1]); pl[lane*2+1]     = pack_f16(lo[2],lo[3]);
    pl[64+lane*2]   = pack_f16(lo[4],lo[5]); pl[64+lane*2+1]  = pack_f16(lo[6],lo[7]);
}

// ---------------- head ----------------
__global__ void __launch_bounds__(256) head_kernel(
    const float* __restrict__ X,   const float* __restrict__ th1_w,
    const float* __restrict__ th1_b, const float* __restrict__ bn_g,
    const float* __restrict__ bn_b,  const float* __restrict__ th2_w,
    const float* __restrict__ th2_b, float* __restrict__ S)
{
    __shared__ float wsm[DD * 32];
    __shared__ float xs[8][DD];
    const int tid = threadIdx.x, w = tid >> 5, lane = tid & 31;

    for (int i = tid; i < DD * 32 / 4; i += 256)
        ((float4*)wsm)[i] = ((const float4*)th1_w)[i];

    const size_t row = (size_t)blockIdx.x * 8 + w;
    const float4* xr = (const float4*)(X + row * DD);
    float4* xd = (float4*)xs[w];
    xd[lane]      = xr[lane];
    xd[lane + 32] = xr[lane + 32];
    __syncthreads();

    float acc = th1_b[lane];
#pragma unroll 4
    for (int d = 0; d < DD; d++)
        acc += xs[w][d] * wsm[d * 32 + lane];

    float hv = acc * (bn_g[lane] * rsqrtf(1.f + 1e-5f)) + bn_b[lane];
    const float c = 0.7978845608028654f;
    float gl = 0.5f * hv * (1.f + tanhf(c * (hv + 0.044715f * hv * hv * hv)));
    float p = warp_sum(gl * th2_w[lane]);
    if (lane == 0) S[row] = p + th2_b[0];
}

// ---------------- pool ----------------
__global__ void __launch_bounds__(256) pool_kernel(const float* __restrict__ X,
                                                   const float* __restrict__ S,
                                                   float* __restrict__ out)
{
    __shared__ float wv[LLN];
    __shared__ float red[256];
    const int b = blockIdx.x, tid = threadIdx.x;
    const float* sp = S + (size_t)b * LLN;

    float mx = -1e30f;
    for (int l = tid; l < LLN; l += 256) mx = fmaxf(mx, sp[l]);
    red[tid] = mx; __syncthreads();
    for (int s = 128; s; s >>= 1) { if (tid < s) red[tid] = fmaxf(red[tid], red[tid + s]); __syncthreads(); }
    mx = red[0]; __syncthreads();

    float sum = 0.f;
    for (int l = tid; l < LLN; l += 256) { float e = __expf(sp[l] - mx); wv[l] = e; sum += e; }
    red[tid] = sum; __syncthreads();
    for (int s = 128; s; s >>= 1) { if (tid < s) red[tid] += red[tid + s]; __syncthreads(); }
    float inv = 1.f / red[0];
    __syncthreads();

    float acc = 0.f;
    const float* xp = X + (size_t)b * LLN * DD + tid;
#pragma unroll 4
    for (int l = 0; l < LLN; l++) acc += wv[l] * xp[(size_t)l * DD];
    out[(size_t)b * DD + tid] = acc * inv;
}

// ---------------- launch ----------------
extern "C" void kernel_launch(void* const* d_in, const int* in_sizes, int n_in,
                              void* d_out, int out_size)
{
    const float* gene_exp = (const float*)d_in[0];
    const float* coords   = (const float*)d_in[1];
    const float* w_in     = (const float*)d_in[2];
    const float* b_in     = (const float*)d_in[3];
    const float* w_cls    = (const float*)d_in[4];
    const float* b_cls    = (const float*)d_in[5];
    const float* qkv_w    = (const float*)d_in[6];
    const float* qkv_b    = (const float*)d_in[7];
    const float* ln1_g    = (const float*)d_in[8];
    const float* ln1_b    = (const float*)d_in[9];
    const float* ffn_w1   = (const float*)d_in[10];
    const float* ffn_b1   = (const float*)d_in[11];
    const float* ffn_w2   = (const float*)d_in[12];
    const float* ffn_b2   = (const float*)d_in[13];
    const float* ln2_g    = (const float*)d_in[14];
    const float* ln2_b    = (const float*)d_in[15];
    const float* th1_w    = (const float*)d_in[16];
    const float* th1_b    = (const float*)d_in[17];
    const float* bn_g     = (const float*)d_in[18];
    const float* bn_b     = (const float*)d_in[19];
    const float* th2_w    = (const float*)d_in[20];
    const float* th2_b    = (const float*)d_in[21];
    float* out = (float*)d_out;

    float *X, *T, *QKV, *S;
    __half *Xh, *Xl, *Hh, *Hl, *Wh;
    cudaGetSymbolAddress((void**)&X,   g_X);
    cudaGetSymbolAddress((void**)&T,   g_T);
    cudaGetSymbolAddress((void**)&QKV, g_QKV);
    cudaGetSymbolAddress((void**)&S,   g_S);
    cudaGetSymbolAddress((void**)&Xh,  g_Xh);
    cudaGetSymbolAddress((void**)&Xl,  g_Xl);
    cudaGetSymbolAddress((void**)&Hh,  g_Hh);
    cudaGetSymbolAddress((void**)&Hl,  g_Hl);
    cudaGetSymbolAddress((void**)&Wh,  g_Wh);

    cudaFuncSetAttribute(attn_kernel, cudaFuncAttributeMaxDynamicSharedMemorySize,
                         ATTN_SMEM_BYTES);
    cudaFuncSetAttribute(gemmA_kernel<false,false>,
                         cudaFuncAttributeMaxDynamicSharedMemorySize, GEMM_SMEM);
    cudaFuncSetAttribute(gemmA_kernel<true,true>,
                         cudaFuncAttributeMaxDynamicSharedMemorySize, GEMM_SMEM);

    const int GM = (MROWS + 127) / 128;   // 229

    // ---- weight pre-split (pre-tiled, pre-swizzled, single fp16) ----
    split_w_kernel<<<dim3((256*768 + 255)/256, 4), 256>>>(qkv_w,  Wh,          256, 768);
    split_w_kernel<<<dim3((256*1024 + 255)/256, 4), 256>>>(ffn_w1, Wh + 196608, 256, 1024);
    split_w_kernel<<<dim3((1024*256 + 255)/256, 4), 256>>>(ffn_w2, Wh + 458752, 1024, 256);

    // ---- embed: CLS row + token GEMM (emits X fp32 + fp16 hi/lo) ----
    cls_kernel<<<BB, 256>>>(coords, w_cls, b_cls, X, Xh, Xl);
    gemm_embed_kernel<<<dim3(NTT * BB / 64, DD / 128), 256>>>(
        gene_exp, w_in, b_in, X, Xh, Xl, TOKK, DD);

    for (int l = 0; l < 4; l++) {
        const __half* Wq = Wh + (size_t)l * WPL;
        gemmA_kernel<false,false><<<dim3(6, GM), 256, GEMM_SMEM>>>(
            Xh, Xl, Wq, qkv_b + (size_t)l * 768,
            QKV, nullptr, nullptr, MROWS, 256, 768);
        attn_kernel<<<BB * HH, 512, ATTN_SMEM_BYTES>>>(QKV, T);
        add_ln_kernel<<<MROWS / 8, 256>>>(X, T, ln1_g + l * DD, ln1_b + l * DD, Xh, Xl);
        gemmA_kernel<true,true><<<dim3(8, GM), 256, GEMM_SMEM>>>(
            Xh, Xl, Wq + 196608, ffn_b1 + (size_t)l * FFF,
            nullptr, Hh, Hl, MROWS, 256, 1024);
        gemmA_kernel<false,false><<<dim3(2, GM), 256, GEMM_SMEM>>>(
            Hh, Hl, Wq + 458752, ffn_b2 + (size_t)l * DD,
            T, nullptr, nullptr, MROWS, 1024, 256);
        add_ln_kernel<<<MROWS / 8, 256>>>(X, T, ln2_g + l * DD, ln2_b + l * DD, Xh, Xl);
    }

    head_kernel<<<MROWS / 8, 256>>>(X, th1_w, th1_b, bn_g, bn_b, th2_w, th2_b, S);
    pool_kernel<<<BB, 256>>>(X, S, out);
}

// round 17
// speedup vs baseline: 2.4602x; 1.1199x over previous
#include <cuda_runtime.h>
#include <cuda_fp16.h>
#include <math.h>
#include <stdint.h>

// ---------------- problem constants ----------------
#define BB   64
#define NTT  456
#define TOKK 64
#define DD   256
#define HH   8
#define HDD  32
#define FFF  1024
#define LLN  457            // L = NT + 1
#define MROWS (BB * LLN)    // 29248
#define WPL  720896         // weight elems per layer: 256*768 + 256*1024 + 1024*256

// ---------------- device scratch (static, no allocs) ----------------
__device__ float g_X  [MROWS * DD];
__device__ float g_T  [MROWS * DD];
__device__ float g_QKV[MROWS * 3 * DD];
__device__ __half g_Xh[MROWS * DD];
__device__ __half g_Hh[MROWS * FFF];
__device__ __half g_Wh[4 * WPL];
__device__ float g_S  [MROWS];

// ---------------- helpers ----------------
__device__ __forceinline__ float warp_sum(float v) {
#pragma unroll
    for (int o = 16; o; o >>= 1) v += __shfl_xor_sync(0xffffffffu, v, o);
    return v;
}
__device__ __forceinline__ float warp_max(float v) {
#pragma unroll
    for (int o = 16; o; o >>= 1) v = fmaxf(v, __shfl_xor_sync(0xffffffffu, v, o));
    return v;
}
__device__ __forceinline__ uint32_t smem_u32(const void* p) {
    uint32_t a;
    asm("{ .reg .u64 t; cvta.to.shared.u64 t, %1; cvt.u32.u64 %0, t; }"
        : "=r"(a) : "l"(p));
    return a;
}
__device__ __forceinline__ uint32_t pack_f16(float lo, float hi) {
    uint32_t r;   // lo -> low half, hi -> high half
    asm("cvt.rn.f16x2.f32 %0, %1, %2;" : "=r"(r) : "f"(hi), "f"(lo));
    return r;
}
// SW64 swizzle for 64-byte rows (involution; conflict-free ldmatrix/STS)
__device__ __forceinline__ uint32_t swz64(uint32_t x) {
    return x ^ ((x >> 3) & 0x30);
}
__device__ __forceinline__ void ldsm4(uint32_t* r, uint32_t addr) {
    asm volatile("ldmatrix.sync.aligned.m8n8.x4.shared.b16 {%0,%1,%2,%3}, [%4];"
                 : "=r"(r[0]), "=r"(r[1]), "=r"(r[2]), "=r"(r[3]) : "r"(addr));
}
__device__ __forceinline__ void mma_f16(float* d, const uint32_t* a, const uint32_t* b) {
    asm volatile(
        "mma.sync.aligned.m16n8k16.row.col.f32.f16.f16.f32 "
        "{%0,%1,%2,%3}, {%4,%5,%6,%7}, {%8,%9}, {%0,%1,%2,%3};"
        : "+f"(d[0]), "+f"(d[1]), "+f"(d[2]), "+f"(d[3])
        : "r"(a[0]), "r"(a[1]), "r"(a[2]), "r"(a[3]), "r"(b[0]), "r"(b[1]));
}
__device__ __forceinline__ void cp16(uint32_t dst, const void* src) {
    asm volatile("cp.async.cg.shared.global [%0], [%1], 16;" :: "r"(dst), "l"(src));
}
#define CP_COMMIT() asm volatile("cp.async.commit_group;" ::: "memory")
#define CP_WAIT2()  asm volatile("cp.async.wait_group 2;" ::: "memory")

// =====================================================================
// weight pre-split: W[K][N] fp32 -> tiled/swizzled fp16
// tile = 128 n x 32 k; blockIdx.y = layer.
// =====================================================================
__global__ void split_w_kernel(const float* __restrict__ W,
                               __half* __restrict__ Wh,
                               int K, int N)
{
    int idx = blockIdx.x * 256 + threadIdx.x;
    if (idx >= K * N) return;
    const size_t lw = (size_t)blockIdx.y * K * N;
    const size_t lo_ = (size_t)blockIdx.y * WPL;
    int tile = idx >> 12, w2 = idx & 4095;
    int kc = K >> 5;
    int n_blk = tile / kc, c = tile % kc;
    uint32_t orig = swz64((uint32_t)w2 * 2);
    int n_local = orig >> 6, k_local = (orig & 63) >> 1;
    int k = c * 32 + k_local, n = n_blk * 128 + n_local;
    Wh[lo_ + idx] = __float2half_rn(W[lw + (size_t)k * N + n]);
}

// =====================================================================
// Pure fp16 tensor-core GEMM: C = A @ W + bias (fp32 accum)
// BM=128, BN=128, BK=32, 256 threads, 4-stage cp.async, 2 CTAs/SM.
// grid = (N/128, ceil(M/128))
// =====================================================================
#define GM_STAGES 4
#define STG 16384            // A 8K + W 8K
#define GEMM_SMEM (GM_STAGES * STG)   // 65536

template<bool RELU, bool HALF_OUT>
__global__ void __launch_bounds__(256, 2)
gemmA_kernel(const __half* __restrict__ Ah,
             const __half* __restrict__ Wh,
             const float* __restrict__ bias,
             float* __restrict__ Cf,
             __half* __restrict__ Ch,
             int M, int K, int N)
{
    extern __shared__ char smc[];
    const uint32_t sb = smem_u32(smc);
    const int tid = threadIdx.x, lane = tid & 31, w = tid >> 5;
    const int wm = w & 3, wn = w >> 2;
    const int bn = blockIdx.x * 128, bm = blockIdx.y * 128;
    const int NC = K >> 5;

    // per-thread cp.async geometry: 512 A-quads + 512 W-quads per stage
    uint32_t adst[2]; const __half* pa[2];
#pragma unroll
    for (int i = 0; i < 2; i++) {
        int q = tid + i * 256;
        int row = q >> 2, seg = q & 3;
        int gr = bm + row; if (gr >= M) gr = M - 1;
        pa[i]   = Ah + (size_t)gr * K + seg * 8;
        adst[i] = swz64((uint32_t)(row * 64 + seg * 16));
    }
    const size_t wtb = (size_t)blockIdx.x * NC * 4096;   // W tile base (elements)

    auto load_stage = [&](int c, int s) {
        const uint32_t base = sb + (uint32_t)s * STG;
#pragma unroll
        for (int i = 0; i < 2; i++) {
            int q = tid + i * 256;
            cp16(base + adst[i], pa[i] + c * 32);
            cp16(base + 8192 + q * 16, Wh + wtb + (size_t)c * 4096 + q * 8);
        }
    };

    // prologue: stages 0..2
#pragma unroll
    for (int s = 0; s < GM_STAGES - 1; s++) { load_stage(s, s); CP_COMMIT(); }

    // ldmatrix lane geometry
    const int g = lane >> 3, rr = lane & 7;
    const int a_row = wm * 32 + rr + (g & 1) * 8;
    const int b_row = wn * 64 + rr + (g & 1) * 8;
    const int kbyt  = (g >> 1) * 16;

    float acc[2][8][4];
#pragma unroll
    for (int mt = 0; mt < 2; mt++)
#pragma unroll
        for (int nt = 0; nt < 8; nt++)
#pragma unroll
            for (int q = 0; q < 4; q++) acc[mt][nt][q] = 0.f;

    for (int c = 0; c < NC; c++) {
        CP_WAIT2();
        __syncthreads();
        const uint32_t base = sb + (uint32_t)(c & 3) * STG;
        const uint32_t AS = base, WS = base + 8192;
#pragma unroll
        for (int ks = 0; ks < 2; ks++) {
            uint32_t Af[2][4];
#pragma unroll
            for (int mt = 0; mt < 2; mt++) {
                uint32_t off = swz64((uint32_t)((a_row + mt * 16) * 64 + kbyt + ks * 32));
                ldsm4(Af[mt], AS + off);
            }
            uint32_t B[8][2];
#pragma unroll
            for (int np = 0; np < 4; np++) {
                uint32_t off = swz64((uint32_t)((b_row + np * 16) * 64 + kbyt + ks * 32));
                uint32_t t4[4];
                ldsm4(t4, WS + off);
                B[2*np][0] = t4[0]; B[2*np+1][0] = t4[1];
                B[2*np][1] = t4[2]; B[2*np+1][1] = t4[3];
            }
#pragma unroll
            for (int mt = 0; mt < 2; mt++)
#pragma unroll
                for (int nt = 0; nt < 8; nt++)
                    mma_f16(acc[mt][nt], Af[mt], B[nt]);
        }
        if (c + GM_STAGES - 1 < NC)
            load_stage(c + GM_STAGES - 1, (c + GM_STAGES - 1) & 3);
        CP_COMMIT();   // one group per iter keeps wait_group accounting exact
    }

    // ---------- epilogue ----------
#pragma unroll
    for (int mt = 0; mt < 2; mt++) {
        const int gr0 = bm + wm * 32 + mt * 16 + (lane >> 2);
        const int gr1 = gr0 + 8;
#pragma unroll
        for (int nt = 0; nt < 8; nt++) {
            const int gc = bn + wn * 64 + nt * 8 + (lane & 3) * 2;
            float2 bz = *(const float2*)(bias + gc);
            float v0 = acc[mt][nt][0] + bz.x, v1 = acc[mt][nt][1] + bz.y;
            float v2 = acc[mt][nt][2] + bz.x, v3 = acc[mt][nt][3] + bz.y;
            if (RELU) {
                v0 = fmaxf(v0, 0.f); v1 = fmaxf(v1, 0.f);
                v2 = fmaxf(v2, 0.f); v3 = fmaxf(v3, 0.f);
            }
            if (HALF_OUT) {
                if (gr0 < M) *(uint32_t*)(Ch + (size_t)gr0 * N + gc) = pack_f16(v0, v1);
                if (gr1 < M) *(uint32_t*)(Ch + (size_t)gr1 * N + gc) = pack_f16(v2, v3);
            } else {
                if (gr0 < M) *(float2*)(Cf + (size_t)gr0 * N + gc) = make_float2(v0, v1);
                if (gr1 < M) *(float2*)(Cf + (size_t)gr1 * N + gc) = make_float2(v2, v3);
            }
        }
    }
}

// ---------------- SIMT SGEMM for embed (K=64, row remap, emits X + fp16) ----------------
__global__ void __launch_bounds__(256) gemm_embed_kernel(
    const float* __restrict__ A, const float* __restrict__ W,
    const float* __restrict__ bias, float* __restrict__ C,
    __half* __restrict__ Xh,
    int K, int N)
{
    __shared__ __align__(16) float As[16][68];
    __shared__ __align__(16) float Bs[16][128];

    const int tid = threadIdx.x;
    const int tx  = tid & 15;
    const int ty  = tid >> 4;
    const int bm  = blockIdx.x * 64;
    const int bn  = blockIdx.y * 128;

    const int la_r = tid >> 2;
    const int la_k = (tid & 3) << 2;
    const int lb_r = tid >> 5;
    const int lb_c = (tid & 31) << 2;

    const float* Aptr  = A + (size_t)(bm + la_r) * K + la_k;
    const float* Wptr0 = W + (size_t)lb_r * N + bn + lb_c;
    const float* Wptr1 = W + (size_t)(lb_r + 8) * N + bn + lb_c;

    float acc[4][8];
#pragma unroll
    for (int i = 0; i < 4; i++)
#pragma unroll
        for (int j = 0; j < 8; j++) acc[i][j] = 0.f;

    for (int k0 = 0; k0 < K; k0 += 16) {
        float4 av  = *(const float4*)(Aptr + k0);
        float4 bw0 = *(const float4*)(Wptr0 + (size_t)k0 * N);
        float4 bw1 = *(const float4*)(Wptr1 + (size_t)k0 * N);
        As[la_k + 0][la_r] = av.x;
        As[la_k + 1][la_r] = av.y;
        As[la_k + 2][la_r] = av.z;
        As[la_k + 3][la_r] = av.w;
        *(float4*)&Bs[lb_r][lb_c]     = bw0;
        *(float4*)&Bs[lb_r + 8][lb_c] = bw1;
        __syncthreads();
#pragma unroll
        for (int kk = 0; kk < 16; kk++) {
            float4 a  = *(const float4*)&As[kk][ty * 4];
            float4 b0 = *(const float4*)&Bs[kk][tx * 8];
            float4 b1 = *(const float4*)&Bs[kk][tx * 8 + 4];
            float ar[4] = {a.x, a.y, a.z, a.w};
            float br[8] = {b0.x, b0.y, b0.z, b0.w, b1.x, b1.y, b1.z, b1.w};
#pragma unroll
            for (int i = 0; i < 4; i++)
#pragma unroll
                for (int j = 0; j < 8; j++)
                    acc[i][j] = fmaf(ar[i], br[j], acc[i][j]);
        }
        __syncthreads();
    }

    float4 bb0 = *(const float4*)(bias + bn + tx * 8);
    float4 bb1 = *(const float4*)(bias + bn + tx * 8 + 4);
    float bx[8] = {bb0.x, bb0.y, bb0.z, bb0.w, bb1.x, bb1.y, bb1.z, bb1.w};

#pragma unroll
    for (int i = 0; i < 4; i++) {
        int r = bm + ty * 4 + i;
        int orow = r + r / NTT + 1;   // (b*NT+t) -> b*L + 1 + t
        float o[8];
#pragma unroll
        for (int j = 0; j < 8; j++) o[j] = acc[i][j] + bx[j];
        size_t off = (size_t)orow * N + bn + tx * 8;
        float4* cp = (float4*)(C + off);
        cp[0] = make_float4(o[0], o[1], o[2], o[3]);
        cp[1] = make_float4(o[4], o[5], o[6], o[7]);
        uint32_t* ph = (uint32_t*)(Xh + off);
        ph[0] = pack_f16(o[0],o[1]);  ph[1] = pack_f16(o[2],o[3]);
        ph[2] = pack_f16(o[4],o[5]);  ph[3] = pack_f16(o[6],o[7]);
    }
}

// ---------------- CLS row ----------------
__global__ void cls_kernel(const float* __restrict__ coords,
                           const float* __restrict__ w_cls,
                           const float* __restrict__ b_cls,
                           float* __restrict__ X,
                           __half* __restrict__ Xh)
{
    int b = blockIdx.x, d = threadIdx.x;
    float c0 = coords[b * 3 + 0], c1 = coords[b * 3 + 1], c2 = coords[b * 3 + 2];
    float v = b_cls[d] + c0 * w_cls[d] + c1 * w_cls[DD + d] + c2 * w_cls[2 * DD + d];
    size_t off = (size_t)b * LLN * DD + d;
    X[off] = v;
    Xh[off] = __float2half_rn(v);
}

// ---------------- fused attention: 512 threads, 16 warps ----------------
#define ATTN_SMEM_FLOATS (457*33 + 457*32 + 32*457 + 16*64)
#define ATTN_SMEM_BYTES  (ATTN_SMEM_FLOATS * 4)

__global__ void __launch_bounds__(512) attn_kernel(const float* __restrict__ QKV,
                                                   float* __restrict__ O)
{
    extern __shared__ float sm[];
    float* Ksm = sm;                      // [457][33]
    float* Vsm = Ksm + 457 * 33;          // [457][32]
    float* Ssm = Vsm + 457 * 32;          // [32][457]
    float* Qsm = Ssm + 32 * 457;          // [16][64]

    const int bh = blockIdx.x;
    const int b = bh >> 3, h = bh & 7;
    const int tid = threadIdx.x, w = tid >> 5, lane = tid & 31;
    const float slope = (h < 4) ? 1.0f : 0.5f;
    const float scale = 0.17677669529663687f;

    const float* base = QKV + (size_t)b * (LLN * 3 * DD) + h * HDD;

    for (int idx = tid; idx < 457 * 32; idx += 512) {
        int j = idx >> 5, d = idx & 31;
        const float* kv = base + (size_t)j * (3 * DD);
        Ksm[j * 33 + d] = kv[DD + d];
        Vsm[idx]        = kv[2 * DD + d];
    }
    __syncthreads();

    for (int i0 = 2 * w; i0 < LLN; i0 += 32) {
        const bool two = (i0 + 1 < LLN);
        Qsm[w * 64 + lane] = base[(size_t)i0 * (3 * DD) + lane];
        if (two) Qsm[w * 64 + 32 + lane] = base[(size_t)(i0 + 1) * (3 * DD) + lane];
        __syncwarp();

        float s0[15], s1[15];
#pragma unroll
        for (int t = 0; t < 15; t++) { s0[t] = 0.f; s1[t] = 0.f; }
        for (int d = 0; d < 32; d++) {
            float q0 = Qsm[w * 64 + d];
            float q1 = Qsm[w * 64 + 32 + d];
#pragma unroll
            for (int t = 0; t < 15; t++) {
                int jj = lane + t * 32;
                if (jj < LLN) {
                    float kv = Ksm[jj * 33 + d];
                    s0[t] += q0 * kv;
                    s1[t] += q1 * kv;
                }
            }
        }
        float mx0 = -1e30f, mx1 = -1e30f;
#pragma unroll
        for (int t = 0; t < 15; t++) {
            int jj = lane + t * 32;
            if (jj < LLN) {
                s0[t] = s0[t] * scale - slope * fabsf((float)(i0 - jj));
                s1[t] = s1[t] * scale - slope * fabsf((float)(i0 + 1 - jj));
                mx0 = fmaxf(mx0, s0[t]);
                mx1 = fmaxf(mx1, s1[t]);
            }
        }
        mx0 = warp_max(mx0); mx1 = warp_max(mx1);
        float sum0 = 0.f, sum1 = 0.f;
#pragma unroll
        for (int t = 0; t < 15; t++) {
            int jj = lane + t * 32;
            if (jj < LLN) {
                float e0 = __expf(s0[t] - mx0);
                float e1 = __expf(s1[t] - mx1);
                Ssm[(2 * w) * 457 + jj]     = e0;
                Ssm[(2 * w + 1) * 457 + jj] = e1;
                sum0 += e0; sum1 += e1;
            }
        }
        sum0 = warp_sum(sum0); sum1 = warp_sum(sum1);
        float inv0 = 1.f / sum0, inv1 = 1.f / sum1;
        __syncwarp();

        float acc0 = 0.f, acc1 = 0.f;
        const float* p0 = Ssm + (2 * w) * 457;
        const float* p1 = Ssm + (2 * w + 1) * 457;
#pragma unroll 4
        for (int j = 0; j < LLN; j++) {
            float v = Vsm[j * 32 + lane];
            acc0 += p0[j] * v;
            acc1 += p1[j] * v;
        }
        float* op = O + ((size_t)b * LLN + i0) * DD + h * HDD + lane;
        op[0] = acc0 * inv0;
        if (two) op[DD] = acc1 * inv1;
        __syncwarp();
    }
}

// ---------------- fused residual add + LayerNorm (emits fp32 X + fp16) ----------------
__global__ void __launch_bounds__(256) add_ln_kernel(float* __restrict__ X,
                                                     const float* __restrict__ T,
                                                     const float* __restrict__ g,
                                                     const float* __restrict__ bta,
                                                     __half* __restrict__ Xh)
{
    const int w = threadIdx.x >> 5, lane = threadIdx.x & 31;
    const size_t row = (size_t)blockIdx.x * 8 + w;
    float* xr = X + row * DD;
    const float* tr = T + row * DD;

    float4 x0 = ((const float4*)xr)[lane];
    float4 x1 = ((const float4*)xr)[lane + 32];
    float4 t0 = ((const float4*)tr)[lane];
    float4 t1 = ((const float4*)tr)[lane + 32];
    float v[8] = {x0.x + t0.x, x0.y + t0.y, x0.z + t0.z, x0.w + t0.w,
                  x1.x + t1.x, x1.y + t1.y, x1.z + t1.z, x1.w + t1.w};
    float s = 0.f;
#pragma unroll
    for (int i = 0; i < 8; i++) s += v[i];
    float m = warp_sum(s) * (1.f / 256.f);
    float vs = 0.f;
#pragma unroll
    for (int i = 0; i < 8; i++) { float d = v[i] - m; vs += d * d; }
    float rstd = rsqrtf(warp_sum(vs) * (1.f / 256.f) + 1e-5f);

    float4 g0 = ((const float4*)g)[lane];
    float4 g1 = ((const float4*)g)[lane + 32];
    float4 b0 = ((const float4*)bta)[lane];
    float4 b1 = ((const float4*)bta)[lane + 32];
    float o[8];
    o[0]=(v[0]-m)*rstd*g0.x + b0.x; o[1]=(v[1]-m)*rstd*g0.y + b0.y;
    o[2]=(v[2]-m)*rstd*g0.z + b0.z; o[3]=(v[3]-m)*rstd*g0.w + b0.w;
    o[4]=(v[4]-m)*rstd*g1.x + b1.x; o[5]=(v[5]-m)*rstd*g1.y + b1.y;
    o[6]=(v[6]-m)*rstd*g1.z + b1.z; o[7]=(v[7]-m)*rstd*g1.w + b1.w;
    ((float4*)xr)[lane]      = make_float4(o[0],o[1],o[2],o[3]);
    ((float4*)xr)[lane + 32] = make_float4(o[4],o[5],o[6],o[7]);

    uint32_t* ph = (uint32_t*)(Xh + row * DD);
    ph[lane*2]      = pack_f16(o[0],o[1]);  ph[lane*2+1]      = pack_f16(o[2],o[3]);
    ph[64+lane*2]   = pack_f16(o[4],o[5]);  ph[64+lane*2+1]   = pack_f16(o[6],o[7]);
}

// ---------------- head ----------------
__global__ void __launch_bounds__(256) head_kernel(
    const float* __restrict__ X,   const float* __restrict__ th1_w,
    const float* __restrict__ th1_b, const float* __restrict__ bn_g,
    const float* __restrict__ bn_b,  const float* __restrict__ th2_w,
    const float* __restrict__ th2_b, float* __restrict__ S)
{
    __shared__ float wsm[DD * 32];
    __shared__ float xs[8][DD];
    const int tid = threadIdx.x, w = tid >> 5, lane = tid & 31;

    for (int i = tid; i < DD * 32 / 4; i += 256)
        ((float4*)wsm)[i] = ((const float4*)th1_w)[i];

    const size_t row = (size_t)blockIdx.x * 8 + w;
    const float4* xr = (const float4*)(X + row * DD);
    float4* xd = (float4*)xs[w];
    xd[lane]      = xr[lane];
    xd[lane + 32] = xr[lane + 32];
    __syncthreads();

    float acc = th1_b[lane];
#pragma unroll 4
    for (int d = 0; d < DD; d++)
        acc += xs[w][d] * wsm[d * 32 + lane];

    float hv = acc * (bn_g[lane] * rsqrtf(1.f + 1e-5f)) + bn_b[lane];
    const float c = 0.7978845608028654f;
    float gl = 0.5f * hv * (1.f + tanhf(c * (hv + 0.044715f * hv * hv * hv)));
    float p = warp_sum(gl * th2_w[lane]);
    if (lane == 0) S[row] = p + th2_b[0];
}

// ---------------- pool ----------------
__global__ void __launch_bounds__(256) pool_kernel(const float* __restrict__ X,
                                                   const float* __restrict__ S,
                                                   float* __restrict__ out)
{
    __shared__ float wv[LLN];
    __shared__ float red[256];
    const int b = blockIdx.x, tid = threadIdx.x;
    const float* sp = S + (size_t)b * LLN;

    float mx = -1e30f;
    for (int l = tid; l < LLN; l += 256) mx = fmaxf(mx, sp[l]);
    red[tid] = mx; __syncthreads();
    for (int s = 128; s; s >>= 1) { if (tid < s) red[tid] = fmaxf(red[tid], red[tid + s]); __syncthreads(); }
    mx = red[0]; __syncthreads();

    float sum = 0.f;
    for (int l = tid; l < LLN; l += 256) { float e = __expf(sp[l] - mx); wv[l] = e; sum += e; }
    red[tid] = sum; __syncthreads();
    for (int s = 128; s; s >>= 1) { if (tid < s) red[tid] += red[tid + s]; __syncthreads(); }
    float inv = 1.f / red[0];
    __syncthreads();

    float acc = 0.f;
    const float* xp = X + (size_t)b * LLN * DD + tid;
#pragma unroll 4
    for (int l = 0; l < LLN; l++) acc += wv[l] * xp[(size_t)l * DD];
    out[(size_t)b * DD + tid] = acc * inv;
}

// ---------------- launch ----------------
extern "C" void kernel_launch(void* const* d_in, const int* in_sizes, int n_in,
                              void* d_out, int out_size)
{
    const float* gene_exp = (const float*)d_in[0];
    const float* coords   = (const float*)d_in[1];
    const float* w_in     = (const float*)d_in[2];
    const float* b_in     = (const float*)d_in[3];
    const float* w_cls    = (const float*)d_in[4];
    const float* b_cls    = (const float*)d_in[5];
    const float* qkv_w    = (const float*)d_in[6];
    const float* qkv_b    = (const float*)d_in[7];
    const float* ln1_g    = (const float*)d_in[8];
    const float* ln1_b    = (const float*)d_in[9];
    const float* ffn_w1   = (const float*)d_in[10];
    const float* ffn_b1   = (const float*)d_in[11];
    const float* ffn_w2   = (const float*)d_in[12];
    const float* ffn_b2   = (const float*)d_in[13];
    const float* ln2_g    = (const float*)d_in[14];
    const float* ln2_b    = (const float*)d_in[15];
    const float* th1_w    = (const float*)d_in[16];
    const float* th1_b    = (const float*)d_in[17];
    const float* bn_g     = (const float*)d_in[18];
    const float* bn_b     = (const float*)d_in[19];
    const float* th2_w    = (const float*)d_in[20];
    const float* th2_b    = (const float*)d_in[21];
    float* out = (float*)d_out;

    float *X, *T, *QKV, *S;
    __half *Xh, *Hh, *Wh;
    cudaGetSymbolAddress((void**)&X,   g_X);
    cudaGetSymbolAddress((void**)&T,   g_T);
    cudaGetSymbolAddress((void**)&QKV, g_QKV);
    cudaGetSymbolAddress((void**)&S,   g_S);
    cudaGetSymbolAddress((void**)&Xh,  g_Xh);
    cudaGetSymbolAddress((void**)&Hh,  g_Hh);
    cudaGetSymbolAddress((void**)&Wh,  g_Wh);

    cudaFuncSetAttribute(attn_kernel, cudaFuncAttributeMaxDynamicSharedMemorySize,
                         ATTN_SMEM_BYTES);
    cudaFuncSetAttribute(gemmA_kernel<false,false>,
                         cudaFuncAttributeMaxDynamicSharedMemorySize, GEMM_SMEM);
    cudaFuncSetAttribute(gemmA_kernel<true,true>,
                         cudaFuncAttributeMaxDynamicSharedMemorySize, GEMM_SMEM);

    const int GM = (MROWS + 127) / 128;   // 229

    // ---- weight pre-convert (pre-tiled, pre-swizzled fp16) ----
    split_w_kernel<<<dim3((256*768 + 255)/256, 4), 256>>>(qkv_w,  Wh,          256, 768);
    split_w_kernel<<<dim3((256*1024 + 255)/256, 4), 256>>>(ffn_w1, Wh + 196608, 256, 1024);
    split_w_kernel<<<dim3((1024*256 + 255)/256, 4), 256>>>(ffn_w2, Wh + 458752, 1024, 256);

    // ---- embed: CLS row + token GEMM (emits X fp32 + fp16) ----
    cls_kernel<<<BB, 256>>>(coords, w_cls, b_cls, X, Xh);
    gemm_embed_kernel<<<dim3(NTT * BB / 64, DD / 128), 256>>>(
        gene_exp, w_in, b_in, X, Xh, TOKK, DD);

    for (int l = 0; l < 4; l++) {
        const __half* Wq = Wh + (size_t)l * WPL;
        gemmA_kernel<false,false><<<dim3(6, GM), 256, GEMM_SMEM>>>(
            Xh, Wq, qkv_b + (size_t)l * 768, QKV, nullptr, MROWS, 256, 768);
        attn_kernel<<<BB * HH, 512, ATTN_SMEM_BYTES>>>(QKV, T);
        add_ln_kernel<<<MROWS / 8, 256>>>(X, T, ln1_g + l * DD, ln1_b + l * DD, Xh);
        gemmA_kernel<true,true><<<dim3(8, GM), 256, GEMM_SMEM>>>(
            Xh, Wq + 196608, ffn_b1 + (size_t)l * FFF, nullptr, Hh, MROWS, 256, 1024);
        gemmA_kernel<false,false><<<dim3(2, GM), 256, GEMM_SMEM>>>(
            Hh, Wq + 458752, ffn_b2 + (size_t)l * DD, T, nullptr, MROWS, 1024, 256);
        add_ln_kernel<<<MROWS / 8, 256>>>(X, T, ln2_g + l * DD, ln2_b + l * DD, Xh);
    }

    head_kernel<<<MROWS / 8, 256>>>(X, th1_w, th1_b, bn_g, bn_b, th2_w, th2_b, S);
    pool_kernel<<<BB, 256>>>(X, S, out);
}